// round 5
// baseline (speedup 1.0000x reference)
#include <cuda_runtime.h>
#include <math.h>

// Problem constants
constexpr int cN  = 10000;   // nodes
constexpr int cE  = 160000;  // edges
constexpr int cB  = 64;      // graphs in batch
constexpr int cD  = 640;     // hidden dim
constexpr int cND = 4;       // input node dim
constexpr int cED = 8;       // edge attr dim
constexpr int RPT = cD / 32; // 20 regs per lane across D

#define FULLMASK 0xffffffffu
#define SCALE 0.0395284707521047416f  // 1/sqrt(640)

// ---------------- scratch (static device globals; no allocs) ----------------
__device__ __align__(16) float g_h [cN * cD];
__device__ __align__(16) float g_q [cN * cD];
__device__ __align__(16) float g_k [cN * cD];
__device__ __align__(16) float g_v [cN * cD];
__device__ __align__(16) float g_hn[cN * cD];  // skip connection output
__device__ int   g_src[cE];
__device__ int   g_dst[cE];
__device__ int   g_bat[cN];
__device__ int   g_flag[2];   // [0]=edge-index is int64, [1]=batch is int64
__device__ int   g_deg[cN];
__device__ int   g_cur[cN];
__device__ int   g_off[cN + 1];
__device__ int   g_csr[cE];
__device__ __align__(16) float g_pool[cB * cD];
__device__ __align__(16) float g_z[2][cB * cD];

// Device-side buffer selector (scratch addressing stays in device code).
__device__ __forceinline__ float* buf_sel(int s) {
    switch (s) {
        case 0:  return g_h;
        case 1:  return g_q;
        case 2:  return g_k;
        case 3:  return g_v;
        default: return g_hn;
    }
}

// ---------------- dtype detection + normalization ----------------
// JAX without x64 silently delivers int32 even though the reference requests
// int64. Reading int32 data as long long produced garbage node indices whose
// generic addresses landed in the shared/local aperture -> error 717 (R1-R3).
// Detection: for int64 data with small values, odd 32-bit words are all zero.
// We scan only the first half of the word buffer so the scan is in-bounds
// under BOTH interpretations.
__global__ void k_flag_zero() {
    if (threadIdx.x < 2) g_flag[threadIdx.x] = 0;
}

// nelem = logical element count; buffer has >= nelem 32-bit words (int32 case)
// or 2*nelem words (int64 case). Scan odd words < nelem.
__global__ void k_detect(const int* __restrict__ p, int nelem, int slot) {
    int i = blockIdx.x * blockDim.x + threadIdx.x;   // element index
    int w = 2 * i + 1;                               // odd word
    if (w < nelem) {
        if (p[w] != 0) atomicOr(&g_flag[slot], 1);   // nonzero odd word => int32
    }
}
// After k_detect: g_flag[slot] == 0 means int64, == 1 means int32.

__global__ void k_cvt_edges(const int* __restrict__ p) {
    int e = blockIdx.x * blockDim.x + threadIdx.x;
    if (e >= 2 * cE) return;
    int is32 = g_flag[0];
    int v;
    if (is32) v = p[e];
    else      v = (int)((const long long*)p)[e];
    if (e < cE) g_src[e] = v;
    else        g_dst[e - cE] = v;
}

__global__ void k_cvt_batch(const int* __restrict__ p) {
    int n = blockIdx.x * blockDim.x + threadIdx.x;
    if (n >= cN) return;
    int is32 = g_flag[1];
    g_bat[n] = is32 ? p[n] : (int)((const long long*)p)[n];
}

// ---------------- CSR build ----------------
__global__ void k_csr_zero() {
    int i = blockIdx.x * blockDim.x + threadIdx.x;
    if (i < cN) { g_deg[i] = 0; g_cur[i] = 0; }
}

__global__ void k_hist() {
    int e = blockIdx.x * blockDim.x + threadIdx.x;
    if (e < cE) atomicAdd(&g_deg[g_dst[e]], 1);
}

__global__ void __launch_bounds__(1024) k_scan() {
    const int T = 1024;
    const int CH = (cN + T - 1) / T; // 10
    int t = threadIdx.x;
    int vals[CH];
    int local = 0;
    int base = t * CH;
#pragma unroll
    for (int j = 0; j < CH; j++) {
        int idx = base + j;
        int v = (idx < cN) ? g_deg[idx] : 0;
        vals[j] = local;
        local += v;
    }
    __shared__ int sh[T];
    sh[t] = local;
    __syncthreads();
    for (int off = 1; off < T; off <<= 1) {
        int v = (t >= off) ? sh[t - off] : 0;
        __syncthreads();
        sh[t] += v;
        __syncthreads();
    }
    int prefix = sh[t] - local; // exclusive
#pragma unroll
    for (int j = 0; j < CH; j++) {
        int idx = base + j;
        if (idx < cN) g_off[idx] = prefix + vals[j];
    }
    if (t == T - 1) g_off[cN] = sh[T - 1];
}

__global__ void k_scatter() {
    int e = blockIdx.x * blockDim.x + threadIdx.x;
    if (e < cE) {
        int d = g_dst[e];
        int p = atomicAdd(&g_cur[d], 1);
        g_csr[g_off[d] + p] = e;
    }
}

// ---------------- layer 0 projections (input dim = 4) ----------------
__global__ void k_layer0(const float* __restrict__ x,
                         const float* __restrict__ Wq, const float* __restrict__ bq,
                         const float* __restrict__ Wk, const float* __restrict__ bk,
                         const float* __restrict__ Wv, const float* __restrict__ bv,
                         const float* __restrict__ Ws, const float* __restrict__ bs) {
    int idx = blockIdx.x * blockDim.x + threadIdx.x;
    if (idx >= cN * cD) return;
    int n = idx / cD, d = idx - n * cD;
    float x0 = x[n * cND + 0], x1 = x[n * cND + 1], x2 = x[n * cND + 2], x3 = x[n * cND + 3];
    float aq = bq[d] + x0 * Wq[0 * cD + d] + x1 * Wq[1 * cD + d] + x2 * Wq[2 * cD + d] + x3 * Wq[3 * cD + d];
    float ak = bk[d] + x0 * Wk[0 * cD + d] + x1 * Wk[1 * cD + d] + x2 * Wk[2 * cD + d] + x3 * Wk[3 * cD + d];
    float av = bv[d] + x0 * Wv[0 * cD + d] + x1 * Wv[1 * cD + d] + x2 * Wv[2 * cD + d] + x3 * Wv[3 * cD + d];
    float as = bs[d] + x0 * Ws[0 * cD + d] + x1 * Ws[1 * cD + d] + x2 * Ws[2 * cD + d] + x3 * Ws[3 * cD + d];
    g_q[idx] = aq; g_k[idx] = ak; g_v[idx] = av; g_hn[idx] = as;
}

// ---------------- fused edge aggregation (one warp per node, online softmax) ---
// score_e = q[dst]·k[src] + (q[dst] We^T)·ea[e], agg = Σα v[src] + (Σα ea[e]) We
__global__ void __launch_bounds__(256) k_edge(const float* __restrict__ ea,
                                              const float* __restrict__ We,
                                              int do_relu) {
    int w = (blockIdx.x * blockDim.x + threadIdx.x) >> 5;
    int lane = threadIdx.x & 31;
    if (w >= cN) return;
    const int n = w;

    float qr[RPT];
#pragma unroll
    for (int i = 0; i < RPT; i++) qr[i] = g_q[(size_t)n * cD + lane + 32 * i];

    // qe[c] = sum_d q_d * We[c][d]
    float qe[cED];
#pragma unroll
    for (int c = 0; c < cED; c++) {
        float p = 0.f;
#pragma unroll
        for (int i = 0; i < RPT; i++) p += qr[i] * We[c * cD + lane + 32 * i];
#pragma unroll
        for (int o = 16; o > 0; o >>= 1) p += __shfl_xor_sync(FULLMASK, p, o);
        qe[c] = p;
    }

    float m = -1e30f, s = 0.f;
    float acc[RPT];
    float av[cED];
#pragma unroll
    for (int i = 0; i < RPT; i++) acc[i] = 0.f;
#pragma unroll
    for (int c = 0; c < cED; c++) av[c] = 0.f;

    int beg = g_off[n], end = g_off[n + 1];
    for (int idx = beg; idx < end; idx++) {
        int e = g_csr[idx];
        int sn = g_src[e];
        const float* kr = g_k + (size_t)sn * cD;
        const float* vr = g_v + (size_t)sn * cD;
        float eav[cED];
#pragma unroll
        for (int c = 0; c < cED; c++) eav[c] = ea[(size_t)e * cED + c];
        float dp = 0.f;
#pragma unroll
        for (int i = 0; i < RPT; i++) dp += qr[i] * kr[lane + 32 * i];
#pragma unroll
        for (int o = 16; o > 0; o >>= 1) dp += __shfl_xor_sync(FULLMASK, dp, o);
        float sc = dp;
#pragma unroll
        for (int c = 0; c < cED; c++) sc += qe[c] * eav[c];
        sc *= SCALE;

        float mn  = fmaxf(m, sc);
        float f   = __expf(m - mn);
        float wgt = __expf(sc - mn);
        s = s * f + wgt;
#pragma unroll
        for (int i = 0; i < RPT; i++) acc[i] = acc[i] * f + wgt * vr[lane + 32 * i];
#pragma unroll
        for (int c = 0; c < cED; c++) av[c] = av[c] * f + wgt * eav[c];
        m = mn;
    }

    float inv = 1.f / (s + 1e-16f);
#pragma unroll
    for (int i = 0; i < RPT; i++) {
        int d = lane + 32 * i;
        float ep = 0.f;
#pragma unroll
        for (int c = 0; c < cED; c++) ep += av[c] * We[c * cD + d];
        float o = g_hn[(size_t)n * cD + d] + (acc[i] + ep) * inv;
        if (do_relu) o = fmaxf(o, 0.f);
        g_h[(size_t)n * cD + d] = o;
    }
}

// ---------------- fp32 tiled GEMM: C[M,640] = A[M,640] @ W[640,640] + bias -----
__global__ void __launch_bounds__(256) k_gemm(int Asel,
                                              const float* __restrict__ W,
                                              const float* __restrict__ bias,
                                              int Csel) {
    const float* A = buf_sel(Asel);
    float*       C = buf_sel(Csel);

    __shared__ float As[16][132]; // transposed A tile, padded
    __shared__ float Bs[16][64];
    int tid = threadIdx.x;
    int bm = blockIdx.x * 128, bn = blockIdx.y * 64;
    int tx = tid & 15, ty = tid >> 4;
    int ar = tid >> 2;        // 0..63 (row in tile, +64 for second)
    int ac = (tid & 3) << 2;  // 0,4,8,12 (k offset)
    int br = tid >> 4, bc = (tid & 15) << 2;

    float acc[8][4];
#pragma unroll
    for (int i = 0; i < 8; i++)
#pragma unroll
        for (int j = 0; j < 4; j++) acc[i][j] = 0.f;

    for (int k0 = 0; k0 < cD; k0 += 16) {
#pragma unroll
        for (int r = 0; r < 2; r++) {
            int row = bm + ar + r * 64;
            float4 avv;
            if (row < cN) avv = *(const float4*)(A + (size_t)row * cD + k0 + ac);
            else          avv = make_float4(0.f, 0.f, 0.f, 0.f);
            As[ac + 0][ar + r * 64] = avv.x;
            As[ac + 1][ar + r * 64] = avv.y;
            As[ac + 2][ar + r * 64] = avv.z;
            As[ac + 3][ar + r * 64] = avv.w;
        }
        *(float4*)&Bs[br][bc] = *(const float4*)(W + (size_t)(k0 + br) * cD + bn + bc);
        __syncthreads();
#pragma unroll
        for (int kk = 0; kk < 16; kk++) {
            float4 a0 = *(const float4*)&As[kk][ty * 4];
            float4 a1 = *(const float4*)&As[kk][64 + ty * 4];
            float4 b  = *(const float4*)&Bs[kk][tx * 4];
            float aa[8] = {a0.x, a0.y, a0.z, a0.w, a1.x, a1.y, a1.z, a1.w};
            float bb[4] = {b.x, b.y, b.z, b.w};
#pragma unroll
            for (int i = 0; i < 8; i++)
#pragma unroll
                for (int j = 0; j < 4; j++) acc[i][j] += aa[i] * bb[j];
        }
        __syncthreads();
    }

    float4 bv = *(const float4*)(bias + bn + tx * 4);
    float bb[4] = {bv.x, bv.y, bv.z, bv.w};
#pragma unroll
    for (int r = 0; r < 2; r++)
#pragma unroll
        for (int i = 0; i < 4; i++) {
            int row = bm + r * 64 + ty * 4 + i;
            if (row < cN) {
                float4 o;
                o.x = acc[r * 4 + i][0] + bb[0];
                o.y = acc[r * 4 + i][1] + bb[1];
                o.z = acc[r * 4 + i][2] + bb[2];
                o.w = acc[r * 4 + i][3] + bb[3];
                *(float4*)(C + (size_t)row * cD + bn + tx * 4) = o;
            }
        }
}

// ---------------- pooling ----------------
__global__ void k_pool_zero() {
    int i = blockIdx.x * blockDim.x + threadIdx.x;
    if (i < cB * cD) g_pool[i] = 0.f;
}

__global__ void k_pool() {
    int w = (blockIdx.x * blockDim.x + threadIdx.x) >> 5;
    int lane = threadIdx.x & 31;
    if (w >= cN) return;
    int b = g_bat[w];
#pragma unroll
    for (int i = 0; i < RPT; i++)
        atomicAdd(&g_pool[b * cD + lane + 32 * i], g_h[(size_t)w * cD + lane + 32 * i]);
}

// ---------------- LN + Linear + ReLU head (per graph) ----------------
__global__ void __launch_bounds__(640) k_head(const float* __restrict__ ln_g,
                                              const float* __restrict__ ln_b,
                                              const float* __restrict__ Wemb,
                                              const float* __restrict__ bemb,
                                              int gi) {
    int b = blockIdx.x, t = threadIdx.x;
    __shared__ float red[20];
    __shared__ float zsh[cD];
    __shared__ float s_mu, s_rs;
    float x = g_pool[b * cD + t];

    float v = x;
#pragma unroll
    for (int o = 16; o > 0; o >>= 1) v += __shfl_xor_sync(FULLMASK, v, o);
    if ((t & 31) == 0) red[t >> 5] = v;
    __syncthreads();
    if (t == 0) {
        float s = 0.f;
        for (int i = 0; i < 20; i++) s += red[i];
        s_mu = s / cD;
    }
    __syncthreads();
    float dev = x - s_mu;
    v = dev * dev;
#pragma unroll
    for (int o = 16; o > 0; o >>= 1) v += __shfl_xor_sync(FULLMASK, v, o);
    if ((t & 31) == 0) red[t >> 5] = v;
    __syncthreads();
    if (t == 0) {
        float s = 0.f;
        for (int i = 0; i < 20; i++) s += red[i];
        s_rs = rsqrtf(s / cD + 1e-5f);
    }
    __syncthreads();
    zsh[t] = dev * s_rs * ln_g[t] + ln_b[t];
    __syncthreads();

    float o = bemb[t];
#pragma unroll 4
    for (int kk = 0; kk < cD; kk++) o += zsh[kk] * Wemb[(size_t)kk * cD + t];
    g_z[gi][b * cD + t] = fmaxf(o, 0.f);
}

// ---------------- cosine ----------------
__global__ void k_cos(float* __restrict__ out) {
    int b = blockIdx.x, t = threadIdx.x; // 256 threads
    float dp = 0.f, ai = 0.f, aj = 0.f;
    for (int d = t; d < cD; d += 256) {
        float zi = g_z[0][b * cD + d];
        float zj = g_z[1][b * cD + d];
        dp += zi * zj; ai += zi * zi; aj += zj * zj;
    }
#pragma unroll
    for (int o = 16; o > 0; o >>= 1) {
        dp += __shfl_xor_sync(FULLMASK, dp, o);
        ai += __shfl_xor_sync(FULLMASK, ai, o);
        aj += __shfl_xor_sync(FULLMASK, aj, o);
    }
    __shared__ float r1[8], r2[8], r3[8];
    int wid = t >> 5;
    if ((t & 31) == 0) { r1[wid] = dp; r2[wid] = ai; r3[wid] = aj; }
    __syncthreads();
    if (t == 0) {
        float D1 = 0.f, A = 0.f, Bv = 0.f;
        for (int i = 0; i < 8; i++) { D1 += r1[i]; A += r2[i]; Bv += r3[i]; }
        out[b] = D1 / (fmaxf(sqrtf(A), 1e-8f) * fmaxf(sqrtf(Bv), 1e-8f));
    }
}

// ---------------- driver: PURE kernel launches, no runtime API calls ----------
extern "C" void kernel_launch(void* const* d_in, const int* in_sizes, int n_in,
                              void* d_out, int out_size) {
    const float* x_i   = (const float*)d_in[0];
    const int*   ei_i  = (const int*)d_in[1];   // dtype detected at runtime
    const float* ea_i  = (const float*)d_in[2];
    const int*   bat_i = (const int*)d_in[3];
    const float* x_j   = (const float*)d_in[4];
    const int*   ei_j  = (const int*)d_in[5];
    const float* ea_j  = (const float*)d_in[6];
    const int*   bat_j = (const int*)d_in[7];
    const float* W0q = (const float*)d_in[8];
    const float* b0q = (const float*)d_in[9];
    const float* W0k = (const float*)d_in[10];
    const float* b0k = (const float*)d_in[11];
    const float* W0v = (const float*)d_in[12];
    const float* b0v = (const float*)d_in[13];
    const float* W0e = (const float*)d_in[14];
    const float* W0s = (const float*)d_in[15];
    const float* b0s = (const float*)d_in[16];
    const float* Wq  = (const float*)d_in[17];
    const float* bq  = (const float*)d_in[18];
    const float* Wk  = (const float*)d_in[19];
    const float* bk  = (const float*)d_in[20];
    const float* Wv  = (const float*)d_in[21];
    const float* bv  = (const float*)d_in[22];
    const float* We  = (const float*)d_in[23];
    const float* Ws  = (const float*)d_in[24];
    const float* bs  = (const float*)d_in[25];
    const float* ln_g = (const float*)d_in[26];
    const float* ln_b = (const float*)d_in[27];
    const float* Wemb = (const float*)d_in[28];
    const float* bemb = (const float*)d_in[29];
    float* out = (float*)d_out;

    const int TB = 256;
    dim3 gemm_grid((cN + 127) / 128, cD / 64);

    const float* xs[2]   = {x_i, x_j};
    const int*   eis[2]  = {ei_i, ei_j};
    const float* eas[2]  = {ea_i, ea_j};
    const int*   bats[2] = {bat_i, bat_j};

    for (int gi = 0; gi < 2; gi++) {
        const float* x  = xs[gi];
        const int* ei   = eis[gi];
        const float* ea = eas[gi];
        const int* bat  = bats[gi];

        // dtype detect + normalize indices to int32 device arrays
        k_flag_zero<<<1, 32>>>();
        k_detect<<<(cE + TB - 1) / TB, TB>>>(ei, 2 * cE, 0);
        k_detect<<<(cN / 2 + TB - 1) / TB, TB>>>(bat, cN, 1);
        k_cvt_edges<<<(2 * cE + TB - 1) / TB, TB>>>(ei);
        k_cvt_batch<<<(cN + TB - 1) / TB, TB>>>(bat);

        // CSR build (edges grouped by dst)
        k_csr_zero<<<(cN + TB - 1) / TB, TB>>>();
        k_hist<<<(cE + TB - 1) / TB, TB>>>();
        k_scan<<<1, 1024>>>();
        k_scatter<<<(cE + TB - 1) / TB, TB>>>();

        // conv 0 (input dim 4) + relu
        k_layer0<<<(cN * cD + TB - 1) / TB, TB>>>(x, W0q, b0q, W0k, b0k, W0v, b0v, W0s, b0s);
        k_edge<<<(cN + 7) / 8, TB>>>(ea, W0e, /*relu=*/1);

        // convs 1..5  (buffer ids: 0=g_h, 1=g_q, 2=g_k, 3=g_v, 4=g_hn)
        for (int l = 0; l < 5; l++) {
            const float* wq = Wq + (size_t)l * cD * cD;
            const float* wk = Wk + (size_t)l * cD * cD;
            const float* wv = Wv + (size_t)l * cD * cD;
            const float* ws = Ws + (size_t)l * cD * cD;
            const float* we = We + (size_t)l * cED * cD;
            k_gemm<<<gemm_grid, TB>>>(0, wq, bq + (size_t)l * cD, 1);
            k_gemm<<<gemm_grid, TB>>>(0, wk, bk + (size_t)l * cD, 2);
            k_gemm<<<gemm_grid, TB>>>(0, wv, bv + (size_t)l * cD, 3);
            k_gemm<<<gemm_grid, TB>>>(0, ws, bs + (size_t)l * cD, 4);
            k_edge<<<(cN + 7) / 8, TB>>>(ea, we, /*relu=*/(l < 4) ? 1 : 0);
        }

        // pool + head
        k_pool_zero<<<(cB * cD + TB - 1) / TB, TB>>>();
        k_pool<<<(cN + 7) / 8, TB>>>();
        k_head<<<cB, cD>>>(ln_g, ln_b, Wemb, bemb, gi);
    }

    k_cos<<<cB, 256>>>(out);
}

// round 8
// speedup vs baseline: 1.0937x; 1.0937x over previous
#include <cuda_runtime.h>
#include <cuda_bf16.h>
#include <cstdint>
#include <cstddef>
#include <math.h>

typedef unsigned int u32;

// Problem constants
constexpr int cN  = 10000;   // nodes
constexpr int cE  = 160000;  // edges
constexpr int cB  = 64;      // graphs in batch
constexpr int cD  = 640;     // hidden dim
constexpr int cND = 4;       // input node dim
constexpr int cED = 8;       // edge attr dim
constexpr int cL1 = 5;       // layers 1..5
constexpr int RPT = cD / 32; // 20 regs per lane across D

#define FULLMASK 0xffffffffu
#define SCALE 0.0395284707521047416f  // 1/sqrt(640)

// ---------------- scratch (static device globals; no allocs) ----------------
__device__ __align__(16) float g_h [cN * cD];
__device__ __align__(16) float g_q [cN * cD];
__device__ __align__(16) float g_k [cN * cD];
__device__ __align__(16) float g_v [cN * cD];
__device__ __align__(16) float g_hn[cN * cD];
__device__ __align__(16) __nv_bfloat16 g_ahi[cN * cD];
__device__ __align__(16) __nv_bfloat16 g_alo[cN * cD];
// weight splits, transposed: [layer][mat(q,k,v,s)][hi/lo][n=640][k=640]
__device__ __align__(16) __nv_bfloat16 g_wsp[cL1 * 4 * 2 * cD * cD];
__device__ int g_src[cE];
__device__ int g_dst[cE];
__device__ int g_bat[cN];
__device__ int g_flag[2];
__device__ int g_deg[cN];
__device__ int g_cur[cN];
__device__ int g_off[cN + 1];
__device__ int g_csr[cE];
__device__ __align__(16) float g_pool[cB * cD];
__device__ __align__(16) float g_z[2][cB * cD];

__device__ __forceinline__ float* buf_sel(int s) {
    switch (s) {
        case 0:  return g_h;
        case 1:  return g_q;
        case 2:  return g_k;
        case 3:  return g_v;
        default: return g_hn;
    }
}

// ---------------- tensor-core helpers ----------------
__device__ __forceinline__ u32 smem_u32(const void* p) {
    return (u32)__cvta_generic_to_shared(p);
}

__device__ __forceinline__ void ldsm4(u32& r0, u32& r1, u32& r2, u32& r3, u32 addr) {
    asm volatile("ldmatrix.sync.aligned.m8n8.x4.shared.b16 {%0,%1,%2,%3}, [%4];"
                 : "=r"(r0), "=r"(r1), "=r"(r2), "=r"(r3)
                 : "r"(addr));
}

__device__ __forceinline__ void mma16816(float* c, const u32* a, u32 b0, u32 b1) {
    asm volatile("mma.sync.aligned.m16n8k16.row.col.f32.bf16.bf16.f32 "
                 "{%0,%1,%2,%3}, {%4,%5,%6,%7}, {%8,%9}, {%0,%1,%2,%3};"
                 : "+f"(c[0]), "+f"(c[1]), "+f"(c[2]), "+f"(c[3])
                 : "r"(a[0]), "r"(a[1]), "r"(a[2]), "r"(a[3]), "r"(b0), "r"(b1));
}

// ---------------- dtype detection + normalization ----------------
__global__ void k_flag_zero() {
    if (threadIdx.x < 2) g_flag[threadIdx.x] = 0;
}

__global__ void k_detect(const int* __restrict__ p, int nelem, int slot) {
    int i = blockIdx.x * blockDim.x + threadIdx.x;
    int w = 2 * i + 1;
    if (w < nelem) {
        if (p[w] != 0) atomicOr(&g_flag[slot], 1);
    }
}

__global__ void k_cvt_edges(const int* __restrict__ p) {
    int e = blockIdx.x * blockDim.x + threadIdx.x;
    if (e >= 2 * cE) return;
    int is32 = g_flag[0];
    int v;
    if (is32) v = p[e];
    else      v = (int)((const long long*)p)[e];
    if (e < cE) g_src[e] = v;
    else        g_dst[e - cE] = v;
}

__global__ void k_cvt_batch(const int* __restrict__ p) {
    int n = blockIdx.x * blockDim.x + threadIdx.x;
    if (n >= cN) return;
    int is32 = g_flag[1];
    g_bat[n] = is32 ? p[n] : (int)((const long long*)p)[n];
}

// ---------------- CSR build ----------------
__global__ void k_csr_zero() {
    int i = blockIdx.x * blockDim.x + threadIdx.x;
    if (i < cN) { g_deg[i] = 0; g_cur[i] = 0; }
}

__global__ void k_hist() {
    int e = blockIdx.x * blockDim.x + threadIdx.x;
    if (e < cE) atomicAdd(&g_deg[g_dst[e]], 1);
}

__global__ void __launch_bounds__(1024) k_scan() {
    const int T = 1024;
    const int CH = (cN + T - 1) / T;
    int t = threadIdx.x;
    int vals[CH];
    int local = 0;
    int base = t * CH;
#pragma unroll
    for (int j = 0; j < CH; j++) {
        int idx = base + j;
        int v = (idx < cN) ? g_deg[idx] : 0;
        vals[j] = local;
        local += v;
    }
    __shared__ int sh[T];
    sh[t] = local;
    __syncthreads();
    for (int off = 1; off < T; off <<= 1) {
        int v = (t >= off) ? sh[t - off] : 0;
        __syncthreads();
        sh[t] += v;
        __syncthreads();
    }
    int prefix = sh[t] - local;
#pragma unroll
    for (int j = 0; j < CH; j++) {
        int idx = base + j;
        if (idx < cN) g_off[idx] = prefix + vals[j];
    }
    if (t == T - 1) g_off[cN] = sh[T - 1];
}

__global__ void k_scatter() {
    int e = blockIdx.x * blockDim.x + threadIdx.x;
    if (e < cE) {
        int d = g_dst[e];
        int p = atomicAdd(&g_cur[d], 1);
        g_csr[g_off[d] + p] = e;
    }
}

// ---------------- weight split + transpose (once; shared by both graphs) ------
__global__ void k_wconv(const float* __restrict__ Wq, const float* __restrict__ Wk,
                        const float* __restrict__ Wv, const float* __restrict__ Ws) {
    int z = blockIdx.z;          // layer*4 + mat
    int l = z >> 2;
    int m = z & 3;
    const float* Wsel;
    if (m == 0)      Wsel = Wq;
    else if (m == 1) Wsel = Wk;
    else if (m == 2) Wsel = Wv;
    else             Wsel = Ws;
    const float* W = Wsel + (size_t)l * cD * cD;

    __shared__ float tile[32][33];
    int k0 = blockIdx.x * 32;
    int n0 = blockIdx.y * 32;
    for (int i = threadIdx.y; i < 32; i += 8) {
        tile[i][threadIdx.x] = W[(size_t)(k0 + i) * cD + n0 + threadIdx.x];
    }
    __syncthreads();
    __nv_bfloat16* hi = g_wsp + ((size_t)z * 2 + 0) * cD * cD;
    __nv_bfloat16* lo = g_wsp + ((size_t)z * 2 + 1) * cD * cD;
    for (int i = threadIdx.y; i < 32; i += 8) {
        float wv = tile[threadIdx.x][i];      // = W[k0+tx][n0+i]
        __nv_bfloat16 h = __float2bfloat16(wv);
        float r = wv - __bfloat162float(h);
        hi[(size_t)(n0 + i) * cD + k0 + threadIdx.x] = h;
        lo[(size_t)(n0 + i) * cD + k0 + threadIdx.x] = __float2bfloat16(r);
    }
}

// ---------------- activation split: g_h -> (g_ahi, g_alo) ----------------
__global__ void k_split_h() {
    int i = blockIdx.x * blockDim.x + threadIdx.x;
    if (i >= cN * cD) return;
    float w = g_h[i];
    __nv_bfloat16 h = __float2bfloat16(w);
    g_ahi[i] = h;
    g_alo[i] = __float2bfloat16(w - __bfloat162float(h));
}

// ---------------- layer 0 projections (input dim = 4) ----------------
__global__ void k_layer0(const float* __restrict__ x,
                         const float* __restrict__ Wq, const float* __restrict__ bq,
                         const float* __restrict__ Wk, const float* __restrict__ bk,
                         const float* __restrict__ Wv, const float* __restrict__ bv,
                         const float* __restrict__ Ws, const float* __restrict__ bs) {
    int idx = blockIdx.x * blockDim.x + threadIdx.x;
    if (idx >= cN * cD) return;
    int n = idx / cD;
    int d = idx - n * cD;
    float x0 = x[n * cND + 0];
    float x1 = x[n * cND + 1];
    float x2 = x[n * cND + 2];
    float x3 = x[n * cND + 3];
    float aq = bq[d] + x0 * Wq[0 * cD + d] + x1 * Wq[1 * cD + d] + x2 * Wq[2 * cD + d] + x3 * Wq[3 * cD + d];
    float ak = bk[d] + x0 * Wk[0 * cD + d] + x1 * Wk[1 * cD + d] + x2 * Wk[2 * cD + d] + x3 * Wk[3 * cD + d];
    float av = bv[d] + x0 * Wv[0 * cD + d] + x1 * Wv[1 * cD + d] + x2 * Wv[2 * cD + d] + x3 * Wv[3 * cD + d];
    float as = bs[d] + x0 * Ws[0 * cD + d] + x1 * Ws[1 * cD + d] + x2 * Ws[2 * cD + d] + x3 * Ws[3 * cD + d];
    g_q[idx] = aq;
    g_k[idx] = ak;
    g_v[idx] = av;
    g_hn[idx] = as;
}

// ---------------- fused edge aggregation (one warp per node, online softmax) ---
__global__ void __launch_bounds__(256) k_edge(const float* __restrict__ ea,
                                              const float* __restrict__ We,
                                              int do_relu) {
    int w = (blockIdx.x * blockDim.x + threadIdx.x) >> 5;
    int lane = threadIdx.x & 31;
    if (w >= cN) return;
    const int n = w;

    float qr[RPT];
#pragma unroll
    for (int i = 0; i < RPT; i++) qr[i] = g_q[(size_t)n * cD + lane + 32 * i];

    float qe[cED];
#pragma unroll
    for (int c = 0; c < cED; c++) {
        float p = 0.f;
#pragma unroll
        for (int i = 0; i < RPT; i++) p += qr[i] * We[c * cD + lane + 32 * i];
#pragma unroll
        for (int o = 16; o > 0; o >>= 1) p += __shfl_xor_sync(FULLMASK, p, o);
        qe[c] = p;
    }

    float m = -1e30f;
    float s = 0.f;
    float acc[RPT];
    float av[cED];
#pragma unroll
    for (int i = 0; i < RPT; i++) acc[i] = 0.f;
#pragma unroll
    for (int c = 0; c < cED; c++) av[c] = 0.f;

    int beg = g_off[n];
    int end = g_off[n + 1];
    for (int idx = beg; idx < end; idx++) {
        int e = g_csr[idx];
        int sn = g_src[e];
        const float* kr = g_k + (size_t)sn * cD;
        const float* vr = g_v + (size_t)sn * cD;
        float eav[cED];
#pragma unroll
        for (int c = 0; c < cED; c++) eav[c] = ea[(size_t)e * cED + c];
        float dp = 0.f;
#pragma unroll
        for (int i = 0; i < RPT; i++) dp += qr[i] * kr[lane + 32 * i];
#pragma unroll
        for (int o = 16; o > 0; o >>= 1) dp += __shfl_xor_sync(FULLMASK, dp, o);
        float sc = dp;
#pragma unroll
        for (int c = 0; c < cED; c++) sc += qe[c] * eav[c];
        sc *= SCALE;

        float mn  = fmaxf(m, sc);
        float f   = __expf(m - mn);
        float wgt = __expf(sc - mn);
        s = s * f + wgt;
#pragma unroll
        for (int i = 0; i < RPT; i++) acc[i] = acc[i] * f + wgt * vr[lane + 32 * i];
#pragma unroll
        for (int c = 0; c < cED; c++) av[c] = av[c] * f + wgt * eav[c];
        m = mn;
    }

    float inv = 1.f / (s + 1e-16f);
#pragma unroll
    for (int i = 0; i < RPT; i++) {
        int d = lane + 32 * i;
        float ep = 0.f;
#pragma unroll
        for (int c = 0; c < cED; c++) ep += av[c] * We[c * cD + d];
        float o = g_hn[(size_t)n * cD + d] + (acc[i] + ep) * inv;
        if (do_relu) o = fmaxf(o, 0.f);
        g_h[(size_t)n * cD + d] = o;
    }
}

// ---------------- tensor-core split-bf16 GEMM -----------------------------
// C = A @ W + bias; 3-term split Ahi@Whi + Ahi@Wlo + Alo@Whi, fp32 accum.
// Block tile 128x64, k-chunk 32; 8 warps (4M x 2N), warp tile 32x32.
// blockIdx.z selects matrix (0=q,1=k,2=v,3=s).
__global__ void __launch_bounds__(256) k_gemm_t(int layer,
                                                const float* __restrict__ bq,
                                                const float* __restrict__ bk,
                                                const float* __restrict__ bv,
                                                const float* __restrict__ bs) {
    int z = blockIdx.z;
    const __nv_bfloat16* Whi = g_wsp + ((size_t)(layer * 4 + z) * 2 + 0) * cD * cD;
    const __nv_bfloat16* Wlo = Whi + (size_t)cD * cD;
    const float* bias;
    if (z == 0)      bias = bq;
    else if (z == 1) bias = bk;
    else if (z == 2) bias = bv;
    else             bias = bs;
    float* outp = buf_sel(z + 1);

    __shared__ __align__(16) __nv_bfloat16 sAh[128][40];
    __shared__ __align__(16) __nv_bfloat16 sAl[128][40];
    __shared__ __align__(16) __nv_bfloat16 sBh[64][40];
    __shared__ __align__(16) __nv_bfloat16 sBl[64][40];

    int tid  = threadIdx.x;
    int lane = tid & 31;
    int warp = tid >> 5;
    int wm = warp & 3;
    int wn = warp >> 2;
    int bm = blockIdx.x * 128;
    int bn = blockIdx.y * 64;

    float acc[2][4][4];
#pragma unroll
    for (int i = 0; i < 2; i++) {
#pragma unroll
        for (int j = 0; j < 4; j++) {
#pragma unroll
            for (int c = 0; c < 4; c++) acc[i][j][c] = 0.f;
        }
    }

    int lrow = lane & 15;
    int lcol = (lane >> 4) * 8;

    for (int k0 = 0; k0 < cD; k0 += 32) {
        // A tiles: 128 rows x 32 k (hi+lo), 16B vector loads
#pragma unroll
        for (int r = 0; r < 2; r++) {
            int vidx = tid + 256 * r;           // 0..511
            int row = vidx >> 2;
            int kc = (vidx & 3) * 8;
            size_t gaddr = (size_t)(bm + row) * cD + k0 + kc;
            uint4 dh;
            uint4 dl;
            if (bm + row < cN) {
                dh = *(const uint4*)(g_ahi + gaddr);
                dl = *(const uint4*)(g_alo + gaddr);
            } else {
                dh = make_uint4(0u, 0u, 0u, 0u);
                dl = make_uint4(0u, 0u, 0u, 0u);
            }
            *(uint4*)(&sAh[row][kc]) = dh;
            *(uint4*)(&sAl[row][kc]) = dl;
        }
        // B tiles: 64 n-rows x 32 k
        {
            int row = tid >> 2;
            int kc = (tid & 3) * 8;
            size_t gaddr = (size_t)(bn + row) * cD + k0 + kc;
            *(uint4*)(&sBh[row][kc]) = *(const uint4*)(Whi + gaddr);
            *(uint4*)(&sBl[row][kc]) = *(const uint4*)(Wlo + gaddr);
        }
        __syncthreads();

#pragma unroll
        for (int ks = 0; ks < 32; ks += 16) {
            u32 ah[2][4];
            u32 al[2][4];
            u32 bh[2][4];
            u32 bl[2][4];
#pragma unroll
            for (int mi = 0; mi < 2; mi++) {
                ldsm4(ah[mi][0], ah[mi][1], ah[mi][2], ah[mi][3],
                      smem_u32(&sAh[wm * 32 + mi * 16 + lrow][ks + lcol]));
                ldsm4(al[mi][0], al[mi][1], al[mi][2], al[mi][3],
                      smem_u32(&sAl[wm * 32 + mi * 16 + lrow][ks + lcol]));
            }
#pragma unroll
            for (int gg = 0; gg < 2; gg++) {
                ldsm4(bh[gg][0], bh[gg][1], bh[gg][2], bh[gg][3],
                      smem_u32(&sBh[wn * 32 + gg * 16 + lrow][ks + lcol]));
                ldsm4(bl[gg][0], bl[gg][1], bl[gg][2], bl[gg][3],
                      smem_u32(&sBl[wn * 32 + gg * 16 + lrow][ks + lcol]));
            }
#pragma unroll
            for (int mi = 0; mi < 2; mi++) {
#pragma unroll
                for (int nj = 0; nj < 4; nj++) {
                    int gg = nj >> 1;
                    int xx = nj & 1;
                    mma16816(acc[mi][nj], ah[mi], bh[gg][xx], bh[gg][xx + 2]);
                    mma16816(acc[mi][nj], ah[mi], bl[gg][xx], bl[gg][xx + 2]);
                    mma16816(acc[mi][nj], al[mi], bh[gg][xx], bh[gg][xx + 2]);
                }
            }
        }
        __syncthreads();
    }

    // epilogue: c0/c1 -> (row=gid, col=tig*2+0/1); c2/c3 -> row+8
    int gid = lane >> 2;
    int tig = lane & 3;
#pragma unroll
    for (int mi = 0; mi < 2; mi++) {
#pragma unroll
        for (int nj = 0; nj < 4; nj++) {
            int colg = bn + wn * 32 + nj * 8 + tig * 2;
            float bias0 = bias[colg];
            float bias1 = bias[colg + 1];
            int r0 = bm + wm * 32 + mi * 16 + gid;
            if (r0 < cN) {
                float2 o0;
                o0.x = acc[mi][nj][0] + bias0;
                o0.y = acc[mi][nj][1] + bias1;
                *(float2*)(outp + (size_t)r0 * cD + colg) = o0;
            }
            int r1 = r0 + 8;
            if (r1 < cN) {
                float2 o1;
                o1.x = acc[mi][nj][2] + bias0;
                o1.y = acc[mi][nj][3] + bias1;
                *(float2*)(outp + (size_t)r1 * cD + colg) = o1;
            }
        }
    }
}

// ---------------- pooling ----------------
__global__ void k_pool_zero() {
    int i = blockIdx.x * blockDim.x + threadIdx.x;
    if (i < cB * cD) g_pool[i] = 0.f;
}

__global__ void k_pool() {
    int w = (blockIdx.x * blockDim.x + threadIdx.x) >> 5;
    int lane = threadIdx.x & 31;
    if (w >= cN) return;
    int b = g_bat[w];
#pragma unroll
    for (int i = 0; i < RPT; i++) {
        atomicAdd(&g_pool[b * cD + lane + 32 * i], g_h[(size_t)w * cD + lane + 32 * i]);
    }
}

// ---------------- LN + Linear + ReLU head (per graph) ----------------
__global__ void __launch_bounds__(640) k_head(const float* __restrict__ ln_g,
                                              const float* __restrict__ ln_b,
                                              const float* __restrict__ Wemb,
                                              const float* __restrict__ bemb,
                                              int gi) {
    int b = blockIdx.x;
    int t = threadIdx.x;
    __shared__ float red[20];
    __shared__ float zsh[cD];
    __shared__ float s_mu;
    __shared__ float s_rs;
    float x = g_pool[b * cD + t];

    float v = x;
#pragma unroll
    for (int o = 16; o > 0; o >>= 1) v += __shfl_xor_sync(FULLMASK, v, o);
    if ((t & 31) == 0) red[t >> 5] = v;
    __syncthreads();
    if (t == 0) {
        float s = 0.f;
        for (int i = 0; i < 20; i++) s += red[i];
        s_mu = s / cD;
    }
    __syncthreads();
    float dev = x - s_mu;
    v = dev * dev;
#pragma unroll
    for (int o = 16; o > 0; o >>= 1) v += __shfl_xor_sync(FULLMASK, v, o);
    if ((t & 31) == 0) red[t >> 5] = v;
    __syncthreads();
    if (t == 0) {
        float s = 0.f;
        for (int i = 0; i < 20; i++) s += red[i];
        s_rs = rsqrtf(s / cD + 1e-5f);
    }
    __syncthreads();
    zsh[t] = dev * s_rs * ln_g[t] + ln_b[t];
    __syncthreads();

    float o = bemb[t];
#pragma unroll 4
    for (int kk = 0; kk < cD; kk++) o += zsh[kk] * Wemb[(size_t)kk * cD + t];
    g_z[gi][b * cD + t] = fmaxf(o, 0.f);
}

// ---------------- cosine ----------------
__global__ void k_cos(float* __restrict__ out) {
    int b = blockIdx.x;
    int t = threadIdx.x;
    float dp = 0.f;
    float ai = 0.f;
    float aj = 0.f;
    for (int d = t; d < cD; d += 256) {
        float zi = g_z[0][b * cD + d];
        float zj = g_z[1][b * cD + d];
        dp += zi * zj;
        ai += zi * zi;
        aj += zj * zj;
    }
#pragma unroll
    for (int o = 16; o > 0; o >>= 1) {
        dp += __shfl_xor_sync(FULLMASK, dp, o);
        ai += __shfl_xor_sync(FULLMASK, ai, o);
        aj += __shfl_xor_sync(FULLMASK, aj, o);
    }
    __shared__ float r1[8];
    __shared__ float r2[8];
    __shared__ float r3[8];
    int wd = t >> 5;
    if ((t & 31) == 0) { r1[wd] = dp; r2[wd] = ai; r3[wd] = aj; }
    __syncthreads();
    if (t == 0) {
        float sD = 0.f;
        float sA = 0.f;
        float sB = 0.f;
        for (int i = 0; i < 8; i++) { sD += r1[i]; sA += r2[i]; sB += r3[i]; }
        out[b] = sD / (fmaxf(sqrtf(sA), 1e-8f) * fmaxf(sqrtf(sB), 1e-8f));
    }
}

// ---------------- driver: PURE kernel launches ----------------
extern "C" void kernel_launch(void* const* d_in, const int* in_sizes, int n_in,
                              void* d_out, int out_size) {
    const float* x_i   = (const float*)d_in[0];
    const int*   ei_i  = (const int*)d_in[1];
    const float* ea_i  = (const float*)d_in[2];
    const int*   bat_i = (const int*)d_in[3];
    const float* x_j   = (const float*)d_in[4];
    const int*   ei_j  = (const int*)d_in[5];
    const float* ea_j  = (const float*)d_in[6];
    const int*   bat_j = (const int*)d_in[7];
    const float* W0q = (const float*)d_in[8];
    const float* b0q = (const float*)d_in[9];
    const float* W0k = (const float*)d_in[10];
    const float* b0k = (const float*)d_in[11];
    const float* W0v = (const float*)d_in[12];
    const float* b0v = (const float*)d_in[13];
    const float* W0e = (const float*)d_in[14];
    const float* W0s = (const float*)d_in[15];
    const float* b0s = (const float*)d_in[16];
    const float* Wq  = (const float*)d_in[17];
    const float* bq  = (const float*)d_in[18];
    const float* Wk  = (const float*)d_in[19];
    const float* bk  = (const float*)d_in[20];
    const float* Wv  = (const float*)d_in[21];
    const float* bv  = (const float*)d_in[22];
    const float* We  = (const float*)d_in[23];
    const float* Ws  = (const float*)d_in[24];
    const float* bs  = (const float*)d_in[25];
    const float* ln_g = (const float*)d_in[26];
    const float* ln_b = (const float*)d_in[27];
    const float* Wemb = (const float*)d_in[28];
    const float* bemb = (const float*)d_in[29];
    float* out = (float*)d_out;

    const int TB = 256;

    // weight split+transpose once (shared by both graphs)
    dim3 wgrid(cD / 32, cD / 32, cL1 * 4);
    dim3 wblock(32, 8, 1);
    k_wconv<<<wgrid, wblock>>>(Wq, Wk, Wv, Ws);

    dim3 gemm_grid((cN + 127) / 128, cD / 64, 4);

    const float* xs[2];
    xs[0] = x_i;  xs[1] = x_j;
    const int* eis[2];
    eis[0] = ei_i;  eis[1] = ei_j;
    const float* eas[2];
    eas[0] = ea_i;  eas[1] = ea_j;
    const int* bats[2];
    bats[0] = bat_i;  bats[1] = bat_j;

    for (int gi = 0; gi < 2; gi++) {
        const float* x  = xs[gi];
        const int* ei   = eis[gi];
        const float* ea = eas[gi];
        const int* bat  = bats[gi];

        // dtype detect + normalize indices to int32
        k_flag_zero<<<1, 32>>>();
        k_detect<<<(cE + TB - 1) / TB, TB>>>(ei, 2 * cE, 0);
        k_detect<<<(cN / 2 + TB - 1) / TB, TB>>>(bat, cN, 1);
        k_cvt_edges<<<(2 * cE + TB - 1) / TB, TB>>>(ei);
        k_cvt_batch<<<(cN + TB - 1) / TB, TB>>>(bat);

        // CSR build
        k_csr_zero<<<(cN + TB - 1) / TB, TB>>>();
        k_hist<<<(cE + TB - 1) / TB, TB>>>();
        k_scan<<<1, 1024>>>();
        k_scatter<<<(cE + TB - 1) / TB, TB>>>();

        // conv 0 (input dim 4) + relu
        k_layer0<<<(cN * cD + TB - 1) / TB, TB>>>(x, W0q, b0q, W0k, b0k, W0v, b0v, W0s, b0s);
        k_edge<<<(cN + 7) / 8, TB>>>(ea, W0e, 1);

        // convs 1..5: split A, tensor GEMM (q,k,v,s via blockIdx.z), edge
        for (int l = 0; l < cL1; l++) {
            k_split_h<<<(cN * cD + TB - 1) / TB, TB>>>();
            k_gemm_t<<<gemm_grid, TB>>>(l,
                bq + (size_t)l * cD, bk + (size_t)l * cD,
                bv + (size_t)l * cD, bs + (size_t)l * cD);
            int dorelu = (l < 4) ? 1 : 0;
            k_edge<<<(cN + 7) / 8, TB>>>(ea, We + (size_t)l * cED * cD, dorelu);
        }

        // pool + head
        k_pool_zero<<<(cB * cD + TB - 1) / TB, TB>>>();
        k_pool<<<(cN + 7) / 8, TB>>>();
        k_head<<<cB, cD>>>(ln_g, ln_b, Wemb, bemb, gi);
    }

    k_cos<<<cB, 256>>>(out);
}

// round 10
// speedup vs baseline: 1.4211x; 1.2993x over previous
#include <cuda_runtime.h>
#include <cuda_bf16.h>
#include <cstdint>
#include <cstddef>
#include <math.h>

typedef unsigned int u32;
typedef unsigned long long u64;

// Problem constants
constexpr int cN  = 10000;
constexpr int cE  = 160000;
constexpr int cB  = 64;
constexpr int cD  = 640;
constexpr int cND = 4;
constexpr int cED = 8;
constexpr int cL1 = 5;
constexpr int RPT = cD / 32;

#define FULLMASK 0xffffffffu
#define SCALE 0.0395284707521047416f  // 1/sqrt(640)

// ---------------- scratch ----------------
__device__ __align__(16) float g_h [cN * cD];
__device__ __align__(16) float g_q [cN * cD];
__device__ __align__(16) float g_k [cN * cD];
__device__ __align__(16) float g_v [cN * cD];
__device__ __align__(16) float g_hn[cN * cD];
__device__ __align__(16) __nv_bfloat16 g_ahi[cN * cD];
__device__ __align__(16) __nv_bfloat16 g_alo[cN * cD];
// weight splits, transposed: [layer][mat(q,k,v,s)][hi/lo][n=640][k=640]
__device__ __align__(16) __nv_bfloat16 g_wsp[cL1 * 4 * 2 * cD * cD];
__device__ int g_src[cE];
__device__ int g_dst[cE];
__device__ int g_bat[cN];
__device__ int g_flag[4];
__device__ int g_deg[cN];
__device__ int g_cur[cN];
__device__ int g_off[cN + 1];
__device__ int g_csr[cE];
__device__ __align__(16) float g_pool[cB * cD];
__device__ __align__(16) float g_z[2][cB * cD];

__device__ __forceinline__ float* buf_sel(int s) {
    switch (s) {
        case 0:  return g_h;
        case 1:  return g_q;
        case 2:  return g_k;
        case 3:  return g_v;
        default: return g_hn;
    }
}

__device__ __forceinline__ u32 smem_u32(const void* p) {
    return (u32)__cvta_generic_to_shared(p);
}

__device__ __forceinline__ void ldsm4(u32& r0, u32& r1, u32& r2, u32& r3, u32 addr) {
    asm volatile("ldmatrix.sync.aligned.m8n8.x4.shared.b16 {%0,%1,%2,%3}, [%4];"
                 : "=r"(r0), "=r"(r1), "=r"(r2), "=r"(r3)
                 : "r"(addr));
}

__device__ __forceinline__ void mma16816(float* c, const u32* a, u32 b0, u32 b1) {
    asm volatile("mma.sync.aligned.m16n8k16.row.col.f32.bf16.bf16.f32 "
                 "{%0,%1,%2,%3}, {%4,%5,%6,%7}, {%8,%9}, {%0,%1,%2,%3};"
                 : "+f"(c[0]), "+f"(c[1]), "+f"(c[2]), "+f"(c[3])
                 : "r"(a[0]), "r"(a[1]), "r"(a[2]), "r"(a[3]), "r"(b0), "r"(b1));
}

template <int N>
__device__ __forceinline__ void cp_wait() {
    asm volatile("cp.async.wait_group %0;" :: "n"(N) : "memory");
}

__device__ __forceinline__ void cp_commit() {
    asm volatile("cp.async.commit_group;" ::: "memory");
}

// ---------------- GEMM config (mma.sync pipelined) ----------------
constexpr int ST = 3;                 // pipeline stages
constexpr int CK = 32;                // k elems per chunk
constexpr int NC = cD / CK;           // 20
constexpr int ROWB  = 80;             // 64B data + 16B pad per row
constexpr int PARTB = 128 * ROWB;     // 10240 B (one 128x32 bf16 part)
constexpr int STAGEB = 4 * PARTB;     // Ah, Al, Bh, Bl
constexpr int GSMEM = ST * STAGEB;    // 122880 B

// load one 128x32 bf16 part into padded smem via cp.async (zero-fill OOB rows)
__device__ __forceinline__ void ld_part(u32 sdst, const __nv_bfloat16* g,
                                        int row0, int rmax, int col0, int tid) {
#pragma unroll
    for (int i = 0; i < 2; i++) {
        int seg = tid + i * 256;          // 0..511
        int row = seg >> 2;
        int s4  = seg & 3;
        u32 dst = sdst + (u32)(row * ROWB + s4 * 16);
        const void* src = (const void*)(g + (size_t)(row0 + row) * cD + col0 + s4 * 8);
        int ok = (row0 + row < rmax) ? 16 : 0;
        asm volatile("cp.async.cg.shared.global [%0], [%1], 16, %2;"
                     :: "r"(dst), "l"(src), "r"(ok) : "memory");
    }
}

// C = A @ W + bias; 3-term bf16 split, fp32 accum.
// block 128x128, 8 warps (2M x 4N), warp tile 64x32. grid (79, 5, mat)
__global__ void __launch_bounds__(256) k_gemm_m(int layer,
                                                const float* __restrict__ bq,
                                                const float* __restrict__ bk,
                                                const float* __restrict__ bv,
                                                const float* __restrict__ bs) {
    extern __shared__ char smem[];
    u32 sb = smem_u32(smem);
    int tid = threadIdx.x;
    int lane = tid & 31;
    int warp = tid >> 5;
    int wm = warp & 1;       // 0..1 -> 64 rows each
    int wn = warp >> 1;      // 0..3 -> 32 cols each
    int z = blockIdx.z;

    const __nv_bfloat16* Whi = g_wsp + ((size_t)(layer * 4 + z) * 2 + 0) * cD * cD;
    const __nv_bfloat16* Wlo = Whi + (size_t)cD * cD;
    const float* bias;
    if (z == 0)      bias = bq;
    else if (z == 1) bias = bk;
    else if (z == 2) bias = bv;
    else             bias = bs;
    float* outp = buf_sel(z + 1);

    int bm = blockIdx.x * 128;
    int bn = blockIdx.y * 128;

    float acc[4][4][4];
#pragma unroll
    for (int mi = 0; mi < 4; mi++) {
#pragma unroll
        for (int nj = 0; nj < 4; nj++) {
#pragma unroll
            for (int c = 0; c < 4; c++) acc[mi][nj][c] = 0.f;
        }
    }

    // prologue: stages 0, 1
#pragma unroll
    for (int c = 0; c < 2; c++) {
        u32 st = sb + (u32)(c * STAGEB);
        int col0 = c * CK;
        ld_part(st,             g_ahi, bm, cN, col0, tid);
        ld_part(st + PARTB,     g_alo, bm, cN, col0, tid);
        ld_part(st + 2 * PARTB, Whi,   bn, cD, col0, tid);
        ld_part(st + 3 * PARTB, Wlo,   bn, cD, col0, tid);
        cp_commit();
    }

    int lrow = lane & 15;
    int lcol = (lane >> 4) * 8;

    for (int c = 0; c < NC; c++) {
        if (c < NC - 1) cp_wait<1>();
        else            cp_wait<0>();
        __syncthreads();

        if (c + 2 < NC) {
            u32 st2 = sb + (u32)(((c + 2) % ST) * STAGEB);
            int col0 = (c + 2) * CK;
            ld_part(st2,             g_ahi, bm, cN, col0, tid);
            ld_part(st2 + PARTB,     g_alo, bm, cN, col0, tid);
            ld_part(st2 + 2 * PARTB, Whi,   bn, cD, col0, tid);
            ld_part(st2 + 3 * PARTB, Wlo,   bn, cD, col0, tid);
            cp_commit();
        }

        u32 st = sb + (u32)((c % ST) * STAGEB);
#pragma unroll
        for (int ks = 0; ks < CK; ks += 16) {
            u32 ah[4][4];
            u32 al[4][4];
            u32 bh[2][4];
            u32 bl[2][4];
            u32 kb = (u32)((ks + lcol) * 2);
#pragma unroll
            for (int mi = 0; mi < 4; mi++) {
                u32 ra = st + (u32)((wm * 64 + mi * 16 + lrow) * ROWB) + kb;
                ldsm4(ah[mi][0], ah[mi][1], ah[mi][2], ah[mi][3], ra);
                ldsm4(al[mi][0], al[mi][1], al[mi][2], al[mi][3], ra + (u32)PARTB);
            }
#pragma unroll
            for (int gg = 0; gg < 2; gg++) {
                u32 rb = st + (u32)(2 * PARTB) + (u32)((wn * 32 + gg * 16 + lrow) * ROWB) + kb;
                ldsm4(bh[gg][0], bh[gg][1], bh[gg][2], bh[gg][3], rb);
                ldsm4(bl[gg][0], bl[gg][1], bl[gg][2], bl[gg][3], rb + (u32)PARTB);
            }
#pragma unroll
            for (int mi = 0; mi < 4; mi++) {
#pragma unroll
                for (int nj = 0; nj < 4; nj++) {
                    int gg = nj >> 1;
                    int xx = nj & 1;
                    mma16816(acc[mi][nj], ah[mi], bh[gg][xx], bh[gg][xx + 2]);
                    mma16816(acc[mi][nj], ah[mi], bl[gg][xx], bl[gg][xx + 2]);
                    mma16816(acc[mi][nj], al[mi], bh[gg][xx], bh[gg][xx + 2]);
                }
            }
        }
    }

    // epilogue
    int gid = lane >> 2;
    int tig = lane & 3;
#pragma unroll
    for (int mi = 0; mi < 4; mi++) {
#pragma unroll
        for (int nj = 0; nj < 4; nj++) {
            int colg = bn + wn * 32 + nj * 8 + tig * 2;
            float bias0 = bias[colg];
            float bias1 = bias[colg + 1];
            int r0 = bm + wm * 64 + mi * 16 + gid;
            if (r0 < cN) {
                float2 o0;
                o0.x = acc[mi][nj][0] + bias0;
                o0.y = acc[mi][nj][1] + bias1;
                *(float2*)(outp + (size_t)r0 * cD + colg) = o0;
            }
            int r1 = r0 + 8;
            if (r1 < cN) {
                float2 o1;
                o1.x = acc[mi][nj][2] + bias0;
                o1.y = acc[mi][nj][3] + bias1;
                *(float2*)(outp + (size_t)r1 * cD + colg) = o1;
            }
        }
    }
}

// ---------------- dtype detect ----------------
__global__ void k_detect2(const int* __restrict__ ei, const int* __restrict__ bat,
                          int slotbase) {
    int i = blockIdx.x * blockDim.x + threadIdx.x;
    if (i < cE) {
        if (ei[2 * i + 1] != 0) atomicOr(&g_flag[slotbase], 1);
    } else {
        int j = i - cE;
        if (j < cN / 2) {
            if (bat[2 * j + 1] != 0) atomicOr(&g_flag[slotbase + 1], 1);
        }
    }
}

// ---------------- normalize indices + zero counters ----------------
__global__ void k_prep(const int* __restrict__ ei, const int* __restrict__ bat,
                       int slotbase) {
    int i = blockIdx.x * blockDim.x + threadIdx.x;
    if (i < 2 * cE) {
        int is32 = g_flag[slotbase];
        int v;
        if (is32) v = ei[i];
        else      v = (int)((const long long*)ei)[i];
        if (i < cE) g_src[i] = v;
        else        g_dst[i - cE] = v;
    }
    if (i < cN) {
        int is32b = g_flag[slotbase + 1];
        g_bat[i] = is32b ? bat[i] : (int)((const long long*)bat)[i];
        g_deg[i] = 0;
        g_cur[i] = 0;
    }
}

// ---------------- CSR build ----------------
__global__ void k_hist() {
    int e = blockIdx.x * blockDim.x + threadIdx.x;
    if (e < cE) atomicAdd(&g_deg[g_dst[e]], 1);
}

__global__ void __launch_bounds__(1024) k_scan() {
    const int T = 1024;
    const int CH = (cN + T - 1) / T;
    int t = threadIdx.x;
    int vals[CH];
    int local = 0;
    int base = t * CH;
#pragma unroll
    for (int j = 0; j < CH; j++) {
        int idx = base + j;
        int v = (idx < cN) ? g_deg[idx] : 0;
        vals[j] = local;
        local += v;
    }
    __shared__ int sh[T];
    sh[t] = local;
    __syncthreads();
    for (int off = 1; off < T; off <<= 1) {
        int v = (t >= off) ? sh[t - off] : 0;
        __syncthreads();
        sh[t] += v;
        __syncthreads();
    }
    int prefix = sh[t] - local;
#pragma unroll
    for (int j = 0; j < CH; j++) {
        int idx = base + j;
        if (idx < cN) g_off[idx] = prefix + vals[j];
    }
    if (t == T - 1) g_off[cN] = sh[T - 1];
}

__global__ void k_scatter() {
    int e = blockIdx.x * blockDim.x + threadIdx.x;
    if (e < cE) {
        int d = g_dst[e];
        int p = atomicAdd(&g_cur[d], 1);
        g_csr[g_off[d] + p] = e;
    }
}

// ---------------- weight split + transpose (+ flag zero) ----------------
__global__ void k_wconv(const float* __restrict__ Wq, const float* __restrict__ Wk,
                        const float* __restrict__ Wv, const float* __restrict__ Ws) {
    if (blockIdx.x == 0 && blockIdx.y == 0 && blockIdx.z == 0 &&
        threadIdx.y == 0 && threadIdx.x < 4) {
        g_flag[threadIdx.x] = 0;
    }
    int z = blockIdx.z;
    int l = z >> 2;
    int m = z & 3;
    const float* Wsel;
    if (m == 0)      Wsel = Wq;
    else if (m == 1) Wsel = Wk;
    else if (m == 2) Wsel = Wv;
    else             Wsel = Ws;
    const float* W = Wsel + (size_t)l * cD * cD;

    __shared__ float tile[32][33];
    int k0 = blockIdx.x * 32;
    int n0 = blockIdx.y * 32;
    for (int i = threadIdx.y; i < 32; i += 8) {
        tile[i][threadIdx.x] = W[(size_t)(k0 + i) * cD + n0 + threadIdx.x];
    }
    __syncthreads();
    __nv_bfloat16* hi = g_wsp + ((size_t)z * 2 + 0) * cD * cD;
    __nv_bfloat16* lo = g_wsp + ((size_t)z * 2 + 1) * cD * cD;
    for (int i = threadIdx.y; i < 32; i += 8) {
        float wv = tile[threadIdx.x][i];
        __nv_bfloat16 h = __float2bfloat16(wv);
        float r = wv - __bfloat162float(h);
        hi[(size_t)(n0 + i) * cD + k0 + threadIdx.x] = h;
        lo[(size_t)(n0 + i) * cD + k0 + threadIdx.x] = __float2bfloat16(r);
    }
}

// ---------------- layer 0 projections ----------------
__global__ void k_layer0(const float* __restrict__ x,
                         const float* __restrict__ Wq, const float* __restrict__ bq,
                         const float* __restrict__ Wk, const float* __restrict__ bk,
                         const float* __restrict__ Wv, const float* __restrict__ bv,
                         const float* __restrict__ Ws, const float* __restrict__ bs) {
    int idx = blockIdx.x * blockDim.x + threadIdx.x;
    if (idx >= cN * cD) return;
    int n = idx / cD;
    int d = idx - n * cD;
    float x0 = x[n * cND + 0];
    float x1 = x[n * cND + 1];
    float x2 = x[n * cND + 2];
    float x3 = x[n * cND + 3];
    float aq = bq[d] + x0 * Wq[0 * cD + d] + x1 * Wq[1 * cD + d] + x2 * Wq[2 * cD + d] + x3 * Wq[3 * cD + d];
    float ak = bk[d] + x0 * Wk[0 * cD + d] + x1 * Wk[1 * cD + d] + x2 * Wk[2 * cD + d] + x3 * Wk[3 * cD + d];
    float av = bv[d] + x0 * Wv[0 * cD + d] + x1 * Wv[1 * cD + d] + x2 * Wv[2 * cD + d] + x3 * Wv[3 * cD + d];
    float as = bs[d] + x0 * Ws[0 * cD + d] + x1 * Ws[1 * cD + d] + x2 * Ws[2 * cD + d] + x3 * Ws[3 * cD + d];
    g_q[idx] = aq;
    g_k[idx] = ak;
    g_v[idx] = av;
    g_hn[idx] = as;
}

// ---------------- fused edge aggregation (+ bf16 split of output) ----------
__global__ void __launch_bounds__(256) k_edge(const float* __restrict__ ea,
                                              const float* __restrict__ We,
                                              int do_relu) {
    int w = (blockIdx.x * blockDim.x + threadIdx.x) >> 5;
    int lane = threadIdx.x & 31;
    if (w >= cN) return;
    const int n = w;

    float qr[RPT];
#pragma unroll
    for (int i = 0; i < RPT; i++) qr[i] = g_q[(size_t)n * cD + lane + 32 * i];

    float qe[cED];
#pragma unroll
    for (int c = 0; c < cED; c++) {
        float p = 0.f;
#pragma unroll
        for (int i = 0; i < RPT; i++) p += qr[i] * We[c * cD + lane + 32 * i];
#pragma unroll
        for (int o = 16; o > 0; o >>= 1) p += __shfl_xor_sync(FULLMASK, p, o);
        qe[c] = p;
    }

    float m = -1e30f;
    float s = 0.f;
    float acc[RPT];
    float av[cED];
#pragma unroll
    for (int i = 0; i < RPT; i++) acc[i] = 0.f;
#pragma unroll
    for (int c = 0; c < cED; c++) av[c] = 0.f;

    int beg = g_off[n];
    int end = g_off[n + 1];
    for (int idx = beg; idx < end; idx++) {
        int e = g_csr[idx];
        int sn = g_src[e];
        const float* kr = g_k + (size_t)sn * cD;
        const float* vr = g_v + (size_t)sn * cD;
        float eav[cED];
#pragma unroll
        for (int c = 0; c < cED; c++) eav[c] = ea[(size_t)e * cED + c];
        float dp = 0.f;
#pragma unroll
        for (int i = 0; i < RPT; i++) dp += qr[i] * kr[lane + 32 * i];
#pragma unroll
        for (int o = 16; o > 0; o >>= 1) dp += __shfl_xor_sync(FULLMASK, dp, o);
        float sc = dp;
#pragma unroll
        for (int c = 0; c < cED; c++) sc += qe[c] * eav[c];
        sc *= SCALE;

        float mn  = fmaxf(m, sc);
        float f   = __expf(m - mn);
        float wgt = __expf(sc - mn);
        s = s * f + wgt;
#pragma unroll
        for (int i = 0; i < RPT; i++) acc[i] = acc[i] * f + wgt * vr[lane + 32 * i];
#pragma unroll
        for (int c = 0; c < cED; c++) av[c] = av[c] * f + wgt * eav[c];
        m = mn;
    }

    float inv = 1.f / (s + 1e-16f);
#pragma unroll
    for (int i = 0; i < RPT; i++) {
        int d = lane + 32 * i;
        float ep = 0.f;
#pragma unroll
        for (int c = 0; c < cED; c++) ep += av[c] * We[c * cD + d];
        float o = g_hn[(size_t)n * cD + d] + (acc[i] + ep) * inv;
        if (do_relu) o = fmaxf(o, 0.f);
        size_t gi = (size_t)n * cD + d;
        g_h[gi] = o;
        __nv_bfloat16 h = __float2bfloat16(o);
        g_ahi[gi] = h;
        g_alo[gi] = __float2bfloat16(o - __bfloat162float(h));
    }
}

// ---------------- pooling ----------------
__global__ void k_pool_zero() {
    int i = blockIdx.x * blockDim.x + threadIdx.x;
    if (i < cB * cD) g_pool[i] = 0.f;
}

__global__ void k_pool() {
    int w = (blockIdx.x * blockDim.x + threadIdx.x) >> 5;
    int lane = threadIdx.x & 31;
    if (w >= cN) return;
    int b = g_bat[w];
#pragma unroll
    for (int i = 0; i < RPT; i++) {
        atomicAdd(&g_pool[b * cD + lane + 32 * i], g_h[(size_t)w * cD + lane + 32 * i]);
    }
}

// ---------------- LN + Linear + ReLU head ----------------
__global__ void __launch_bounds__(640) k_head(const float* __restrict__ ln_g,
                                              const float* __restrict__ ln_b,
                                              const float* __restrict__ Wemb,
                                              const float* __restrict__ bemb,
                                              int gi) {
    int b = blockIdx.x;
    int t = threadIdx.x;
    __shared__ float red[20];
    __shared__ float zsh[cD];
    __shared__ float s_mu;
    __shared__ float s_rs;
    float x = g_pool[b * cD + t];

    float v = x;
#pragma unroll
    for (int o = 16; o > 0; o >>= 1) v += __shfl_xor_sync(FULLMASK, v, o);
    if ((t & 31) == 0) red[t >> 5] = v;
    __syncthreads();
    if (t == 0) {
        float s = 0.f;
        for (int i = 0; i < 20; i++) s += red[i];
        s_mu = s / cD;
    }
    __syncthreads();
    float dev = x - s_mu;
    v = dev * dev;
#pragma unroll
    for (int o = 16; o > 0; o >>= 1) v += __shfl_xor_sync(FULLMASK, v, o);
    if ((t & 31) == 0) red[t >> 5] = v;
    __syncthreads();
    if (t == 0) {
        float s = 0.f;
        for (int i = 0; i < 20; i++) s += red[i];
        s_rs = rsqrtf(s / cD + 1e-5f);
    }
    __syncthreads();
    zsh[t] = dev * s_rs * ln_g[t] + ln_b[t];
    __syncthreads();

    float o = bemb[t];
#pragma unroll 4
    for (int kk = 0; kk < cD; kk++) o += zsh[kk] * Wemb[(size_t)kk * cD + t];
    g_z[gi][b * cD + t] = fmaxf(o, 0.f);
}

// ---------------- cosine ----------------
__global__ void k_cos(float* __restrict__ out) {
    int b = blockIdx.x;
    int t = threadIdx.x;
    float dp = 0.f;
    float ai = 0.f;
    float aj = 0.f;
    for (int d = t; d < cD; d += 256) {
        float zi = g_z[0][b * cD + d];
        float zj = g_z[1][b * cD + d];
        dp += zi * zj;
        ai += zi * zi;
        aj += zj * zj;
    }
#pragma unroll
    for (int o = 16; o > 0; o >>= 1) {
        dp += __shfl_xor_sync(FULLMASK, dp, o);
        ai += __shfl_xor_sync(FULLMASK, ai, o);
        aj += __shfl_xor_sync(FULLMASK, aj, o);
    }
    __shared__ float r1[8];
    __shared__ float r2[8];
    __shared__ float r3[8];
    int wd = t >> 5;
    if ((t & 31) == 0) { r1[wd] = dp; r2[wd] = ai; r3[wd] = aj; }
    __syncthreads();
    if (t == 0) {
        float sD = 0.f;
        float sA = 0.f;
        float sB = 0.f;
        for (int i = 0; i < 8; i++) { sD += r1[i]; sA += r2[i]; sB += r3[i]; }
        out[b] = sD / (fmaxf(sqrtf(sA), 1e-8f) * fmaxf(sqrtf(sB), 1e-8f));
    }
}

// ---------------- driver ----------------
extern "C" void kernel_launch(void* const* d_in, const int* in_sizes, int n_in,
                              void* d_out, int out_size) {
    const float* x_i   = (const float*)d_in[0];
    const int*   ei_i  = (const int*)d_in[1];
    const float* ea_i  = (const float*)d_in[2];
    const int*   bat_i = (const int*)d_in[3];
    const float* x_j   = (const float*)d_in[4];
    const int*   ei_j  = (const int*)d_in[5];
    const float* ea_j  = (const float*)d_in[6];
    const int*   bat_j = (const int*)d_in[7];
    const float* W0q = (const float*)d_in[8];
    const float* b0q = (const float*)d_in[9];
    const float* W0k = (const float*)d_in[10];
    const float* b0k = (const float*)d_in[11];
    const float* W0v = (const float*)d_in[12];
    const float* b0v = (const float*)d_in[13];
    const float* W0e = (const float*)d_in[14];
    const float* W0s = (const float*)d_in[15];
    const float* b0s = (const float*)d_in[16];
    const float* Wq  = (const float*)d_in[17];
    const float* bq  = (const float*)d_in[18];
    const float* Wk  = (const float*)d_in[19];
    const float* bk  = (const float*)d_in[20];
    const float* Wv  = (const float*)d_in[21];
    const float* bv  = (const float*)d_in[22];
    const float* We  = (const float*)d_in[23];
    const float* Ws  = (const float*)d_in[24];
    const float* bs  = (const float*)d_in[25];
    const float* ln_g = (const float*)d_in[26];
    const float* ln_b = (const float*)d_in[27];
    const float* Wemb = (const float*)d_in[28];
    const float* bemb = (const float*)d_in[29];
    float* out = (float*)d_out;

    const int TB = 256;

    static int attr_done = 0;
    if (!attr_done) {
        cudaFuncSetAttribute(k_gemm_m, cudaFuncAttributeMaxDynamicSharedMemorySize, GSMEM);
        attr_done = 1;
    }

    // weight split+transpose once (also zeroes dtype flags)
    dim3 wgrid(cD / 32, cD / 32, cL1 * 4);
    dim3 wblock(32, 8, 1);
    k_wconv<<<wgrid, wblock>>>(Wq, Wk, Wv, Ws);

    dim3 gemm_grid((cN + 127) / 128, cD / 128, 4);

    const float* xs[2];
    xs[0] = x_i;  xs[1] = x_j;
    const int* eis[2];
    eis[0] = ei_i;  eis[1] = ei_j;
    const float* eas[2];
    eas[0] = ea_i;  eas[1] = ea_j;
    const int* bats[2];
    bats[0] = bat_i;  bats[1] = bat_j;

    for (int gi = 0; gi < 2; gi++) {
        const float* x  = xs[gi];
        const int* ei   = eis[gi];
        const float* ea = eas[gi];
        const int* bat  = bats[gi];
        int slotbase = gi * 2;

        k_detect2<<<(cE + cN / 2 + TB - 1) / TB, TB>>>(ei, bat, slotbase);
        k_prep<<<(2 * cE + TB - 1) / TB, TB>>>(ei, bat, slotbase);
        k_hist<<<(cE + TB - 1) / TB, TB>>>();
        k_scan<<<1, 1024>>>();
        k_scatter<<<(cE + TB - 1) / TB, TB>>>();

        k_layer0<<<(cN * cD + TB - 1) / TB, TB>>>(x, W0q, b0q, W0k, b0k, W0v, b0v, W0s, b0s);
        k_edge<<<(cN + 7) / 8, TB>>>(ea, W0e, 1);

        for (int l = 0; l < cL1; l++) {
            k_gemm_m<<<gemm_grid, 256, GSMEM>>>(l,
                bq + (size_t)l * cD, bk + (size_t)l * cD,
                bv + (size_t)l * cD, bs + (size_t)l * cD);
            int dorelu = (l < 4) ? 1 : 0;
            k_edge<<<(cN + 7) / 8, TB>>>(ea, We + (size_t)l * cED * cD, dorelu);
        }

        k_pool_zero<<<(cB * cD + TB - 1) / TB, TB>>>();
        k_pool<<<(cN + 7) / 8, TB>>>();
        k_head<<<cB, cD>>>(ln_g, ln_b, Wemb, bemb, gi);
    }

    k_cos<<<cB, 256>>>(out);
}

// round 12
// speedup vs baseline: 1.7980x; 1.2653x over previous
#include <cuda_runtime.h>
#include <cuda_bf16.h>
#include <cstdint>
#include <cstddef>
#include <math.h>

typedef unsigned int u32;
typedef unsigned long long u64;

// Problem constants
constexpr int cN  = 10000;
constexpr int cE  = 160000;
constexpr int cB  = 64;
constexpr int cD  = 640;
constexpr int cND = 4;
constexpr int cED = 8;
constexpr int cL1 = 5;
constexpr int RPT = cD / 32;
constexpr int V4  = cD / 128;   // 5 float4 spans per row per lane

#define FULLMASK 0xffffffffu
#define SCALE 0.0395284707521047416f  // 1/sqrt(640)

// ---------------- scratch ----------------
__device__ __align__(16) float g_h [cN * cD];
__device__ __align__(16) float g_q [cN * cD];
__device__ __align__(16) float g_k [cN * cD];
__device__ __align__(16) float g_v [cN * cD];
__device__ __align__(16) float g_hn[cN * cD];
__device__ __align__(16) __nv_bfloat16 g_ahi[cN * cD];
__device__ __align__(16) __nv_bfloat16 g_alo[cN * cD];
// weight splits, transposed: [layer][mat(q,k,v,s)][hi/lo][n=640][k=640]
__device__ __align__(16) __nv_bfloat16 g_wsp[cL1 * 4 * 2 * cD * cD];
__device__ int g_src[cE];
__device__ int g_dst[cE];
__device__ int g_bat[cN];
__device__ int g_flag[4];
__device__ int g_deg[cN];
__device__ int g_cur[cN];
__device__ int g_off[cN + 1];
__device__ int g_csr[cE];
__device__ __align__(16) float g_pool[cB * cD];
__device__ __align__(16) float g_z[2][cB * cD];

__device__ __forceinline__ float* buf_sel(int s) {
    switch (s) {
        case 0:  return g_h;
        case 1:  return g_q;
        case 2:  return g_k;
        case 3:  return g_v;
        default: return g_hn;
    }
}

__device__ __forceinline__ u32 smem_u32(const void* p) {
    return (u32)__cvta_generic_to_shared(p);
}

__device__ __forceinline__ void ldsm4(u32& r0, u32& r1, u32& r2, u32& r3, u32 addr) {
    asm volatile("ldmatrix.sync.aligned.m8n8.x4.shared.b16 {%0,%1,%2,%3}, [%4];"
                 : "=r"(r0), "=r"(r1), "=r"(r2), "=r"(r3)
                 : "r"(addr));
}

__device__ __forceinline__ void mma16816(float* c, const u32* a, u32 b0, u32 b1) {
    asm volatile("mma.sync.aligned.m16n8k16.row.col.f32.bf16.bf16.f32 "
                 "{%0,%1,%2,%3}, {%4,%5,%6,%7}, {%8,%9}, {%0,%1,%2,%3};"
                 : "+f"(c[0]), "+f"(c[1]), "+f"(c[2]), "+f"(c[3])
                 : "r"(a[0]), "r"(a[1]), "r"(a[2]), "r"(a[3]), "r"(b0), "r"(b1));
}

template <int N>
__device__ __forceinline__ void cp_wait() {
    asm volatile("cp.async.wait_group %0;" :: "n"(N) : "memory");
}

__device__ __forceinline__ void cp_commit() {
    asm volatile("cp.async.commit_group;" ::: "memory");
}

// ---------------- GEMM config ----------------
constexpr int ST = 3;                 // pipeline stages
constexpr int CK = 32;                // k elems per chunk
constexpr int NC = cD / CK;           // 20
constexpr int ROWB  = 80;             // 64B data + 16B pad
constexpr int PARTB = 128 * ROWB;     // 10240 B
constexpr int STAGEB = 4 * PARTB;     // Ah, Al, Bh, Bl
constexpr int GSMEM = ST * STAGEB;    // 122880 B

// 512 threads: each thread issues exactly one 16B cp.async per part
__device__ __forceinline__ void ld_part(u32 sdst, const __nv_bfloat16* g,
                                        int row0, int rmax, int col0, int tid) {
    int row = tid >> 2;
    int s4  = tid & 3;
    u32 dst = sdst + (u32)(row * ROWB + s4 * 16);
    const void* src = (const void*)(g + (size_t)(row0 + row) * cD + col0 + s4 * 8);
    int ok = (row0 + row < rmax) ? 16 : 0;
    asm volatile("cp.async.cg.shared.global [%0], [%1], 16, %2;"
                 :: "r"(dst), "l"(src), "r"(ok) : "memory");
}

// C = A @ W + bias; 3-term bf16 split, fp32 accum.
// block 128x128, 16 warps (4M x 4N), warp tile 32x32. grid (79, 5, mat)
__global__ void __launch_bounds__(512, 1) k_gemm_m(int layer,
                                                   const float* __restrict__ bq,
                                                   const float* __restrict__ bk,
                                                   const float* __restrict__ bv,
                                                   const float* __restrict__ bs) {
    extern __shared__ char smem[];
    u32 sb = smem_u32(smem);
    int tid = threadIdx.x;
    int lane = tid & 31;
    int warp = tid >> 5;
    int wm = warp & 3;       // 4 M groups of 32 rows
    int wn = warp >> 2;      // 4 N groups of 32 cols
    int z = blockIdx.z;

    const __nv_bfloat16* Whi = g_wsp + ((size_t)(layer * 4 + z) * 2 + 0) * cD * cD;
    const __nv_bfloat16* Wlo = Whi + (size_t)cD * cD;
    const float* bias;
    if (z == 0)      bias = bq;
    else if (z == 1) bias = bk;
    else if (z == 2) bias = bv;
    else             bias = bs;
    float* outp = buf_sel(z + 1);

    int bm = blockIdx.x * 128;
    int bn = blockIdx.y * 128;

    float acc[2][4][4];
#pragma unroll
    for (int mi = 0; mi < 2; mi++) {
#pragma unroll
        for (int nj = 0; nj < 4; nj++) {
#pragma unroll
            for (int c = 0; c < 4; c++) acc[mi][nj][c] = 0.f;
        }
    }

    // prologue: stages 0, 1
#pragma unroll
    for (int c = 0; c < 2; c++) {
        u32 st = sb + (u32)(c * STAGEB);
        int col0 = c * CK;
        ld_part(st,             g_ahi, bm, cN, col0, tid);
        ld_part(st + PARTB,     g_alo, bm, cN, col0, tid);
        ld_part(st + 2 * PARTB, Whi,   bn, cD, col0, tid);
        ld_part(st + 3 * PARTB, Wlo,   bn, cD, col0, tid);
        cp_commit();
    }

    int lrow = lane & 15;
    int lcol = (lane >> 4) * 8;

    for (int c = 0; c < NC; c++) {
        if (c < NC - 1) cp_wait<1>();
        else            cp_wait<0>();
        __syncthreads();

        if (c + 2 < NC) {
            u32 st2 = sb + (u32)(((c + 2) % ST) * STAGEB);
            int col0 = (c + 2) * CK;
            ld_part(st2,             g_ahi, bm, cN, col0, tid);
            ld_part(st2 + PARTB,     g_alo, bm, cN, col0, tid);
            ld_part(st2 + 2 * PARTB, Whi,   bn, cD, col0, tid);
            ld_part(st2 + 3 * PARTB, Wlo,   bn, cD, col0, tid);
            cp_commit();
        }

        u32 st = sb + (u32)((c % ST) * STAGEB);
#pragma unroll
        for (int ks = 0; ks < CK; ks += 16) {
            u32 ah[2][4];
            u32 al[2][4];
            u32 bh[2][4];
            u32 bl[2][4];
            u32 kb = (u32)((ks + lcol) * 2);
#pragma unroll
            for (int mi = 0; mi < 2; mi++) {
                u32 ra = st + (u32)((wm * 32 + mi * 16 + lrow) * ROWB) + kb;
                ldsm4(ah[mi][0], ah[mi][1], ah[mi][2], ah[mi][3], ra);
                ldsm4(al[mi][0], al[mi][1], al[mi][2], al[mi][3], ra + (u32)PARTB);
            }
#pragma unroll
            for (int gg = 0; gg < 2; gg++) {
                u32 rb = st + (u32)(2 * PARTB) + (u32)((wn * 32 + gg * 16 + lrow) * ROWB) + kb;
                ldsm4(bh[gg][0], bh[gg][1], bh[gg][2], bh[gg][3], rb);
                ldsm4(bl[gg][0], bl[gg][1], bl[gg][2], bl[gg][3], rb + (u32)PARTB);
            }
#pragma unroll
            for (int mi = 0; mi < 2; mi++) {
#pragma unroll
                for (int nj = 0; nj < 4; nj++) {
                    int gg = nj >> 1;
                    int xx = nj & 1;
                    mma16816(acc[mi][nj], ah[mi], bh[gg][xx], bh[gg][xx + 2]);
                    mma16816(acc[mi][nj], ah[mi], bl[gg][xx], bl[gg][xx + 2]);
                    mma16816(acc[mi][nj], al[mi], bh[gg][xx], bh[gg][xx + 2]);
                }
            }
        }
    }

    // epilogue
    int gid = lane >> 2;
    int tig = lane & 3;
#pragma unroll
    for (int mi = 0; mi < 2; mi++) {
#pragma unroll
        for (int nj = 0; nj < 4; nj++) {
            int colg = bn + wn * 32 + nj * 8 + tig * 2;
            float bias0 = bias[colg];
            float bias1 = bias[colg + 1];
            int r0 = bm + wm * 32 + mi * 16 + gid;
            if (r0 < cN) {
                float2 o0;
                o0.x = acc[mi][nj][0] + bias0;
                o0.y = acc[mi][nj][1] + bias1;
                *(float2*)(outp + (size_t)r0 * cD + colg) = o0;
            }
            int r1 = r0 + 8;
            if (r1 < cN) {
                float2 o1;
                o1.x = acc[mi][nj][2] + bias0;
                o1.y = acc[mi][nj][3] + bias1;
                *(float2*)(outp + (size_t)r1 * cD + colg) = o1;
            }
        }
    }
}

// ---------------- dtype detect ----------------
__global__ void k_detect2(const int* __restrict__ ei, const int* __restrict__ bat,
                          int slotbase) {
    int i = blockIdx.x * blockDim.x + threadIdx.x;
    if (i < cE) {
        if (ei[2 * i + 1] != 0) atomicOr(&g_flag[slotbase], 1);
    } else {
        int j = i - cE;
        if (j < cN / 2) {
            if (bat[2 * j + 1] != 0) atomicOr(&g_flag[slotbase + 1], 1);
        }
    }
}

// ---------------- normalize indices + zero counters ----------------
__global__ void k_prep(const int* __restrict__ ei, const int* __restrict__ bat,
                       int slotbase) {
    int i = blockIdx.x * blockDim.x + threadIdx.x;
    if (i < 2 * cE) {
        int is32 = g_flag[slotbase];
        int v;
        if (is32) v = ei[i];
        else      v = (int)((const long long*)ei)[i];
        if (i < cE) g_src[i] = v;
        else        g_dst[i - cE] = v;
    }
    if (i < cN) {
        int is32b = g_flag[slotbase + 1];
        g_bat[i] = is32b ? bat[i] : (int)((const long long*)bat)[i];
        g_deg[i] = 0;
        g_cur[i] = 0;
    }
}

// ---------------- CSR build ----------------
__global__ void k_hist() {
    int e = blockIdx.x * blockDim.x + threadIdx.x;
    if (e < cE) atomicAdd(&g_deg[g_dst[e]], 1);
}

__global__ void __launch_bounds__(1024) k_scan() {
    const int T = 1024;
    const int CH = (cN + T - 1) / T;
    int t = threadIdx.x;
    int vals[CH];
    int local = 0;
    int base = t * CH;
#pragma unroll
    for (int j = 0; j < CH; j++) {
        int idx = base + j;
        int v = (idx < cN) ? g_deg[idx] : 0;
        vals[j] = local;
        local += v;
    }
    __shared__ int sh[T];
    sh[t] = local;
    __syncthreads();
    for (int off = 1; off < T; off <<= 1) {
        int v = (t >= off) ? sh[t - off] : 0;
        __syncthreads();
        sh[t] += v;
        __syncthreads();
    }
    int prefix = sh[t] - local;
#pragma unroll
    for (int j = 0; j < CH; j++) {
        int idx = base + j;
        if (idx < cN) g_off[idx] = prefix + vals[j];
    }
    if (t == T - 1) g_off[cN] = sh[T - 1];
}

__global__ void k_scatter() {
    int e = blockIdx.x * blockDim.x + threadIdx.x;
    if (e < cE) {
        int d = g_dst[e];
        int p = atomicAdd(&g_cur[d], 1);
        g_csr[g_off[d] + p] = e;
    }
}

// ---------------- weight split + transpose (+ flag zero) ----------------
__global__ void k_wconv(const float* __restrict__ Wq, const float* __restrict__ Wk,
                        const float* __restrict__ Wv, const float* __restrict__ Ws) {
    if (blockIdx.x == 0 && blockIdx.y == 0 && blockIdx.z == 0 &&
        threadIdx.y == 0 && threadIdx.x < 4) {
        g_flag[threadIdx.x] = 0;
    }
    int z = blockIdx.z;
    int l = z >> 2;
    int m = z & 3;
    const float* Wsel;
    if (m == 0)      Wsel = Wq;
    else if (m == 1) Wsel = Wk;
    else if (m == 2) Wsel = Wv;
    else             Wsel = Ws;
    const float* W = Wsel + (size_t)l * cD * cD;

    __shared__ float tile[32][33];
    int k0 = blockIdx.x * 32;
    int n0 = blockIdx.y * 32;
    for (int i = threadIdx.y; i < 32; i += 8) {
        tile[i][threadIdx.x] = W[(size_t)(k0 + i) * cD + n0 + threadIdx.x];
    }
    __syncthreads();
    __nv_bfloat16* hi = g_wsp + ((size_t)z * 2 + 0) * cD * cD;
    __nv_bfloat16* lo = g_wsp + ((size_t)z * 2 + 1) * cD * cD;
    for (int i = threadIdx.y; i < 32; i += 8) {
        float wv = tile[threadIdx.x][i];
        __nv_bfloat16 h = __float2bfloat16(wv);
        float r = wv - __bfloat162float(h);
        hi[(size_t)(n0 + i) * cD + k0 + threadIdx.x] = h;
        lo[(size_t)(n0 + i) * cD + k0 + threadIdx.x] = __float2bfloat16(r);
    }
}

// ---------------- layer 0 projections ----------------
__global__ void k_layer0(const float* __restrict__ x,
                         const float* __restrict__ Wq, const float* __restrict__ bq,
                         const float* __restrict__ Wk, const float* __restrict__ bk,
                         const float* __restrict__ Wv, const float* __restrict__ bv,
                         const float* __restrict__ Ws, const float* __restrict__ bs) {
    int idx = blockIdx.x * blockDim.x + threadIdx.x;
    if (idx >= cN * cD) return;
    int n = idx / cD;
    int d = idx - n * cD;
    float x0 = x[n * cND + 0];
    float x1 = x[n * cND + 1];
    float x2 = x[n * cND + 2];
    float x3 = x[n * cND + 3];
    float aq = bq[d] + x0 * Wq[0 * cD + d] + x1 * Wq[1 * cD + d] + x2 * Wq[2 * cD + d] + x3 * Wq[3 * cD + d];
    float ak = bk[d] + x0 * Wk[0 * cD + d] + x1 * Wk[1 * cD + d] + x2 * Wk[2 * cD + d] + x3 * Wk[3 * cD + d];
    float av = bv[d] + x0 * Wv[0 * cD + d] + x1 * Wv[1 * cD + d] + x2 * Wv[2 * cD + d] + x3 * Wv[3 * cD + d];
    float as = bs[d] + x0 * Ws[0 * cD + d] + x1 * Ws[1 * cD + d] + x2 * Ws[2 * cD + d] + x3 * Ws[3 * cD + d];
    g_q[idx] = aq;
    g_k[idx] = ak;
    g_v[idx] = av;
    g_hn[idx] = as;
}

// ---------------- fused edge aggregation (float4, + bf16 split of output) ----
// lane covers dims d = (lane + 32*i)*4 + {0..3}, i in 0..4
__global__ void __launch_bounds__(256) k_edge(const float* __restrict__ ea,
                                              const float* __restrict__ We,
                                              int do_relu) {
    int w = (blockIdx.x * blockDim.x + threadIdx.x) >> 5;
    int lane = threadIdx.x & 31;
    if (w >= cN) return;
    const int n = w;
    const int fi = lane;   // float4 index base: lane + 32*i

    float4 qr[V4];
#pragma unroll
    for (int i = 0; i < V4; i++)
        qr[i] = ((const float4*)(g_q + (size_t)n * cD))[fi + 32 * i];

    float qe[cED];
#pragma unroll
    for (int c = 0; c < cED; c++) {
        const float4* wr = (const float4*)(We + (size_t)c * cD);
        float p = 0.f;
#pragma unroll
        for (int i = 0; i < V4; i++) {
            float4 wv = wr[fi + 32 * i];
            p += qr[i].x * wv.x + qr[i].y * wv.y + qr[i].z * wv.z + qr[i].w * wv.w;
        }
#pragma unroll
        for (int o = 16; o > 0; o >>= 1) p += __shfl_xor_sync(FULLMASK, p, o);
        qe[c] = p;
    }

    float m = -1e30f;
    float s = 0.f;
    float4 acc[V4];
    float av[cED];
#pragma unroll
    for (int i = 0; i < V4; i++) acc[i] = make_float4(0.f, 0.f, 0.f, 0.f);
#pragma unroll
    for (int c = 0; c < cED; c++) av[c] = 0.f;

    int beg = g_off[n];
    int end = g_off[n + 1];
    for (int idx = beg; idx < end; idx++) {
        int e = g_csr[idx];
        int sn = g_src[e];
        const float4* kr = (const float4*)(g_k + (size_t)sn * cD);
        const float4* vr = (const float4*)(g_v + (size_t)sn * cD);
        float4 ev0 = ((const float4*)(ea + (size_t)e * cED))[0];
        float4 ev1 = ((const float4*)(ea + (size_t)e * cED))[1];
        float eav[cED];
        eav[0] = ev0.x; eav[1] = ev0.y; eav[2] = ev0.z; eav[3] = ev0.w;
        eav[4] = ev1.x; eav[5] = ev1.y; eav[6] = ev1.z; eav[7] = ev1.w;

        float dp = 0.f;
        float4 kv[V4];
#pragma unroll
        for (int i = 0; i < V4; i++) kv[i] = kr[fi + 32 * i];
#pragma unroll
        for (int i = 0; i < V4; i++)
            dp += qr[i].x * kv[i].x + qr[i].y * kv[i].y + qr[i].z * kv[i].z + qr[i].w * kv[i].w;
#pragma unroll
        for (int o = 16; o > 0; o >>= 1) dp += __shfl_xor_sync(FULLMASK, dp, o);
        float sc = dp;
#pragma unroll
        for (int c = 0; c < cED; c++) sc += qe[c] * eav[c];
        sc *= SCALE;

        float mn  = fmaxf(m, sc);
        float f   = __expf(m - mn);
        float wgt = __expf(sc - mn);
        s = s * f + wgt;
#pragma unroll
        for (int i = 0; i < V4; i++) {
            float4 vv = vr[fi + 32 * i];
            acc[i].x = acc[i].x * f + wgt * vv.x;
            acc[i].y = acc[i].y * f + wgt * vv.y;
            acc[i].z = acc[i].z * f + wgt * vv.z;
            acc[i].w = acc[i].w * f + wgt * vv.w;
        }
#pragma unroll
        for (int c = 0; c < cED; c++) av[c] = av[c] * f + wgt * eav[c];
        m = mn;
    }

    float inv = 1.f / (s + 1e-16f);
#pragma unroll
    for (int i = 0; i < V4; i++) {
        float4 ep = make_float4(0.f, 0.f, 0.f, 0.f);
#pragma unroll
        for (int c = 0; c < cED; c++) {
            float4 wv = ((const float4*)(We + (size_t)c * cD))[fi + 32 * i];
            ep.x += av[c] * wv.x;
            ep.y += av[c] * wv.y;
            ep.z += av[c] * wv.z;
            ep.w += av[c] * wv.w;
        }
        float4 hb = ((const float4*)(g_hn + (size_t)n * cD))[fi + 32 * i];
        float4 o;
        o.x = hb.x + (acc[i].x + ep.x) * inv;
        o.y = hb.y + (acc[i].y + ep.y) * inv;
        o.z = hb.z + (acc[i].z + ep.z) * inv;
        o.w = hb.w + (acc[i].w + ep.w) * inv;
        if (do_relu) {
            o.x = fmaxf(o.x, 0.f);
            o.y = fmaxf(o.y, 0.f);
            o.z = fmaxf(o.z, 0.f);
            o.w = fmaxf(o.w, 0.f);
        }
        ((float4*)(g_h + (size_t)n * cD))[fi + 32 * i] = o;

        // bf16 split (hi + residual), 8B vector stores
        __nv_bfloat16 h0 = __float2bfloat16(o.x);
        __nv_bfloat16 h1 = __float2bfloat16(o.y);
        __nv_bfloat16 h2 = __float2bfloat16(o.z);
        __nv_bfloat16 h3 = __float2bfloat16(o.w);
        __nv_bfloat16 l0 = __float2bfloat16(o.x - __bfloat162float(h0));
        __nv_bfloat16 l1 = __float2bfloat16(o.y - __bfloat162float(h1));
        __nv_bfloat16 l2 = __float2bfloat16(o.z - __bfloat162float(h2));
        __nv_bfloat16 l3 = __float2bfloat16(o.w - __bfloat162float(h3));
        ushort4 hv, lv;
        hv.x = *(unsigned short*)&h0; hv.y = *(unsigned short*)&h1;
        hv.z = *(unsigned short*)&h2; hv.w = *(unsigned short*)&h3;
        lv.x = *(unsigned short*)&l0; lv.y = *(unsigned short*)&l1;
        lv.z = *(unsigned short*)&l2; lv.w = *(unsigned short*)&l3;
        ((ushort4*)(g_ahi + (size_t)n * cD))[fi + 32 * i] = hv;
        ((ushort4*)(g_alo + (size_t)n * cD))[fi + 32 * i] = lv;
    }
}

// ---------------- pooling ----------------
__global__ void k_pool_zero() {
    int i = blockIdx.x * blockDim.x + threadIdx.x;
    if (i < cB * cD) g_pool[i] = 0.f;
}

__global__ void k_pool() {
    int w = (blockIdx.x * blockDim.x + threadIdx.x) >> 5;
    int lane = threadIdx.x & 31;
    if (w >= cN) return;
    int b = g_bat[w];
#pragma unroll
    for (int i = 0; i < RPT; i++) {
        atomicAdd(&g_pool[b * cD + lane + 32 * i], g_h[(size_t)w * cD + lane + 32 * i]);
    }
}

// ---------------- LN + Linear + ReLU head ----------------
__global__ void __launch_bounds__(640) k_head(const float* __restrict__ ln_g,
                                              const float* __restrict__ ln_b,
                                              const float* __restrict__ Wemb,
                                              const float* __restrict__ bemb,
                                              int gi) {
    int b = blockIdx.x;
    int t = threadIdx.x;
    __shared__ float red[20];
    __shared__ float zsh[cD];
    __shared__ float s_mu;
    __shared__ float s_rs;
    float x = g_pool[b * cD + t];

    float v = x;
#pragma unroll
    for (int o = 16; o > 0; o >>= 1) v += __shfl_xor_sync(FULLMASK, v, o);
    if ((t & 31) == 0) red[t >> 5] = v;
    __syncthreads();
    if (t == 0) {
        float s = 0.f;
        for (int i = 0; i < 20; i++) s += red[i];
        s_mu = s / cD;
    }
    __syncthreads();
    float dev = x - s_mu;
    v = dev * dev;
#pragma unroll
    for (int o = 16; o > 0; o >>= 1) v += __shfl_xor_sync(FULLMASK, v, o);
    if ((t & 31) == 0) red[t >> 5] = v;
    __syncthreads();
    if (t == 0) {
        float s = 0.f;
        for (int i = 0; i < 20; i++) s += red[i];
        s_rs = rsqrtf(s / cD + 1e-5f);
    }
    __syncthreads();
    zsh[t] = dev * s_rs * ln_g[t] + ln_b[t];
    __syncthreads();

    float o = bemb[t];
#pragma unroll 4
    for (int kk = 0; kk < cD; kk++) o += zsh[kk] * Wemb[(size_t)kk * cD + t];
    g_z[gi][b * cD + t] = fmaxf(o, 0.f);
}

// ---------------- cosine ----------------
__global__ void k_cos(float* __restrict__ out) {
    int b = blockIdx.x;
    int t = threadIdx.x;
    float dp = 0.f;
    float ai = 0.f;
    float aj = 0.f;
    for (int d = t; d < cD; d += 256) {
        float zi = g_z[0][b * cD + d];
        float zj = g_z[1][b * cD + d];
        dp += zi * zj;
        ai += zi * zi;
        aj += zj * zj;
    }
#pragma unroll
    for (int o = 16; o > 0; o >>= 1) {
        dp += __shfl_xor_sync(FULLMASK, dp, o);
        ai += __shfl_xor_sync(FULLMASK, ai, o);
        aj += __shfl_xor_sync(FULLMASK, aj, o);
    }
    __shared__ float r1[8];
    __shared__ float r2[8];
    __shared__ float r3[8];
    int wd = t >> 5;
    if ((t & 31) == 0) { r1[wd] = dp; r2[wd] = ai; r3[wd] = aj; }
    __syncthreads();
    if (t == 0) {
        float sD = 0.f;
        float sA = 0.f;
        float sB = 0.f;
        for (int i = 0; i < 8; i++) { sD += r1[i]; sA += r2[i]; sB += r3[i]; }
        out[b] = sD / (fmaxf(sqrtf(sA), 1e-8f) * fmaxf(sqrtf(sB), 1e-8f));
    }
}

// ---------------- driver ----------------
extern "C" void kernel_launch(void* const* d_in, const int* in_sizes, int n_in,
                              void* d_out, int out_size) {
    const float* x_i   = (const float*)d_in[0];
    const int*   ei_i  = (const int*)d_in[1];
    const float* ea_i  = (const float*)d_in[2];
    const int*   bat_i = (const int*)d_in[3];
    const float* x_j   = (const float*)d_in[4];
    const int*   ei_j  = (const int*)d_in[5];
    const float* ea_j  = (const float*)d_in[6];
    const int*   bat_j = (const int*)d_in[7];
    const float* W0q = (const float*)d_in[8];
    const float* b0q = (const float*)d_in[9];
    const float* W0k = (const float*)d_in[10];
    const float* b0k = (const float*)d_in[11];
    const float* W0v = (const float*)d_in[12];
    const float* b0v = (const float*)d_in[13];
    const float* W0e = (const float*)d_in[14];
    const float* W0s = (const float*)d_in[15];
    const float* b0s = (const float*)d_in[16];
    const float* Wq  = (const float*)d_in[17];
    const float* bq  = (const float*)d_in[18];
    const float* Wk  = (const float*)d_in[19];
    const float* bk  = (const float*)d_in[20];
    const float* Wv  = (const float*)d_in[21];
    const float* bv  = (const float*)d_in[22];
    const float* We  = (const float*)d_in[23];
    const float* Ws  = (const float*)d_in[24];
    const float* bs  = (const float*)d_in[25];
    const float* ln_g = (const float*)d_in[26];
    const float* ln_b = (const float*)d_in[27];
    const float* Wemb = (const float*)d_in[28];
    const float* bemb = (const float*)d_in[29];
    float* out = (float*)d_out;

    const int TB = 256;

    static int attr_done = 0;
    if (!attr_done) {
        cudaFuncSetAttribute(k_gemm_m, cudaFuncAttributeMaxDynamicSharedMemorySize, GSMEM);
        attr_done = 1;
    }

    // weight split+transpose once (also zeroes dtype flags)
    dim3 wgrid(cD / 32, cD / 32, cL1 * 4);
    dim3 wblock(32, 8, 1);
    k_wconv<<<wgrid, wblock>>>(Wq, Wk, Wv, Ws);

    dim3 gemm_grid((cN + 127) / 128, cD / 128, 4);

    const float* xs[2];
    xs[0] = x_i;  xs[1] = x_j;
    const int* eis[2];
    eis[0] = ei_i;  eis[1] = ei_j;
    const float* eas[2];
    eas[0] = ea_i;  eas[1] = ea_j;
    const int* bats[2];
    bats[0] = bat_i;  bats[1] = bat_j;

    for (int gi = 0; gi < 2; gi++) {
        const float* x  = xs[gi];
        const int* ei   = eis[gi];
        const float* ea = eas[gi];
        const int* bat  = bats[gi];
        int slotbase = gi * 2;

        k_detect2<<<(cE + cN / 2 + TB - 1) / TB, TB>>>(ei, bat, slotbase);
        k_prep<<<(2 * cE + TB - 1) / TB, TB>>>(ei, bat, slotbase);
        k_hist<<<(cE + TB - 1) / TB, TB>>>();
        k_scan<<<1, 1024>>>();
        k_scatter<<<(cE + TB - 1) / TB, TB>>>();

        k_layer0<<<(cN * cD + TB - 1) / TB, TB>>>(x, W0q, b0q, W0k, b0k, W0v, b0v, W0s, b0s);
        k_edge<<<(cN + 7) / 8, TB>>>(ea, W0e, 1);

        for (int l = 0; l < cL1; l++) {
            k_gemm_m<<<gemm_grid, 512, GSMEM>>>(l,
                bq + (size_t)l * cD, bk + (size_t)l * cD,
                bv + (size_t)l * cD, bs + (size_t)l * cD);
            int dorelu = (l < 4) ? 1 : 0;
            k_edge<<<(cN + 7) / 8, TB>>>(ea, We + (size_t)l * cED * cD, dorelu);
        }

        k_pool_zero<<<(cB * cD + TB - 1) / TB, TB>>>();
        k_pool<<<(cN + 7) / 8, TB>>>();
        k_head<<<cB, cD>>>(ln_g, ln_b, Wemb, bemb, gi);
    }

    k_cos<<<cB, 256>>>(out);
}

// round 13
// speedup vs baseline: 2.0567x; 1.1438x over previous
#include <cuda_runtime.h>
#include <cuda_bf16.h>
#include <cstdint>
#include <cstddef>
#include <math.h>

typedef unsigned int u32;
typedef unsigned long long u64;

// Problem constants
constexpr int cN  = 10000;
constexpr int cE  = 160000;
constexpr int cB  = 64;
constexpr int cD  = 640;
constexpr int cND = 4;
constexpr int cED = 8;
constexpr int cL1 = 5;
constexpr int RPT = cD / 32;
constexpr int V4  = cD / 128;            // 5 float4 spans per row per lane
constexpr size_t NSZ = (size_t)cN * cD;  // per-graph feature array size

#define FULLMASK 0xffffffffu
#define SCALE 0.0395284707521047416f  // 1/sqrt(640)

// ---------------- scratch (per-graph doubled) ----------------
__device__ __align__(16) float g_h [2 * cN * cD];
__device__ __align__(16) float g_q [2 * cN * cD];
__device__ __align__(16) float g_k [2 * cN * cD];
__device__ __align__(16) float g_v [2 * cN * cD];
__device__ __align__(16) float g_hn[2 * cN * cD];
__device__ __align__(16) __nv_bfloat16 g_ahi[2 * cN * cD];
__device__ __align__(16) __nv_bfloat16 g_alo[2 * cN * cD];
// weight splits, transposed: [layer][mat(q,k,v,s)][hi/lo][n=640][k=640]
__device__ __align__(16) __nv_bfloat16 g_wsp[cL1 * 4 * 2 * cD * cD];
__device__ int g_src[2 * cE];
__device__ int g_dst[2 * cE];
__device__ int g_bat[2 * cN];
__device__ int g_flag[4];
__device__ int g_deg[2 * cN];
__device__ int g_cur[2 * cN];
__device__ int g_off[2 * (cN + 1)];
__device__ int g_csr[2 * cE];
__device__ __align__(16) float g_pool[2 * cB * cD];
__device__ __align__(16) float g_z[2][cB * cD];

__device__ __forceinline__ float* buf_sel(int grp, int s) {
    float* p;
    switch (s) {
        case 0:  p = g_h;  break;
        case 1:  p = g_q;  break;
        case 2:  p = g_k;  break;
        case 3:  p = g_v;  break;
        default: p = g_hn; break;
    }
    return p + (size_t)grp * NSZ;
}

__device__ __forceinline__ u32 smem_u32(const void* p) {
    return (u32)__cvta_generic_to_shared(p);
}

__device__ __forceinline__ void ldsm4(u32& r0, u32& r1, u32& r2, u32& r3, u32 addr) {
    asm volatile("ldmatrix.sync.aligned.m8n8.x4.shared.b16 {%0,%1,%2,%3}, [%4];"
                 : "=r"(r0), "=r"(r1), "=r"(r2), "=r"(r3)
                 : "r"(addr));
}

__device__ __forceinline__ void mma16816(float* c, const u32* a, u32 b0, u32 b1) {
    asm volatile("mma.sync.aligned.m16n8k16.row.col.f32.bf16.bf16.f32 "
                 "{%0,%1,%2,%3}, {%4,%5,%6,%7}, {%8,%9}, {%0,%1,%2,%3};"
                 : "+f"(c[0]), "+f"(c[1]), "+f"(c[2]), "+f"(c[3])
                 : "r"(a[0]), "r"(a[1]), "r"(a[2]), "r"(a[3]), "r"(b0), "r"(b1));
}

template <int N>
__device__ __forceinline__ void cp_wait() {
    asm volatile("cp.async.wait_group %0;" :: "n"(N) : "memory");
}

__device__ __forceinline__ void cp_commit() {
    asm volatile("cp.async.commit_group;" ::: "memory");
}

// ---------------- GEMM config ----------------
constexpr int ST = 3;
constexpr int CK = 32;
constexpr int NC = cD / CK;           // 20
constexpr int ROWB  = 80;
constexpr int PARTB = 128 * ROWB;
constexpr int STAGEB = 4 * PARTB;
constexpr int GSMEM = ST * STAGEB;    // 122880 B

__device__ __forceinline__ void ld_part(u32 sdst, const __nv_bfloat16* g,
                                        int row0, int rmax, int col0, int tid) {
    int row = tid >> 2;
    int s4  = tid & 3;
    u32 dst = sdst + (u32)(row * ROWB + s4 * 16);
    const void* src = (const void*)(g + (size_t)(row0 + row) * cD + col0 + s4 * 8);
    int ok = (row0 + row < rmax) ? 16 : 0;
    asm volatile("cp.async.cg.shared.global [%0], [%1], 16, %2;"
                 :: "r"(dst), "l"(src), "r"(ok) : "memory");
}

// C = A @ W + bias; 3-term bf16 split, fp32 accum. Both graphs via blockIdx.z.
// block 128x128, 16 warps (4M x 4N). grid (79, 5, 8): z = graph*4 + mat
__global__ void __launch_bounds__(512, 1) k_gemm_m(int layer,
                                                   const float* __restrict__ bq,
                                                   const float* __restrict__ bk,
                                                   const float* __restrict__ bv,
                                                   const float* __restrict__ bs) {
    extern __shared__ char smem[];
    u32 sb = smem_u32(smem);
    int tid = threadIdx.x;
    int lane = tid & 31;
    int warp = tid >> 5;
    int wm = warp & 3;
    int wn = warp >> 2;
    int zz = blockIdx.z;
    int grp = zz >> 2;
    int z = zz & 3;

    const __nv_bfloat16* Ahi = g_ahi + (size_t)grp * NSZ;
    const __nv_bfloat16* Alo = g_alo + (size_t)grp * NSZ;
    const __nv_bfloat16* Whi = g_wsp + ((size_t)(layer * 4 + z) * 2 + 0) * cD * cD;
    const __nv_bfloat16* Wlo = Whi + (size_t)cD * cD;
    const float* bias;
    if (z == 0)      bias = bq;
    else if (z == 1) bias = bk;
    else if (z == 2) bias = bv;
    else             bias = bs;
    float* outp = buf_sel(grp, z + 1);

    int bm = blockIdx.x * 128;
    int bn = blockIdx.y * 128;

    float acc[2][4][4];
#pragma unroll
    for (int mi = 0; mi < 2; mi++) {
#pragma unroll
        for (int nj = 0; nj < 4; nj++) {
#pragma unroll
            for (int c = 0; c < 4; c++) acc[mi][nj][c] = 0.f;
        }
    }

#pragma unroll
    for (int c = 0; c < 2; c++) {
        u32 st = sb + (u32)(c * STAGEB);
        int col0 = c * CK;
        ld_part(st,             Ahi, bm, cN, col0, tid);
        ld_part(st + PARTB,     Alo, bm, cN, col0, tid);
        ld_part(st + 2 * PARTB, Whi, bn, cD, col0, tid);
        ld_part(st + 3 * PARTB, Wlo, bn, cD, col0, tid);
        cp_commit();
    }

    int lrow = lane & 15;
    int lcol = (lane >> 4) * 8;

    for (int c = 0; c < NC; c++) {
        if (c < NC - 1) cp_wait<1>();
        else            cp_wait<0>();
        __syncthreads();

        if (c + 2 < NC) {
            u32 st2 = sb + (u32)(((c + 2) % ST) * STAGEB);
            int col0 = (c + 2) * CK;
            ld_part(st2,             Ahi, bm, cN, col0, tid);
            ld_part(st2 + PARTB,     Alo, bm, cN, col0, tid);
            ld_part(st2 + 2 * PARTB, Whi, bn, cD, col0, tid);
            ld_part(st2 + 3 * PARTB, Wlo, bn, cD, col0, tid);
            cp_commit();
        }

        u32 st = sb + (u32)((c % ST) * STAGEB);
#pragma unroll
        for (int ks = 0; ks < CK; ks += 16) {
            u32 ah[2][4];
            u32 al[2][4];
            u32 bh[2][4];
            u32 bl[2][4];
            u32 kb = (u32)((ks + lcol) * 2);
#pragma unroll
            for (int mi = 0; mi < 2; mi++) {
                u32 ra = st + (u32)((wm * 32 + mi * 16 + lrow) * ROWB) + kb;
                ldsm4(ah[mi][0], ah[mi][1], ah[mi][2], ah[mi][3], ra);
                ldsm4(al[mi][0], al[mi][1], al[mi][2], al[mi][3], ra + (u32)PARTB);
            }
#pragma unroll
            for (int gg = 0; gg < 2; gg++) {
                u32 rb = st + (u32)(2 * PARTB) + (u32)((wn * 32 + gg * 16 + lrow) * ROWB) + kb;
                ldsm4(bh[gg][0], bh[gg][1], bh[gg][2], bh[gg][3], rb);
                ldsm4(bl[gg][0], bl[gg][1], bl[gg][2], bl[gg][3], rb + (u32)PARTB);
            }
#pragma unroll
            for (int mi = 0; mi < 2; mi++) {
#pragma unroll
                for (int nj = 0; nj < 4; nj++) {
                    int gg = nj >> 1;
                    int xx = nj & 1;
                    mma16816(acc[mi][nj], ah[mi], bh[gg][xx], bh[gg][xx + 2]);
                    mma16816(acc[mi][nj], ah[mi], bl[gg][xx], bl[gg][xx + 2]);
                    mma16816(acc[mi][nj], al[mi], bh[gg][xx], bh[gg][xx + 2]);
                }
            }
        }
    }

    int gid = lane >> 2;
    int tig = lane & 3;
#pragma unroll
    for (int mi = 0; mi < 2; mi++) {
#pragma unroll
        for (int nj = 0; nj < 4; nj++) {
            int colg = bn + wn * 32 + nj * 8 + tig * 2;
            float bias0 = bias[colg];
            float bias1 = bias[colg + 1];
            int r0 = bm + wm * 32 + mi * 16 + gid;
            if (r0 < cN) {
                float2 o0;
                o0.x = acc[mi][nj][0] + bias0;
                o0.y = acc[mi][nj][1] + bias1;
                *(float2*)(outp + (size_t)r0 * cD + colg) = o0;
            }
            int r1 = r0 + 8;
            if (r1 < cN) {
                float2 o1;
                o1.x = acc[mi][nj][2] + bias0;
                o1.y = acc[mi][nj][3] + bias1;
                *(float2*)(outp + (size_t)r1 * cD + colg) = o1;
            }
        }
    }
}

// ---------------- detect (both graphs) + zero deg/cur/pool ----------------
__global__ void k_detect(const int* __restrict__ ei0, const int* __restrict__ bat0,
                         const int* __restrict__ ei1, const int* __restrict__ bat1) {
    int i = blockIdx.x * blockDim.x + threadIdx.x;
    if (i < 2 * cE) {
        int grp = i / cE;
        int j = i - grp * cE;
        const int* ei = grp ? ei1 : ei0;
        if (ei[2 * j + 1] != 0) atomicOr(&g_flag[grp], 1);
    }
    if (i < cN) {  // cN/2 odd-word checks per graph
        int grp = i / (cN / 2);
        int j = i - grp * (cN / 2);
        const int* bat = grp ? bat1 : bat0;
        if (bat[2 * j + 1] != 0) atomicOr(&g_flag[2 + grp], 1);
    }
    if (i < 2 * cN) { g_deg[i] = 0; g_cur[i] = 0; }
    if (i < 2 * cB * cD) g_pool[i] = 0.f;
}

// ---------------- prep: convert idx + hist + batch + layer0 (both graphs) ----
__global__ void k_prep(const int* __restrict__ ei0, const int* __restrict__ bat0,
                       const int* __restrict__ ei1, const int* __restrict__ bat1,
                       const float* __restrict__ x0, const float* __restrict__ x1,
                       const float* __restrict__ Wq, const float* __restrict__ bq,
                       const float* __restrict__ Wk, const float* __restrict__ bk,
                       const float* __restrict__ Wv, const float* __restrict__ bv,
                       const float* __restrict__ Ws, const float* __restrict__ bs) {
    int i = blockIdx.x * blockDim.x + threadIdx.x;
    // edge-index convert + dst histogram
    if (i < 4 * cE) {
        int grp = i / (2 * cE);
        int j = i - grp * (2 * cE);
        const int* ei = grp ? ei1 : ei0;
        int is32 = g_flag[grp];
        int v;
        if (is32) v = ei[j];
        else      v = (int)((const long long*)ei)[j];
        if (j < cE) {
            g_src[grp * cE + j] = v;
        } else {
            g_dst[grp * cE + (j - cE)] = v;
            atomicAdd(&g_deg[grp * cN + v], 1);
        }
    }
    // batch convert
    if (i < 2 * cN) {
        int grp = i / cN;
        int j = i - grp * cN;
        const int* bat = grp ? bat1 : bat0;
        int is32 = g_flag[2 + grp];
        g_bat[i] = is32 ? bat[j] : (int)((const long long*)bat)[j];
    }
    // layer-0 projections (input dim 4)
    if (i < 2 * cN * cD) {
        int grp = i / (cN * cD);
        int idx = i - grp * (cN * cD);
        const float* x = grp ? x1 : x0;
        int n = idx / cD;
        int d = idx - n * cD;
        float x0v = x[n * cND + 0];
        float x1v = x[n * cND + 1];
        float x2v = x[n * cND + 2];
        float x3v = x[n * cND + 3];
        float aq = bq[d] + x0v * Wq[0 * cD + d] + x1v * Wq[1 * cD + d] + x2v * Wq[2 * cD + d] + x3v * Wq[3 * cD + d];
        float ak = bk[d] + x0v * Wk[0 * cD + d] + x1v * Wk[1 * cD + d] + x2v * Wk[2 * cD + d] + x3v * Wk[3 * cD + d];
        float av = bv[d] + x0v * Wv[0 * cD + d] + x1v * Wv[1 * cD + d] + x2v * Wv[2 * cD + d] + x3v * Wv[3 * cD + d];
        float as = bs[d] + x0v * Ws[0 * cD + d] + x1v * Ws[1 * cD + d] + x2v * Ws[2 * cD + d] + x3v * Ws[3 * cD + d];
        size_t o = (size_t)grp * NSZ + idx;
        g_q[o] = aq;
        g_k[o] = ak;
        g_v[o] = av;
        g_hn[o] = as;
    }
}

// ---------------- CSR scan (one block per graph) ----------------
__global__ void __launch_bounds__(1024) k_scan() {
    const int T = 1024;
    const int CH = (cN + T - 1) / T;
    int grp = blockIdx.x;
    int t = threadIdx.x;
    const int* deg = g_deg + grp * cN;
    int* off = g_off + grp * (cN + 1);
    int vals[CH];
    int local = 0;
    int base = t * CH;
#pragma unroll
    for (int j = 0; j < CH; j++) {
        int idx = base + j;
        int v = (idx < cN) ? deg[idx] : 0;
        vals[j] = local;
        local += v;
    }
    __shared__ int sh[T];
    sh[t] = local;
    __syncthreads();
    for (int o = 1; o < T; o <<= 1) {
        int v = (t >= o) ? sh[t - o] : 0;
        __syncthreads();
        sh[t] += v;
        __syncthreads();
    }
    int prefix = sh[t] - local;
#pragma unroll
    for (int j = 0; j < CH; j++) {
        int idx = base + j;
        if (idx < cN) off[idx] = prefix + vals[j];
    }
    if (t == T - 1) off[cN] = sh[T - 1];
}

__global__ void k_scatter() {
    int i = blockIdx.x * blockDim.x + threadIdx.x;
    if (i < 2 * cE) {
        int grp = i / cE;
        int e = i - grp * cE;
        int d = g_dst[i];
        int p = atomicAdd(&g_cur[grp * cN + d], 1);
        g_csr[grp * cE + g_off[grp * (cN + 1) + d] + p] = e;
    }
}

// ---------------- weight split + transpose (+ flag zero) ----------------
__global__ void k_wconv(const float* __restrict__ Wq, const float* __restrict__ Wk,
                        const float* __restrict__ Wv, const float* __restrict__ Ws) {
    if (blockIdx.x == 0 && blockIdx.y == 0 && blockIdx.z == 0 &&
        threadIdx.y == 0 && threadIdx.x < 4) {
        g_flag[threadIdx.x] = 0;
    }
    int z = blockIdx.z;
    int l = z >> 2;
    int m = z & 3;
    const float* Wsel;
    if (m == 0)      Wsel = Wq;
    else if (m == 1) Wsel = Wk;
    else if (m == 2) Wsel = Wv;
    else             Wsel = Ws;
    const float* W = Wsel + (size_t)l * cD * cD;

    __shared__ float tile[32][33];
    int k0 = blockIdx.x * 32;
    int n0 = blockIdx.y * 32;
    for (int i = threadIdx.y; i < 32; i += 8) {
        tile[i][threadIdx.x] = W[(size_t)(k0 + i) * cD + n0 + threadIdx.x];
    }
    __syncthreads();
    __nv_bfloat16* hi = g_wsp + ((size_t)z * 2 + 0) * cD * cD;
    __nv_bfloat16* lo = g_wsp + ((size_t)z * 2 + 1) * cD * cD;
    for (int i = threadIdx.y; i < 32; i += 8) {
        float wv = tile[threadIdx.x][i];
        __nv_bfloat16 h = __float2bfloat16(wv);
        float r = wv - __bfloat162float(h);
        hi[(size_t)(n0 + i) * cD + k0 + threadIdx.x] = h;
        lo[(size_t)(n0 + i) * cD + k0 + threadIdx.x] = __float2bfloat16(r);
    }
}

// ---------------- fused edge aggregation, unroll-2, both graphs -------------
__global__ void __launch_bounds__(256, 2) k_edge(const float* __restrict__ ea0,
                                                 const float* __restrict__ ea1,
                                                 const float* __restrict__ We,
                                                 int do_relu) {
    int w = (blockIdx.x * blockDim.x + threadIdx.x) >> 5;
    int lane = threadIdx.x & 31;
    if (w >= 2 * cN) return;
    int grp = (w >= cN) ? 1 : 0;
    int n = w - grp * cN;
    const float* ea = grp ? ea1 : ea0;
    size_t gb = (size_t)grp * NSZ;
    const float4* qrow = (const float4*)(g_q + gb + (size_t)n * cD);
    const float* kbase = g_k + gb;
    const float* vbase = g_v + gb;
    const int* csr = g_csr + grp * cE;
    const int* srcarr = g_src + grp * cE;
    const int fi = lane;

    float4 qr[V4];
#pragma unroll
    for (int i = 0; i < V4; i++) qr[i] = qrow[fi + 32 * i];

    // qe packed as two float4 (8 edge-channels)
    float4 qeA, qeB;
    {
        float qe[cED];
#pragma unroll
        for (int c = 0; c < cED; c++) {
            const float4* wr = (const float4*)(We + (size_t)c * cD);
            float p = 0.f;
#pragma unroll
            for (int i = 0; i < V4; i++) {
                float4 wv = wr[fi + 32 * i];
                p += qr[i].x * wv.x + qr[i].y * wv.y + qr[i].z * wv.z + qr[i].w * wv.w;
            }
#pragma unroll
            for (int o = 16; o > 0; o >>= 1) p += __shfl_xor_sync(FULLMASK, p, o);
            qe[c] = p;
        }
        qeA = make_float4(qe[0], qe[1], qe[2], qe[3]);
        qeB = make_float4(qe[4], qe[5], qe[6], qe[7]);
    }

    float m = -1e30f;
    float s = 0.f;
    float4 acc[V4];
    float4 avA = make_float4(0.f, 0.f, 0.f, 0.f);
    float4 avB = make_float4(0.f, 0.f, 0.f, 0.f);
#pragma unroll
    for (int i = 0; i < V4; i++) acc[i] = make_float4(0.f, 0.f, 0.f, 0.f);

    int beg = g_off[grp * (cN + 1) + n];
    int end = g_off[grp * (cN + 1) + n + 1];
    int idx = beg;

    // unroll-2 main loop: two edges in flight
    for (; idx + 2 <= end; idx += 2) {
        int e0 = csr[idx];
        int e1 = csr[idx + 1];
        int s0 = srcarr[e0];
        int s1 = srcarr[e1];
        const float4* kr0 = (const float4*)(kbase + (size_t)s0 * cD);
        const float4* kr1 = (const float4*)(kbase + (size_t)s1 * cD);
        float4 e0A = ((const float4*)(ea + (size_t)e0 * cED))[0];
        float4 e0B = ((const float4*)(ea + (size_t)e0 * cED))[1];
        float4 e1A = ((const float4*)(ea + (size_t)e1 * cED))[0];
        float4 e1B = ((const float4*)(ea + (size_t)e1 * cED))[1];

        float dp0 = 0.f;
        float dp1 = 0.f;
#pragma unroll
        for (int i = 0; i < V4; i++) {
            float4 a = kr0[fi + 32 * i];
            float4 b = kr1[fi + 32 * i];
            dp0 += qr[i].x * a.x + qr[i].y * a.y + qr[i].z * a.z + qr[i].w * a.w;
            dp1 += qr[i].x * b.x + qr[i].y * b.y + qr[i].z * b.z + qr[i].w * b.w;
        }
#pragma unroll
        for (int o = 16; o > 0; o >>= 1) {
            dp0 += __shfl_xor_sync(FULLMASK, dp0, o);
            dp1 += __shfl_xor_sync(FULLMASK, dp1, o);
        }
        float sc0 = dp0 + qeA.x * e0A.x + qeA.y * e0A.y + qeA.z * e0A.z + qeA.w * e0A.w
                        + qeB.x * e0B.x + qeB.y * e0B.y + qeB.z * e0B.z + qeB.w * e0B.w;
        float sc1 = dp1 + qeA.x * e1A.x + qeA.y * e1A.y + qeA.z * e1A.z + qeA.w * e1A.w
                        + qeB.x * e1B.x + qeB.y * e1B.y + qeB.z * e1B.z + qeB.w * e1B.w;
        sc0 *= SCALE;
        sc1 *= SCALE;

        float mn = fmaxf(m, fmaxf(sc0, sc1));
        float f  = __expf(m - mn);
        float w0 = __expf(sc0 - mn);
        float w1 = __expf(sc1 - mn);
        s = s * f + w0 + w1;

        const float4* vr0 = (const float4*)(vbase + (size_t)s0 * cD);
        const float4* vr1 = (const float4*)(vbase + (size_t)s1 * cD);
#pragma unroll
        for (int i = 0; i < V4; i++) {
            float4 v0 = vr0[fi + 32 * i];
            float4 v1 = vr1[fi + 32 * i];
            acc[i].x = acc[i].x * f + w0 * v0.x + w1 * v1.x;
            acc[i].y = acc[i].y * f + w0 * v0.y + w1 * v1.y;
            acc[i].z = acc[i].z * f + w0 * v0.z + w1 * v1.z;
            acc[i].w = acc[i].w * f + w0 * v0.w + w1 * v1.w;
        }
        avA.x = avA.x * f + w0 * e0A.x + w1 * e1A.x;
        avA.y = avA.y * f + w0 * e0A.y + w1 * e1A.y;
        avA.z = avA.z * f + w0 * e0A.z + w1 * e1A.z;
        avA.w = avA.w * f + w0 * e0A.w + w1 * e1A.w;
        avB.x = avB.x * f + w0 * e0B.x + w1 * e1B.x;
        avB.y = avB.y * f + w0 * e0B.y + w1 * e1B.y;
        avB.z = avB.z * f + w0 * e0B.z + w1 * e1B.z;
        avB.w = avB.w * f + w0 * e0B.w + w1 * e1B.w;
        m = mn;
    }

    // tail (0 or 1 edge)
    if (idx < end) {
        int e0 = csr[idx];
        int s0 = srcarr[e0];
        const float4* kr0 = (const float4*)(kbase + (size_t)s0 * cD);
        float4 e0A = ((const float4*)(ea + (size_t)e0 * cED))[0];
        float4 e0B = ((const float4*)(ea + (size_t)e0 * cED))[1];
        float dp0 = 0.f;
#pragma unroll
        for (int i = 0; i < V4; i++) {
            float4 a = kr0[fi + 32 * i];
            dp0 += qr[i].x * a.x + qr[i].y * a.y + qr[i].z * a.z + qr[i].w * a.w;
        }
#pragma unroll
        for (int o = 16; o > 0; o >>= 1) dp0 += __shfl_xor_sync(FULLMASK, dp0, o);
        float sc0 = dp0 + qeA.x * e0A.x + qeA.y * e0A.y + qeA.z * e0A.z + qeA.w * e0A.w
                        + qeB.x * e0B.x + qeB.y * e0B.y + qeB.z * e0B.z + qeB.w * e0B.w;
        sc0 *= SCALE;
        float mn = fmaxf(m, sc0);
        float f  = __expf(m - mn);
        float w0 = __expf(sc0 - mn);
        s = s * f + w0;
        const float4* vr0 = (const float4*)(vbase + (size_t)s0 * cD);
#pragma unroll
        for (int i = 0; i < V4; i++) {
            float4 v0 = vr0[fi + 32 * i];
            acc[i].x = acc[i].x * f + w0 * v0.x;
            acc[i].y = acc[i].y * f + w0 * v0.y;
            acc[i].z = acc[i].z * f + w0 * v0.z;
            acc[i].w = acc[i].w * f + w0 * v0.w;
        }
        avA.x = avA.x * f + w0 * e0A.x;
        avA.y = avA.y * f + w0 * e0A.y;
        avA.z = avA.z * f + w0 * e0A.z;
        avA.w = avA.w * f + w0 * e0A.w;
        avB.x = avB.x * f + w0 * e0B.x;
        avB.y = avB.y * f + w0 * e0B.y;
        avB.z = avB.z * f + w0 * e0B.z;
        avB.w = avB.w * f + w0 * e0B.w;
        m = mn;
    }

    float inv = 1.f / (s + 1e-16f);
    float av[cED];
    av[0] = avA.x; av[1] = avA.y; av[2] = avA.z; av[3] = avA.w;
    av[4] = avB.x; av[5] = avB.y; av[6] = avB.z; av[7] = avB.w;
#pragma unroll
    for (int i = 0; i < V4; i++) {
        float4 ep = make_float4(0.f, 0.f, 0.f, 0.f);
#pragma unroll
        for (int c = 0; c < cED; c++) {
            float4 wv = ((const float4*)(We + (size_t)c * cD))[fi + 32 * i];
            ep.x += av[c] * wv.x;
            ep.y += av[c] * wv.y;
            ep.z += av[c] * wv.z;
            ep.w += av[c] * wv.w;
        }
        float4 hb = ((const float4*)(g_hn + gb + (size_t)n * cD))[fi + 32 * i];
        float4 o;
        o.x = hb.x + (acc[i].x + ep.x) * inv;
        o.y = hb.y + (acc[i].y + ep.y) * inv;
        o.z = hb.z + (acc[i].z + ep.z) * inv;
        o.w = hb.w + (acc[i].w + ep.w) * inv;
        if (do_relu) {
            o.x = fmaxf(o.x, 0.f);
            o.y = fmaxf(o.y, 0.f);
            o.z = fmaxf(o.z, 0.f);
            o.w = fmaxf(o.w, 0.f);
        }
        ((float4*)(g_h + gb + (size_t)n * cD))[fi + 32 * i] = o;

        __nv_bfloat16 h0 = __float2bfloat16(o.x);
        __nv_bfloat16 h1 = __float2bfloat16(o.y);
        __nv_bfloat16 h2 = __float2bfloat16(o.z);
        __nv_bfloat16 h3 = __float2bfloat16(o.w);
        __nv_bfloat16 l0 = __float2bfloat16(o.x - __bfloat162float(h0));
        __nv_bfloat16 l1 = __float2bfloat16(o.y - __bfloat162float(h1));
        __nv_bfloat16 l2 = __float2bfloat16(o.z - __bfloat162float(h2));
        __nv_bfloat16 l3 = __float2bfloat16(o.w - __bfloat162float(h3));
        ushort4 hv, lv;
        hv.x = *(unsigned short*)&h0; hv.y = *(unsigned short*)&h1;
        hv.z = *(unsigned short*)&h2; hv.w = *(unsigned short*)&h3;
        lv.x = *(unsigned short*)&l0; lv.y = *(unsigned short*)&l1;
        lv.z = *(unsigned short*)&l2; lv.w = *(unsigned short*)&l3;
        ((ushort4*)(g_ahi + gb + (size_t)n * cD))[fi + 32 * i] = hv;
        ((ushort4*)(g_alo + gb + (size_t)n * cD))[fi + 32 * i] = lv;
    }
}

// ---------------- pooling (both graphs) ----------------
__global__ void k_pool() {
    int w = (blockIdx.x * blockDim.x + threadIdx.x) >> 5;
    int lane = threadIdx.x & 31;
    if (w >= 2 * cN) return;
    int grp = (w >= cN) ? 1 : 0;
    int n = w - grp * cN;
    int b = g_bat[w];
    size_t gb = (size_t)grp * NSZ;
    float* pool = g_pool + grp * cB * cD;
#pragma unroll
    for (int i = 0; i < RPT; i++) {
        atomicAdd(&pool[b * cD + lane + 32 * i], g_h[gb + (size_t)n * cD + lane + 32 * i]);
    }
}

// ---------------- LN + Linear + ReLU head (both graphs) ----------------
__global__ void __launch_bounds__(640) k_head(const float* __restrict__ ln_g,
                                              const float* __restrict__ ln_b,
                                              const float* __restrict__ Wemb,
                                              const float* __restrict__ bemb) {
    int bx = blockIdx.x;
    int grp = bx >> 6;
    int b = bx & 63;
    int t = threadIdx.x;
    __shared__ float red[20];
    __shared__ float zsh[cD];
    __shared__ float s_mu;
    __shared__ float s_rs;
    float x = g_pool[grp * cB * cD + b * cD + t];

    float v = x;
#pragma unroll
    for (int o = 16; o > 0; o >>= 1) v += __shfl_xor_sync(FULLMASK, v, o);
    if ((t & 31) == 0) red[t >> 5] = v;
    __syncthreads();
    if (t == 0) {
        float s = 0.f;
        for (int i = 0; i < 20; i++) s += red[i];
        s_mu = s / cD;
    }
    __syncthreads();
    float dev = x - s_mu;
    v = dev * dev;
#pragma unroll
    for (int o = 16; o > 0; o >>= 1) v += __shfl_xor_sync(FULLMASK, v, o);
    if ((t & 31) == 0) red[t >> 5] = v;
    __syncthreads();
    if (t == 0) {
        float s = 0.f;
        for (int i = 0; i < 20; i++) s += red[i];
        s_rs = rsqrtf(s / cD + 1e-5f);
    }
    __syncthreads();
    zsh[t] = dev * s_rs * ln_g[t] + ln_b[t];
    __syncthreads();

    float o = bemb[t];
#pragma unroll 4
    for (int kk = 0; kk < cD; kk++) o += zsh[kk] * Wemb[(size_t)kk * cD + t];
    g_z[grp][b * cD + t] = fmaxf(o, 0.f);
}

// ---------------- cosine ----------------
__global__ void k_cos(float* __restrict__ out) {
    int b = blockIdx.x;
    int t = threadIdx.x;
    float dp = 0.f;
    float ai = 0.f;
    float aj = 0.f;
    for (int d = t; d < cD; d += 256) {
        float zi = g_z[0][b * cD + d];
        float zj = g_z[1][b * cD + d];
        dp += zi * zj;
        ai += zi * zi;
        aj += zj * zj;
    }
#pragma unroll
    for (int o = 16; o > 0; o >>= 1) {
        dp += __shfl_xor_sync(FULLMASK, dp, o);
        ai += __shfl_xor_sync(FULLMASK, ai, o);
        aj += __shfl_xor_sync(FULLMASK, aj, o);
    }
    __shared__ float r1[8];
    __shared__ float r2[8];
    __shared__ float r3[8];
    int wd = t >> 5;
    if ((t & 31) == 0) { r1[wd] = dp; r2[wd] = ai; r3[wd] = aj; }
    __syncthreads();
    if (t == 0) {
        float sD = 0.f;
        float sA = 0.f;
        float sB = 0.f;
        for (int i = 0; i < 8; i++) { sD += r1[i]; sA += r2[i]; sB += r3[i]; }
        out[b] = sD / (fmaxf(sqrtf(sA), 1e-8f) * fmaxf(sqrtf(sB), 1e-8f));
    }
}

// ---------------- driver ----------------
extern "C" void kernel_launch(void* const* d_in, const int* in_sizes, int n_in,
                              void* d_out, int out_size) {
    const float* x_i   = (const float*)d_in[0];
    const int*   ei_i  = (const int*)d_in[1];
    const float* ea_i  = (const float*)d_in[2];
    const int*   bat_i = (const int*)d_in[3];
    const float* x_j   = (const float*)d_in[4];
    const int*   ei_j  = (const int*)d_in[5];
    const float* ea_j  = (const float*)d_in[6];
    const int*   bat_j = (const int*)d_in[7];
    const float* W0q = (const float*)d_in[8];
    const float* b0q = (const float*)d_in[9];
    const float* W0k = (const float*)d_in[10];
    const float* b0k = (const float*)d_in[11];
    const float* W0v = (const float*)d_in[12];
    const float* b0v = (const float*)d_in[13];
    const float* W0e = (const float*)d_in[14];
    const float* W0s = (const float*)d_in[15];
    const float* b0s = (const float*)d_in[16];
    const float* Wq  = (const float*)d_in[17];
    const float* bq  = (const float*)d_in[18];
    const float* Wk  = (const float*)d_in[19];
    const float* bk  = (const float*)d_in[20];
    const float* Wv  = (const float*)d_in[21];
    const float* bv  = (const float*)d_in[22];
    const float* We  = (const float*)d_in[23];
    const float* Ws  = (const float*)d_in[24];
    const float* bs  = (const float*)d_in[25];
    const float* ln_g = (const float*)d_in[26];
    const float* ln_b = (const float*)d_in[27];
    const float* Wemb = (const float*)d_in[28];
    const float* bemb = (const float*)d_in[29];
    float* out = (float*)d_out;

    const int TB = 256;

    static int attr_done = 0;
    if (!attr_done) {
        cudaFuncSetAttribute(k_gemm_m, cudaFuncAttributeMaxDynamicSharedMemorySize, GSMEM);
        attr_done = 1;
    }

    // 1: weight split+transpose (also zeroes dtype flags)
    dim3 wgrid(cD / 32, cD / 32, cL1 * 4);
    dim3 wblock(32, 8, 1);
    k_wconv<<<wgrid, wblock>>>(Wq, Wk, Wv, Ws);

    // 2: dtype detect + zero counters/pool (both graphs)
    k_detect<<<(2 * cE + TB - 1) / TB, TB>>>(ei_i, bat_i, ei_j, bat_j);

    // 3: convert + hist + batch + layer0 (both graphs)
    k_prep<<<(2 * cN * cD + TB - 1) / TB, TB>>>(ei_i, bat_i, ei_j, bat_j, x_i, x_j,
                                                W0q, b0q, W0k, b0k, W0v, b0v, W0s, b0s);

    // 4: scan, 5: scatter
    k_scan<<<2, 1024>>>();
    k_scatter<<<(2 * cE + TB - 1) / TB, TB>>>();

    // 6: edge layer 0 (both graphs)  [ncu -s 5 profiles this one]
    k_edge<<<(2 * cN + 7) / 8, TB>>>(ea_i, ea_j, W0e, 1);

    // layers 1..5: gemm (both graphs, z=8) + edge (both graphs)
    dim3 gemm_grid((cN + 127) / 128, cD / 128, 8);
    for (int l = 0; l < cL1; l++) {
        k_gemm_m<<<gemm_grid, 512, GSMEM>>>(l,
            bq + (size_t)l * cD, bk + (size_t)l * cD,
            bv + (size_t)l * cD, bs + (size_t)l * cD);
        int dorelu = (l < 4) ? 1 : 0;
        k_edge<<<(2 * cN + 7) / 8, TB>>>(ea_i, ea_j, We + (size_t)l * cED * cD, dorelu);
    }

    // pool + head + cosine
    k_pool<<<(2 * cN + 7) / 8, TB>>>();
    k_head<<<2 * cB, cD>>>(ln_g, ln_b, Wemb, bemb);
    k_cos<<<cB, 256>>>(out);
}

// round 14
// speedup vs baseline: 2.1113x; 1.0266x over previous
#include <cuda_runtime.h>
#include <cuda_bf16.h>
#include <cstdint>
#include <cstddef>
#include <math.h>

typedef unsigned int u32;
typedef unsigned long long u64;

// Problem constants
constexpr int cN  = 10000;
constexpr int cE  = 160000;
constexpr int cB  = 64;
constexpr int cD  = 640;
constexpr int cND = 4;
constexpr int cED = 8;
constexpr int cL1 = 5;
constexpr int RPT = cD / 32;
constexpr int V4  = cD / 128;
constexpr size_t NSZ = (size_t)cN * cD;

#define FULLMASK 0xffffffffu
#define SCALE 0.0395284707521047416f  // 1/sqrt(640)

// ---------------- scratch (per-graph doubled) ----------------
__device__ __align__(16) float g_h [2 * cN * cD];
__device__ __align__(16) float g_q [2 * cN * cD];
__device__ __align__(16) float g_k [2 * cN * cD];
__device__ __align__(16) float g_v [2 * cN * cD];
__device__ __align__(16) float g_hn[2 * cN * cD];
__device__ __align__(16) __nv_bfloat16 g_ahi[2 * cN * cD];
__device__ __align__(16) __nv_bfloat16 g_alo[2 * cN * cD];
__device__ __align__(16) __nv_bfloat16 g_wsp[cL1 * 4 * 2 * cD * cD];
__device__ int g_src[2 * cE];
__device__ int g_dst[2 * cE];
__device__ int g_bat[2 * cN];
__device__ int g_flag[4];
__device__ int g_deg[2 * cN];
__device__ int g_cur[2 * cN];
__device__ int g_off[2 * (cN + 1)];
__device__ int g_csr[2 * cE];
__device__ __align__(16) float g_pool[2 * cB * cD];
__device__ __align__(16) float g_z[2][cB * cD];

__device__ __forceinline__ float* buf_sel(int grp, int s) {
    float* p;
    switch (s) {
        case 0:  p = g_h;  break;
        case 1:  p = g_q;  break;
        case 2:  p = g_k;  break;
        case 3:  p = g_v;  break;
        default: p = g_hn; break;
    }
    return p + (size_t)grp * NSZ;
}

__device__ __forceinline__ u32 smem_u32(const void* p) {
    return (u32)__cvta_generic_to_shared(p);
}

__device__ __forceinline__ void ldsm4(u32& r0, u32& r1, u32& r2, u32& r3, u32 addr) {
    asm volatile("ldmatrix.sync.aligned.m8n8.x4.shared.b16 {%0,%1,%2,%3}, [%4];"
                 : "=r"(r0), "=r"(r1), "=r"(r2), "=r"(r3)
                 : "r"(addr));
}

__device__ __forceinline__ void mma16816(float* c, const u32* a, u32 b0, u32 b1) {
    asm volatile("mma.sync.aligned.m16n8k16.row.col.f32.bf16.bf16.f32 "
                 "{%0,%1,%2,%3}, {%4,%5,%6,%7}, {%8,%9}, {%0,%1,%2,%3};"
                 : "+f"(c[0]), "+f"(c[1]), "+f"(c[2]), "+f"(c[3])
                 : "r"(a[0]), "r"(a[1]), "r"(a[2]), "r"(a[3]), "r"(b0), "r"(b1));
}

template <int N>
__device__ __forceinline__ void cp_wait() {
    asm volatile("cp.async.wait_group %0;" :: "n"(N) : "memory");
}

__device__ __forceinline__ void cp_commit() {
    asm volatile("cp.async.commit_group;" ::: "memory");
}

// ---------------- GEMM config ----------------
constexpr int ST = 3;
constexpr int CK = 32;
constexpr int NC = cD / CK;
constexpr int ROWB  = 80;
constexpr int PARTB = 128 * ROWB;
constexpr int STAGEB = 4 * PARTB;
constexpr int GSMEM = ST * STAGEB;    // 122880 B

__device__ __forceinline__ void ld_part(u32 sdst, const __nv_bfloat16* g,
                                        int row0, int rmax, int col0, int tid) {
    int row = tid >> 2;
    int s4  = tid & 3;
    u32 dst = sdst + (u32)(row * ROWB + s4 * 16);
    const void* src = (const void*)(g + (size_t)(row0 + row) * cD + col0 + s4 * 8);
    int ok = (row0 + row < rmax) ? 16 : 0;
    asm volatile("cp.async.cg.shared.global [%0], [%1], 16, %2;"
                 :: "r"(dst), "l"(src), "r"(ok) : "memory");
}

// C = A @ W + bias; 3-term bf16 split, fp32 accum. One graph per launch.
// block 128x128, 16 warps (4M x 4N). grid (79, 5, 4): z = mat
__global__ void __launch_bounds__(512, 1) k_gemm_m(int layer, int grp,
                                                   const float* __restrict__ bq,
                                                   const float* __restrict__ bk,
                                                   const float* __restrict__ bv,
                                                   const float* __restrict__ bs) {
    extern __shared__ char smem[];
    u32 sb = smem_u32(smem);
    int tid = threadIdx.x;
    int lane = tid & 31;
    int warp = tid >> 5;
    int wm = warp & 3;
    int wn = warp >> 2;
    int z = blockIdx.z;

    const __nv_bfloat16* Ahi = g_ahi + (size_t)grp * NSZ;
    const __nv_bfloat16* Alo = g_alo + (size_t)grp * NSZ;
    const __nv_bfloat16* Whi = g_wsp + ((size_t)(layer * 4 + z) * 2 + 0) * cD * cD;
    const __nv_bfloat16* Wlo = Whi + (size_t)cD * cD;
    const float* bias;
    if (z == 0)      bias = bq;
    else if (z == 1) bias = bk;
    else if (z == 2) bias = bv;
    else             bias = bs;
    float* outp = buf_sel(grp, z + 1);

    int bm = blockIdx.x * 128;
    int bn = blockIdx.y * 128;

    float acc[2][4][4];
#pragma unroll
    for (int mi = 0; mi < 2; mi++) {
#pragma unroll
        for (int nj = 0; nj < 4; nj++) {
#pragma unroll
            for (int c = 0; c < 4; c++) acc[mi][nj][c] = 0.f;
        }
    }

#pragma unroll
    for (int c = 0; c < 2; c++) {
        u32 st = sb + (u32)(c * STAGEB);
        int col0 = c * CK;
        ld_part(st,             Ahi, bm, cN, col0, tid);
        ld_part(st + PARTB,     Alo, bm, cN, col0, tid);
        ld_part(st + 2 * PARTB, Whi, bn, cD, col0, tid);
        ld_part(st + 3 * PARTB, Wlo, bn, cD, col0, tid);
        cp_commit();
    }

    int lrow = lane & 15;
    int lcol = (lane >> 4) * 8;

    for (int c = 0; c < NC; c++) {
        if (c < NC - 1) cp_wait<1>();
        else            cp_wait<0>();
        __syncthreads();

        if (c + 2 < NC) {
            u32 st2 = sb + (u32)(((c + 2) % ST) * STAGEB);
            int col0 = (c + 2) * CK;
            ld_part(st2,             Ahi, bm, cN, col0, tid);
            ld_part(st2 + PARTB,     Alo, bm, cN, col0, tid);
            ld_part(st2 + 2 * PARTB, Whi, bn, cD, col0, tid);
            ld_part(st2 + 3 * PARTB, Wlo, bn, cD, col0, tid);
            cp_commit();
        }

        u32 st = sb + (u32)((c % ST) * STAGEB);
#pragma unroll
        for (int ks = 0; ks < CK; ks += 16) {
            u32 ah[2][4];
            u32 al[2][4];
            u32 bh[2][4];
            u32 bl[2][4];
            u32 kb = (u32)((ks + lcol) * 2);
#pragma unroll
            for (int mi = 0; mi < 2; mi++) {
                u32 ra = st + (u32)((wm * 32 + mi * 16 + lrow) * ROWB) + kb;
                ldsm4(ah[mi][0], ah[mi][1], ah[mi][2], ah[mi][3], ra);
                ldsm4(al[mi][0], al[mi][1], al[mi][2], al[mi][3], ra + (u32)PARTB);
            }
#pragma unroll
            for (int gg = 0; gg < 2; gg++) {
                u32 rb = st + (u32)(2 * PARTB) + (u32)((wn * 32 + gg * 16 + lrow) * ROWB) + kb;
                ldsm4(bh[gg][0], bh[gg][1], bh[gg][2], bh[gg][3], rb);
                ldsm4(bl[gg][0], bl[gg][1], bl[gg][2], bl[gg][3], rb + (u32)PARTB);
            }
#pragma unroll
            for (int mi = 0; mi < 2; mi++) {
#pragma unroll
                for (int nj = 0; nj < 4; nj++) {
                    int gg = nj >> 1;
                    int xx = nj & 1;
                    mma16816(acc[mi][nj], ah[mi], bh[gg][xx], bh[gg][xx + 2]);
                    mma16816(acc[mi][nj], ah[mi], bl[gg][xx], bl[gg][xx + 2]);
                    mma16816(acc[mi][nj], al[mi], bh[gg][xx], bh[gg][xx + 2]);
                }
            }
        }
    }

    int gid = lane >> 2;
    int tig = lane & 3;
#pragma unroll
    for (int mi = 0; mi < 2; mi++) {
#pragma unroll
        for (int nj = 0; nj < 4; nj++) {
            int colg = bn + wn * 32 + nj * 8 + tig * 2;
            float bias0 = bias[colg];
            float bias1 = bias[colg + 1];
            int r0 = bm + wm * 32 + mi * 16 + gid;
            if (r0 < cN) {
                float2 o0;
                o0.x = acc[mi][nj][0] + bias0;
                o0.y = acc[mi][nj][1] + bias1;
                *(float2*)(outp + (size_t)r0 * cD + colg) = o0;
            }
            int r1 = r0 + 8;
            if (r1 < cN) {
                float2 o1;
                o1.x = acc[mi][nj][2] + bias0;
                o1.y = acc[mi][nj][3] + bias1;
                *(float2*)(outp + (size_t)r1 * cD + colg) = o1;
            }
        }
    }
}

// ---------------- detect (both graphs) + zero deg/cur/pool ----------------
__global__ void k_detect(const int* __restrict__ ei0, const int* __restrict__ bat0,
                         const int* __restrict__ ei1, const int* __restrict__ bat1) {
    int i = blockIdx.x * blockDim.x + threadIdx.x;
    if (i < 2 * cE) {
        int grp = i / cE;
        int j = i - grp * cE;
        const int* ei = grp ? ei1 : ei0;
        if (ei[2 * j + 1] != 0) atomicOr(&g_flag[grp], 1);
    }
    if (i < cN) {
        int grp = i / (cN / 2);
        int j = i - grp * (cN / 2);
        const int* bat = grp ? bat1 : bat0;
        if (bat[2 * j + 1] != 0) atomicOr(&g_flag[2 + grp], 1);
    }
    if (i < 2 * cN) { g_deg[i] = 0; g_cur[i] = 0; }
    if (i < 2 * cB * cD) g_pool[i] = 0.f;
}

// ---------------- prep: convert idx + hist + batch + layer0 (both graphs) ----
__global__ void k_prep(const int* __restrict__ ei0, const int* __restrict__ bat0,
                       const int* __restrict__ ei1, const int* __restrict__ bat1,
                       const float* __restrict__ x0, const float* __restrict__ x1,
                       const float* __restrict__ Wq, const float* __restrict__ bq,
                       const float* __restrict__ Wk, const float* __restrict__ bk,
                       const float* __restrict__ Wv, const float* __restrict__ bv,
                       const float* __restrict__ Ws, const float* __restrict__ bs) {
    int i = blockIdx.x * blockDim.x + threadIdx.x;
    if (i < 4 * cE) {
        int grp = i / (2 * cE);
        int j = i - grp * (2 * cE);
        const int* ei = grp ? ei1 : ei0;
        int is32 = g_flag[grp];
        int v;
        if (is32) v = ei[j];
        else      v = (int)((const long long*)ei)[j];
        if (j < cE) {
            g_src[grp * cE + j] = v;
        } else {
            g_dst[grp * cE + (j - cE)] = v;
            atomicAdd(&g_deg[grp * cN + v], 1);
        }
    }
    if (i < 2 * cN) {
        int grp = i / cN;
        int j = i - grp * cN;
        const int* bat = grp ? bat1 : bat0;
        int is32 = g_flag[2 + grp];
        g_bat[i] = is32 ? bat[j] : (int)((const long long*)bat)[j];
    }
    if (i < 2 * cN * cD) {
        int grp = i / (cN * cD);
        int idx = i - grp * (cN * cD);
        const float* x = grp ? x1 : x0;
        int n = idx / cD;
        int d = idx - n * cD;
        float x0v = x[n * cND + 0];
        float x1v = x[n * cND + 1];
        float x2v = x[n * cND + 2];
        float x3v = x[n * cND + 3];
        float aq = bq[d] + x0v * Wq[0 * cD + d] + x1v * Wq[1 * cD + d] + x2v * Wq[2 * cD + d] + x3v * Wq[3 * cD + d];
        float ak = bk[d] + x0v * Wk[0 * cD + d] + x1v * Wk[1 * cD + d] + x2v * Wk[2 * cD + d] + x3v * Wk[3 * cD + d];
        float av = bv[d] + x0v * Wv[0 * cD + d] + x1v * Wv[1 * cD + d] + x2v * Wv[2 * cD + d] + x3v * Wv[3 * cD + d];
        float as = bs[d] + x0v * Ws[0 * cD + d] + x1v * Ws[1 * cD + d] + x2v * Ws[2 * cD + d] + x3v * Ws[3 * cD + d];
        size_t o = (size_t)grp * NSZ + idx;
        g_q[o] = aq;
        g_k[o] = ak;
        g_v[o] = av;
        g_hn[o] = as;
    }
}

// ---------------- CSR scan (one block per graph) ----------------
__global__ void __launch_bounds__(1024) k_scan() {
    const int T = 1024;
    const int CH = (cN + T - 1) / T;
    int grp = blockIdx.x;
    int t = threadIdx.x;
    const int* deg = g_deg + grp * cN;
    int* off = g_off + grp * (cN + 1);
    int vals[CH];
    int local = 0;
    int base = t * CH;
#pragma unroll
    for (int j = 0; j < CH; j++) {
        int idx = base + j;
        int v = (idx < cN) ? deg[idx] : 0;
        vals[j] = local;
        local += v;
    }
    __shared__ int sh[T];
    sh[t] = local;
    __syncthreads();
    for (int o = 1; o < T; o <<= 1) {
        int v = (t >= o) ? sh[t - o] : 0;
        __syncthreads();
        sh[t] += v;
        __syncthreads();
    }
    int prefix = sh[t] - local;
#pragma unroll
    for (int j = 0; j < CH; j++) {
        int idx = base + j;
        if (idx < cN) off[idx] = prefix + vals[j];
    }
    if (t == T - 1) off[cN] = sh[T - 1];
}

__global__ void k_scatter() {
    int i = blockIdx.x * blockDim.x + threadIdx.x;
    if (i < 2 * cE) {
        int grp = i / cE;
        int e = i - grp * cE;
        int d = g_dst[i];
        int p = atomicAdd(&g_cur[grp * cN + d], 1);
        g_csr[grp * cE + g_off[grp * (cN + 1) + d] + p] = e;
    }
}

// ---------------- weight split + transpose (+ flag zero) ----------------
__global__ void k_wconv(const float* __restrict__ Wq, const float* __restrict__ Wk,
                        const float* __restrict__ Wv, const float* __restrict__ Ws) {
    if (blockIdx.x == 0 && blockIdx.y == 0 && blockIdx.z == 0 &&
        threadIdx.y == 0 && threadIdx.x < 4) {
        g_flag[threadIdx.x] = 0;
    }
    int z = blockIdx.z;
    int l = z >> 2;
    int m = z & 3;
    const float* Wsel;
    if (m == 0)      Wsel = Wq;
    else if (m == 1) Wsel = Wk;
    else if (m == 2) Wsel = Wv;
    else             Wsel = Ws;
    const float* W = Wsel + (size_t)l * cD * cD;

    __shared__ float tile[32][33];
    int k0 = blockIdx.x * 32;
    int n0 = blockIdx.y * 32;
    for (int i = threadIdx.y; i < 32; i += 8) {
        tile[i][threadIdx.x] = W[(size_t)(k0 + i) * cD + n0 + threadIdx.x];
    }
    __syncthreads();
    __nv_bfloat16* hi = g_wsp + ((size_t)z * 2 + 0) * cD * cD;
    __nv_bfloat16* lo = g_wsp + ((size_t)z * 2 + 1) * cD * cD;
    for (int i = threadIdx.y; i < 32; i += 8) {
        float wv = tile[threadIdx.x][i];
        __nv_bfloat16 h = __float2bfloat16(wv);
        float r = wv - __bfloat162float(h);
        hi[(size_t)(n0 + i) * cD + k0 + threadIdx.x] = h;
        lo[(size_t)(n0 + i) * cD + k0 + threadIdx.x] = __float2bfloat16(r);
    }
}

// ---------------- fused edge aggregation, unroll-2, one graph per launch ----
__global__ void __launch_bounds__(256, 2) k_edge(const float* __restrict__ ea,
                                                 const float* __restrict__ We,
                                                 int grp, int do_relu) {
    int n = (blockIdx.x * blockDim.x + threadIdx.x) >> 5;
    int lane = threadIdx.x & 31;
    if (n >= cN) return;
    size_t gb = (size_t)grp * NSZ;
    const float4* qrow = (const float4*)(g_q + gb + (size_t)n * cD);
    const float* kbase = g_k + gb;
    const float* vbase = g_v + gb;
    const int* csr = g_csr + grp * cE;
    const int* srcarr = g_src + grp * cE;
    const int fi = lane;

    float4 qr[V4];
#pragma unroll
    for (int i = 0; i < V4; i++) qr[i] = qrow[fi + 32 * i];

    float4 qeA, qeB;
    {
        float qe[cED];
#pragma unroll
        for (int c = 0; c < cED; c++) {
            const float4* wr = (const float4*)(We + (size_t)c * cD);
            float p = 0.f;
#pragma unroll
            for (int i = 0; i < V4; i++) {
                float4 wv = wr[fi + 32 * i];
                p += qr[i].x * wv.x + qr[i].y * wv.y + qr[i].z * wv.z + qr[i].w * wv.w;
            }
#pragma unroll
            for (int o = 16; o > 0; o >>= 1) p += __shfl_xor_sync(FULLMASK, p, o);
            qe[c] = p;
        }
        qeA = make_float4(qe[0], qe[1], qe[2], qe[3]);
        qeB = make_float4(qe[4], qe[5], qe[6], qe[7]);
    }

    float m = -1e30f;
    float s = 0.f;
    float4 acc[V4];
    float4 avA = make_float4(0.f, 0.f, 0.f, 0.f);
    float4 avB = make_float4(0.f, 0.f, 0.f, 0.f);
#pragma unroll
    for (int i = 0; i < V4; i++) acc[i] = make_float4(0.f, 0.f, 0.f, 0.f);

    int beg = g_off[grp * (cN + 1) + n];
    int end = g_off[grp * (cN + 1) + n + 1];
    int idx = beg;

    for (; idx + 2 <= end; idx += 2) {
        int e0 = csr[idx];
        int e1 = csr[idx + 1];
        int s0 = srcarr[e0];
        int s1 = srcarr[e1];
        const float4* kr0 = (const float4*)(kbase + (size_t)s0 * cD);
        const float4* kr1 = (const float4*)(kbase + (size_t)s1 * cD);
        float4 e0A = ((const float4*)(ea + (size_t)e0 * cED))[0];
        float4 e0B = ((const float4*)(ea + (size_t)e0 * cED))[1];
        float4 e1A = ((const float4*)(ea + (size_t)e1 * cED))[0];
        float4 e1B = ((const float4*)(ea + (size_t)e1 * cED))[1];

        float dp0 = 0.f;
        float dp1 = 0.f;
#pragma unroll
        for (int i = 0; i < V4; i++) {
            float4 a = kr0[fi + 32 * i];
            float4 b = kr1[fi + 32 * i];
            dp0 += qr[i].x * a.x + qr[i].y * a.y + qr[i].z * a.z + qr[i].w * a.w;
            dp1 += qr[i].x * b.x + qr[i].y * b.y + qr[i].z * b.z + qr[i].w * b.w;
        }
#pragma unroll
        for (int o = 16; o > 0; o >>= 1) {
            dp0 += __shfl_xor_sync(FULLMASK, dp0, o);
            dp1 += __shfl_xor_sync(FULLMASK, dp1, o);
        }
        float sc0 = dp0 + qeA.x * e0A.x + qeA.y * e0A.y + qeA.z * e0A.z + qeA.w * e0A.w
                        + qeB.x * e0B.x + qeB.y * e0B.y + qeB.z * e0B.z + qeB.w * e0B.w;
        float sc1 = dp1 + qeA.x * e1A.x + qeA.y * e1A.y + qeA.z * e1A.z + qeA.w * e1A.w
                        + qeB.x * e1B.x + qeB.y * e1B.y + qeB.z * e1B.z + qeB.w * e1B.w;
        sc0 *= SCALE;
        sc1 *= SCALE;

        float mn = fmaxf(m, fmaxf(sc0, sc1));
        float f  = __expf(m - mn);
        float w0 = __expf(sc0 - mn);
        float w1 = __expf(sc1 - mn);
        s = s * f + w0 + w1;

        const float4* vr0 = (const float4*)(vbase + (size_t)s0 * cD);
        const float4* vr1 = (const float4*)(vbase + (size_t)s1 * cD);
#pragma unroll
        for (int i = 0; i < V4; i++) {
            float4 v0 = vr0[fi + 32 * i];
            float4 v1 = vr1[fi + 32 * i];
            acc[i].x = acc[i].x * f + w0 * v0.x + w1 * v1.x;
            acc[i].y = acc[i].y * f + w0 * v0.y + w1 * v1.y;
            acc[i].z = acc[i].z * f + w0 * v0.z + w1 * v1.z;
            acc[i].w = acc[i].w * f + w0 * v0.w + w1 * v1.w;
        }
        avA.x = avA.x * f + w0 * e0A.x + w1 * e1A.x;
        avA.y = avA.y * f + w0 * e0A.y + w1 * e1A.y;
        avA.z = avA.z * f + w0 * e0A.z + w1 * e1A.z;
        avA.w = avA.w * f + w0 * e0A.w + w1 * e1A.w;
        avB.x = avB.x * f + w0 * e0B.x + w1 * e1B.x;
        avB.y = avB.y * f + w0 * e0B.y + w1 * e1B.y;
        avB.z = avB.z * f + w0 * e0B.z + w1 * e1B.z;
        avB.w = avB.w * f + w0 * e0B.w + w1 * e1B.w;
        m = mn;
    }

    if (idx < end) {
        int e0 = csr[idx];
        int s0 = srcarr[e0];
        const float4* kr0 = (const float4*)(kbase + (size_t)s0 * cD);
        float4 e0A = ((const float4*)(ea + (size_t)e0 * cED))[0];
        float4 e0B = ((const float4*)(ea + (size_t)e0 * cED))[1];
        float dp0 = 0.f;
#pragma unroll
        for (int i = 0; i < V4; i++) {
            float4 a = kr0[fi + 32 * i];
            dp0 += qr[i].x * a.x + qr[i].y * a.y + qr[i].z * a.z + qr[i].w * a.w;
        }
#pragma unroll
        for (int o = 16; o > 0; o >>= 1) dp0 += __shfl_xor_sync(FULLMASK, dp0, o);
        float sc0 = dp0 + qeA.x * e0A.x + qeA.y * e0A.y + qeA.z * e0A.z + qeA.w * e0A.w
                        + qeB.x * e0B.x + qeB.y * e0B.y + qeB.z * e0B.z + qeB.w * e0B.w;
        sc0 *= SCALE;
        float mn = fmaxf(m, sc0);
        float f  = __expf(m - mn);
        float w0 = __expf(sc0 - mn);
        s = s * f + w0;
        const float4* vr0 = (const float4*)(vbase + (size_t)s0 * cD);
#pragma unroll
        for (int i = 0; i < V4; i++) {
            float4 v0 = vr0[fi + 32 * i];
            acc[i].x = acc[i].x * f + w0 * v0.x;
            acc[i].y = acc[i].y * f + w0 * v0.y;
            acc[i].z = acc[i].z * f + w0 * v0.z;
            acc[i].w = acc[i].w * f + w0 * v0.w;
        }
        avA.x = avA.x * f + w0 * e0A.x;
        avA.y = avA.y * f + w0 * e0A.y;
        avA.z = avA.z * f + w0 * e0A.z;
        avA.w = avA.w * f + w0 * e0A.w;
        avB.x = avB.x * f + w0 * e0B.x;
        avB.y = avB.y * f + w0 * e0B.y;
        avB.z = avB.z * f + w0 * e0B.z;
        avB.w = avB.w * f + w0 * e0B.w;
        m = mn;
    }

    float inv = 1.f / (s + 1e-16f);
    float av[cED];
    av[0] = avA.x; av[1] = avA.y; av[2] = avA.z; av[3] = avA.w;
    av[4] = avB.x; av[5] = avB.y; av[6] = avB.z; av[7] = avB.w;
#pragma unroll
    for (int i = 0; i < V4; i++) {
        float4 ep = make_float4(0.f, 0.f, 0.f, 0.f);
#pragma unroll
        for (int c = 0; c < cED; c++) {
            float4 wv = ((const float4*)(We + (size_t)c * cD))[fi + 32 * i];
            ep.x += av[c] * wv.x;
            ep.y += av[c] * wv.y;
            ep.z += av[c] * wv.z;
            ep.w += av[c] * wv.w;
        }
        float4 hb = ((const float4*)(g_hn + gb + (size_t)n * cD))[fi + 32 * i];
        float4 o;
        o.x = hb.x + (acc[i].x + ep.x) * inv;
        o.y = hb.y + (acc[i].y + ep.y) * inv;
        o.z = hb.z + (acc[i].z + ep.z) * inv;
        o.w = hb.w + (acc[i].w + ep.w) * inv;
        if (do_relu) {
            o.x = fmaxf(o.x, 0.f);
            o.y = fmaxf(o.y, 0.f);
            o.z = fmaxf(o.z, 0.f);
            o.w = fmaxf(o.w, 0.f);
        }
        ((float4*)(g_h + gb + (size_t)n * cD))[fi + 32 * i] = o;

        __nv_bfloat16 h0 = __float2bfloat16(o.x);
        __nv_bfloat16 h1 = __float2bfloat16(o.y);
        __nv_bfloat16 h2 = __float2bfloat16(o.z);
        __nv_bfloat16 h3 = __float2bfloat16(o.w);
        __nv_bfloat16 l0 = __float2bfloat16(o.x - __bfloat162float(h0));
        __nv_bfloat16 l1 = __float2bfloat16(o.y - __bfloat162float(h1));
        __nv_bfloat16 l2 = __float2bfloat16(o.z - __bfloat162float(h2));
        __nv_bfloat16 l3 = __float2bfloat16(o.w - __bfloat162float(h3));
        ushort4 hv, lv;
        hv.x = *(unsigned short*)&h0; hv.y = *(unsigned short*)&h1;
        hv.z = *(unsigned short*)&h2; hv.w = *(unsigned short*)&h3;
        lv.x = *(unsigned short*)&l0; lv.y = *(unsigned short*)&l1;
        lv.z = *(unsigned short*)&l2; lv.w = *(unsigned short*)&l3;
        ((ushort4*)(g_ahi + gb + (size_t)n * cD))[fi + 32 * i] = hv;
        ((ushort4*)(g_alo + gb + (size_t)n * cD))[fi + 32 * i] = lv;
    }
}

// ---------------- pooling (both graphs) ----------------
__global__ void k_pool() {
    int w = (blockIdx.x * blockDim.x + threadIdx.x) >> 5;
    int lane = threadIdx.x & 31;
    if (w >= 2 * cN) return;
    int grp = (w >= cN) ? 1 : 0;
    int n = w - grp * cN;
    int b = g_bat[w];
    size_t gb = (size_t)grp * NSZ;
    float* pool = g_pool + grp * cB * cD;
#pragma unroll
    for (int i = 0; i < RPT; i++) {
        atomicAdd(&pool[b * cD + lane + 32 * i], g_h[gb + (size_t)n * cD + lane + 32 * i]);
    }
}

// ---------------- LN + Linear + ReLU head (both graphs) ----------------
__global__ void __launch_bounds__(640) k_head(const float* __restrict__ ln_g,
                                              const float* __restrict__ ln_b,
                                              const float* __restrict__ Wemb,
                                              const float* __restrict__ bemb) {
    int bx = blockIdx.x;
    int grp = bx >> 6;
    int b = bx & 63;
    int t = threadIdx.x;
    __shared__ float red[20];
    __shared__ float zsh[cD];
    __shared__ float s_mu;
    __shared__ float s_rs;
    float x = g_pool[grp * cB * cD + b * cD + t];

    float v = x;
#pragma unroll
    for (int o = 16; o > 0; o >>= 1) v += __shfl_xor_sync(FULLMASK, v, o);
    if ((t & 31) == 0) red[t >> 5] = v;
    __syncthreads();
    if (t == 0) {
        float s = 0.f;
        for (int i = 0; i < 20; i++) s += red[i];
        s_mu = s / cD;
    }
    __syncthreads();
    float dev = x - s_mu;
    v = dev * dev;
#pragma unroll
    for (int o = 16; o > 0; o >>= 1) v += __shfl_xor_sync(FULLMASK, v, o);
    if ((t & 31) == 0) red[t >> 5] = v;
    __syncthreads();
    if (t == 0) {
        float s = 0.f;
        for (int i = 0; i < 20; i++) s += red[i];
        s_rs = rsqrtf(s / cD + 1e-5f);
    }
    __syncthreads();
    zsh[t] = dev * s_rs * ln_g[t] + ln_b[t];
    __syncthreads();

    float o = bemb[t];
#pragma unroll 4
    for (int kk = 0; kk < cD; kk++) o += zsh[kk] * Wemb[(size_t)kk * cD + t];
    g_z[grp][b * cD + t] = fmaxf(o, 0.f);
}

// ---------------- cosine ----------------
__global__ void k_cos(float* __restrict__ out) {
    int b = blockIdx.x;
    int t = threadIdx.x;
    float dp = 0.f;
    float ai = 0.f;
    float aj = 0.f;
    for (int d = t; d < cD; d += 256) {
        float zi = g_z[0][b * cD + d];
        float zj = g_z[1][b * cD + d];
        dp += zi * zj;
        ai += zi * zi;
        aj += zj * zj;
    }
#pragma unroll
    for (int o = 16; o > 0; o >>= 1) {
        dp += __shfl_xor_sync(FULLMASK, dp, o);
        ai += __shfl_xor_sync(FULLMASK, ai, o);
        aj += __shfl_xor_sync(FULLMASK, aj, o);
    }
    __shared__ float r1[8];
    __shared__ float r2[8];
    __shared__ float r3[8];
    int wd = t >> 5;
    if ((t & 31) == 0) { r1[wd] = dp; r2[wd] = ai; r3[wd] = aj; }
    __syncthreads();
    if (t == 0) {
        float sD = 0.f;
        float sA = 0.f;
        float sB = 0.f;
        for (int i = 0; i < 8; i++) { sD += r1[i]; sA += r2[i]; sB += r3[i]; }
        out[b] = sD / (fmaxf(sqrtf(sA), 1e-8f) * fmaxf(sqrtf(sB), 1e-8f));
    }
}

// ---------------- driver: two-stream overlap of the two graph chains --------
extern "C" void kernel_launch(void* const* d_in, const int* in_sizes, int n_in,
                              void* d_out, int out_size) {
    const float* x_i   = (const float*)d_in[0];
    const int*   ei_i  = (const int*)d_in[1];
    const float* ea_i  = (const float*)d_in[2];
    const int*   bat_i = (const int*)d_in[3];
    const float* x_j   = (const float*)d_in[4];
    const int*   ei_j  = (const int*)d_in[5];
    const float* ea_j  = (const float*)d_in[6];
    const int*   bat_j = (const int*)d_in[7];
    const float* W0q = (const float*)d_in[8];
    const float* b0q = (const float*)d_in[9];
    const float* W0k = (const float*)d_in[10];
    const float* b0k = (const float*)d_in[11];
    const float* W0v = (const float*)d_in[12];
    const float* b0v = (const float*)d_in[13];
    const float* W0e = (const float*)d_in[14];
    const float* W0s = (const float*)d_in[15];
    const float* b0s = (const float*)d_in[16];
    const float* Wq  = (const float*)d_in[17];
    const float* bq  = (const float*)d_in[18];
    const float* Wk  = (const float*)d_in[19];
    const float* bk  = (const float*)d_in[20];
    const float* Wv  = (const float*)d_in[21];
    const float* bv  = (const float*)d_in[22];
    const float* We  = (const float*)d_in[23];
    const float* Ws  = (const float*)d_in[24];
    const float* bs  = (const float*)d_in[25];
    const float* ln_g = (const float*)d_in[26];
    const float* ln_b = (const float*)d_in[27];
    const float* Wemb = (const float*)d_in[28];
    const float* bemb = (const float*)d_in[29];
    float* out = (float*)d_out;

    const int TB = 256;

    static int init_done = 0;
    static cudaStream_t st1;
    static cudaEvent_t evF, evJ;
    if (!init_done) {
        cudaFuncSetAttribute(k_gemm_m, cudaFuncAttributeMaxDynamicSharedMemorySize, GSMEM);
        cudaStreamCreateWithFlags(&st1, cudaStreamNonBlocking);
        cudaEventCreateWithFlags(&evF, cudaEventDisableTiming);
        cudaEventCreateWithFlags(&evJ, cudaEventDisableTiming);
        init_done = 1;
    }

    // ---- shared prologue on default stream ----
    dim3 wgrid(cD / 32, cD / 32, cL1 * 4);
    dim3 wblock(32, 8, 1);
    k_wconv<<<wgrid, wblock>>>(Wq, Wk, Wv, Ws);
    k_detect<<<(2 * cE + TB - 1) / TB, TB>>>(ei_i, bat_i, ei_j, bat_j);
    k_prep<<<(2 * cN * cD + TB - 1) / TB, TB>>>(ei_i, bat_i, ei_j, bat_j, x_i, x_j,
                                                W0q, b0q, W0k, b0k, W0v, b0v, W0s, b0s);
    k_scan<<<2, 1024>>>();
    k_scatter<<<(2 * cE + TB - 1) / TB, TB>>>();

    // ---- fork: graph 1 chain moves to st1 ----
    cudaEventRecord(evF, 0);
    cudaStreamWaitEvent(st1, evF, 0);

    int eb = (cN + 7) / 8;  // edge blocks per graph
    dim3 gemm_grid((cN + 127) / 128, cD / 128, 4);

    // layer 0 edge (per graph)
    k_edge<<<eb, TB>>>(ea_i, W0e, 0, 1);
    k_edge<<<eb, TB, 0, st1>>>(ea_j, W0e, 1, 1);

    // layers 1..5: per-graph gemm + edge chains on separate streams
    for (int l = 0; l < cL1; l++) {
        int dorelu = (l < 4) ? 1 : 0;
        const float* wel = We + (size_t)l * cED * cD;
        k_gemm_m<<<gemm_grid, 512, GSMEM>>>(l, 0,
            bq + (size_t)l * cD, bk + (size_t)l * cD,
            bv + (size_t)l * cD, bs + (size_t)l * cD);
        k_edge<<<eb, TB>>>(ea_i, wel, 0, dorelu);
        k_gemm_m<<<gemm_grid, 512, GSMEM, st1>>>(l, 1,
            bq + (size_t)l * cD, bk + (size_t)l * cD,
            bv + (size_t)l * cD, bs + (size_t)l * cD);
        k_edge<<<eb, TB, 0, st1>>>(ea_j, wel, 1, dorelu);
    }

    // ---- join ----
    cudaEventRecord(evJ, st1);
    cudaStreamWaitEvent(0, evJ, 0);

    // ---- shared epilogue on default stream ----
    k_pool<<<(2 * cN + 7) / 8, TB>>>();
    k_head<<<2 * cB, cD>>>(ln_g, ln_b, Wemb, bemb);
    k_cos<<<cB, 256>>>(out);
}

// round 16
// speedup vs baseline: 2.5909x; 1.2272x over previous
#include <cuda_runtime.h>
#include <cuda_bf16.h>
#include <cstdint>
#include <cstddef>
#include <math.h>

typedef unsigned int u32;
typedef unsigned long long u64;

// Problem constants
constexpr int cN  = 10000;
constexpr int cE  = 160000;
constexpr int cB  = 64;
constexpr int cD  = 640;
constexpr int cND = 4;
constexpr int cED = 8;
constexpr int cL1 = 5;
constexpr int V4  = cD / 128;
constexpr size_t NSZ = (size_t)cN * cD;

#define FULLMASK 0xffffffffu
#define SCALE 0.0395284707521047416f  // 1/sqrt(640)

// ---------------- scratch (per-graph doubled) ----------------
__device__ __align__(16) float g_q [2 * cN * cD];
__device__ __align__(16) float g_k [2 * cN * cD];
__device__ __align__(16) float g_v [2 * cN * cD];
__device__ __align__(16) float g_hn[2 * cN * cD];
__device__ __align__(16) __nv_bfloat16 g_ahi[2 * cN * cD];
__device__ __align__(16) __nv_bfloat16 g_alo[2 * cN * cD];
__device__ __align__(16) __nv_bfloat16 g_wsp[cL1 * 4 * 2 * cD * cD];
__device__ int g_src[2 * cE];
__device__ int g_dst[2 * cE];
__device__ int g_bat[2 * cN];
__device__ int g_flag[4];
__device__ int g_deg[2 * cN];
__device__ int g_cur[2 * cN];
__device__ int g_off[2 * (cN + 1)];
__device__ int g_csr[2 * cE];
__device__ __align__(16) float g_pool[2 * cB * cD];
__device__ __align__(16) float g_z[2][cB * cD];

__device__ __forceinline__ float* buf_sel(int grp, int s) {
    float* p;
    switch (s) {
        case 1:  p = g_q;  break;
        case 2:  p = g_k;  break;
        case 3:  p = g_v;  break;
        default: p = g_hn; break;
    }
    return p + (size_t)grp * NSZ;
}

__device__ __forceinline__ u32 smem_u32(const void* p) {
    return (u32)__cvta_generic_to_shared(p);
}

__device__ __forceinline__ void ldsm4(u32& r0, u32& r1, u32& r2, u32& r3, u32 addr) {
    asm volatile("ldmatrix.sync.aligned.m8n8.x4.shared.b16 {%0,%1,%2,%3}, [%4];"
                 : "=r"(r0), "=r"(r1), "=r"(r2), "=r"(r3)
                 : "r"(addr));
}

__device__ __forceinline__ void mma16816(float* c, const u32* a, u32 b0, u32 b1) {
    asm volatile("mma.sync.aligned.m16n8k16.row.col.f32.bf16.bf16.f32 "
                 "{%0,%1,%2,%3}, {%4,%5,%6,%7}, {%8,%9}, {%0,%1,%2,%3};"
                 : "+f"(c[0]), "+f"(c[1]), "+f"(c[2]), "+f"(c[3])
                 : "r"(a[0]), "r"(a[1]), "r"(a[2]), "r"(a[3]), "r"(b0), "r"(b1));
}

template <int N>
__device__ __forceinline__ void cp_wait() {
    asm volatile("cp.async.wait_group %0;" :: "n"(N) : "memory");
}

__device__ __forceinline__ void cp_commit() {
    asm volatile("cp.async.commit_group;" ::: "memory");
}

// ---------------- GEMM config: CK=64, 2 stages, reg-pipelined ----------------
constexpr int ST = 2;
constexpr int CK = 64;
constexpr int NC = cD / CK;              // 10
constexpr int ROWB  = 144;               // 128B data + 16B pad
constexpr int PARTB = 128 * ROWB;        // 18432 B
constexpr int STAGEB = 4 * PARTB;        // 73728 B
constexpr int GSMEM = ST * STAGEB;       // 147456 B

// 512 threads: each thread issues two 16B cp.async per part
__device__ __forceinline__ void ld_part(u32 sdst, const __nv_bfloat16* g,
                                        int row0, int rmax, int col0, int tid) {
#pragma unroll
    for (int i = 0; i < 2; i++) {
        int seg = tid + i * 512;          // 0..1023
        int row = seg >> 3;
        int s8  = seg & 7;
        u32 dst = sdst + (u32)(row * ROWB + s8 * 16);
        const void* src = (const void*)(g + (size_t)(row0 + row) * cD + col0 + s8 * 8);
        int ok = (row0 + row < rmax) ? 16 : 0;
        asm volatile("cp.async.cg.shared.global [%0], [%1], 16, %2;"
                     :: "r"(dst), "l"(src), "r"(ok) : "memory");
    }
}

// fragment load for one k16 step (set = pipeline slot)
#define LDFRAGS(stbase, kstep, AH, AL_, BH, BL_) do {                               \
    u32 kb_ = (u32)((((kstep) * 16) + lcol) * 2);                                   \
    _Pragma("unroll")                                                               \
    for (int mi_ = 0; mi_ < 2; mi_++) {                                             \
        u32 ra_ = (stbase) + (u32)((wm * 32 + mi_ * 16 + lrow) * ROWB) + kb_;       \
        ldsm4(AH[mi_][0], AH[mi_][1], AH[mi_][2], AH[mi_][3], ra_);                 \
        ldsm4(AL_[mi_][0], AL_[mi_][1], AL_[mi_][2], AL_[mi_][3], ra_ + (u32)PARTB);\
    }                                                                               \
    _Pragma("unroll")                                                               \
    for (int gg_ = 0; gg_ < 2; gg_++) {                                             \
        u32 rb_ = (stbase) + (u32)(2 * PARTB)                                       \
                + (u32)((wn * 32 + gg_ * 16 + lrow) * ROWB) + kb_;                  \
        ldsm4(BH[gg_][0], BH[gg_][1], BH[gg_][2], BH[gg_][3], rb_);                 \
        ldsm4(BL_[gg_][0], BL_[gg_][1], BL_[gg_][2], BL_[gg_][3], rb_ + (u32)PARTB);\
    }                                                                               \
} while (0)

// C = A @ W + bias; 3-term bf16 split, fp32 accum. One graph per launch.
// block 128x128, 16 warps (4M x 4N). grid (79, 5, 4): z = mat
__global__ void __launch_bounds__(512, 1) k_gemm_m(int layer, int grp,
                                                   const float* __restrict__ bq,
                                                   const float* __restrict__ bk,
                                                   const float* __restrict__ bv,
                                                   const float* __restrict__ bs) {
    extern __shared__ char smem[];
    u32 sb = smem_u32(smem);
    int tid = threadIdx.x;
    int lane = tid & 31;
    int warp = tid >> 5;
    int wm = warp & 3;
    int wn = warp >> 2;
    int z = blockIdx.z;

    const __nv_bfloat16* Ahi = g_ahi + (size_t)grp * NSZ;
    const __nv_bfloat16* Alo = g_alo + (size_t)grp * NSZ;
    const __nv_bfloat16* Whi = g_wsp + ((size_t)(layer * 4 + z) * 2 + 0) * cD * cD;
    const __nv_bfloat16* Wlo = Whi + (size_t)cD * cD;
    const float* bias;
    if (z == 0)      bias = bq;
    else if (z == 1) bias = bk;
    else if (z == 2) bias = bv;
    else             bias = bs;
    float* outp = buf_sel(grp, z + 1);

    int bm = blockIdx.x * 128;
    int bn = blockIdx.y * 128;

    float acc[2][4][4];
#pragma unroll
    for (int mi = 0; mi < 2; mi++) {
#pragma unroll
        for (int nj = 0; nj < 4; nj++) {
#pragma unroll
            for (int c = 0; c < 4; c++) acc[mi][nj][c] = 0.f;
        }
    }

    // prologue: chunk 0 into stage 0
    {
        u32 st = sb;
        ld_part(st,             Ahi, bm, cN, 0, tid);
        ld_part(st + PARTB,     Alo, bm, cN, 0, tid);
        ld_part(st + 2 * PARTB, Whi, bn, cD, 0, tid);
        ld_part(st + 3 * PARTB, Wlo, bn, cD, 0, tid);
        cp_commit();
    }

    int lrow = lane & 15;
    int lcol = (lane >> 4) * 8;

    u32 ahx[2][2][4];
    u32 alx[2][2][4];
    u32 bhx[2][2][4];
    u32 blx[2][2][4];

    for (int c = 0; c < NC; c++) {
        cp_wait<0>();
        __syncthreads();

        if (c + 1 < NC) {
            u32 st2 = sb + (u32)(((c + 1) & 1) * STAGEB);
            int col0 = (c + 1) * CK;
            ld_part(st2,             Ahi, bm, cN, col0, tid);
            ld_part(st2 + PARTB,     Alo, bm, cN, col0, tid);
            ld_part(st2 + 2 * PARTB, Whi, bn, cD, col0, tid);
            ld_part(st2 + 3 * PARTB, Wlo, bn, cD, col0, tid);
            cp_commit();
        }

        u32 st = sb + (u32)((c & 1) * STAGEB);
        // register pipeline over 4 k16 steps
        LDFRAGS(st, 0, ahx[0], alx[0], bhx[0], blx[0]);
#pragma unroll
        for (int ks = 0; ks < 4; ks++) {
            int cur = ks & 1;
            int nxt = cur ^ 1;
            if (ks < 3) {
                LDFRAGS(st, ks + 1, ahx[nxt], alx[nxt], bhx[nxt], blx[nxt]);
            }
#pragma unroll
            for (int mi = 0; mi < 2; mi++) {
#pragma unroll
                for (int nj = 0; nj < 4; nj++) {
                    int gg = nj >> 1;
                    int xx = nj & 1;
                    mma16816(acc[mi][nj], ahx[cur][mi], bhx[cur][gg][xx], bhx[cur][gg][xx + 2]);
                    mma16816(acc[mi][nj], ahx[cur][mi], blx[cur][gg][xx], blx[cur][gg][xx + 2]);
                    mma16816(acc[mi][nj], alx[cur][mi], bhx[cur][gg][xx], bhx[cur][gg][xx + 2]);
                }
            }
        }
    }

    int gid = lane >> 2;
    int tig = lane & 3;
#pragma unroll
    for (int mi = 0; mi < 2; mi++) {
#pragma unroll
        for (int nj = 0; nj < 4; nj++) {
            int colg = bn + wn * 32 + nj * 8 + tig * 2;
            float bias0 = bias[colg];
            float bias1 = bias[colg + 1];
            int r0 = bm + wm * 32 + mi * 16 + gid;
            if (r0 < cN) {
                float2 o0;
                o0.x = acc[mi][nj][0] + bias0;
                o0.y = acc[mi][nj][1] + bias1;
                *(float2*)(outp + (size_t)r0 * cD + colg) = o0;
            }
            int r1 = r0 + 8;
            if (r1 < cN) {
                float2 o1;
                o1.x = acc[mi][nj][2] + bias0;
                o1.y = acc[mi][nj][3] + bias1;
                *(float2*)(outp + (size_t)r1 * cD + colg) = o1;
            }
        }
    }
}

// ---------------- detect (both graphs) + zero deg/cur/pool ----------------
__global__ void k_detect(const int* __restrict__ ei0, const int* __restrict__ bat0,
                         const int* __restrict__ ei1, const int* __restrict__ bat1) {
    int i = blockIdx.x * blockDim.x + threadIdx.x;
    if (i < 2 * cE) {
        int grp = i / cE;
        int j = i - grp * cE;
        const int* ei = grp ? ei1 : ei0;
        if (ei[2 * j + 1] != 0) atomicOr(&g_flag[grp], 1);
    }
    if (i < cN) {
        int grp = i / (cN / 2);
        int j = i - grp * (cN / 2);
        const int* bat = grp ? bat1 : bat0;
        if (bat[2 * j + 1] != 0) atomicOr(&g_flag[2 + grp], 1);
    }
    if (i < 2 * cN) { g_deg[i] = 0; g_cur[i] = 0; }
    if (i < 2 * cB * cD) g_pool[i] = 0.f;
}

// ---------------- prep: convert idx + hist + batch + layer0 (both graphs) ----
__global__ void k_prep(const int* __restrict__ ei0, const int* __restrict__ bat0,
                       const int* __restrict__ ei1, const int* __restrict__ bat1,
                       const float* __restrict__ x0, const float* __restrict__ x1,
                       const float* __restrict__ Wq, const float* __restrict__ bq,
                       const float* __restrict__ Wk, const float* __restrict__ bk,
                       const float* __restrict__ Wv, const float* __restrict__ bv,
                       const float* __restrict__ Ws, const float* __restrict__ bs) {
    int i = blockIdx.x * blockDim.x + threadIdx.x;
    if (i < 4 * cE) {
        int grp = i / (2 * cE);
        int j = i - grp * (2 * cE);
        const int* ei = grp ? ei1 : ei0;
        int is32 = g_flag[grp];
        int v;
        if (is32) v = ei[j];
        else      v = (int)((const long long*)ei)[j];
        if (j < cE) {
            g_src[grp * cE + j] = v;
        } else {
            g_dst[grp * cE + (j - cE)] = v;
            atomicAdd(&g_deg[grp * cN + v], 1);
        }
    }
    if (i < 2 * cN) {
        int grp = i / cN;
        int j = i - grp * cN;
        const int* bat = grp ? bat1 : bat0;
        int is32 = g_flag[2 + grp];
        g_bat[i] = is32 ? bat[j] : (int)((const long long*)bat)[j];
    }
    if (i < 2 * cN * cD) {
        int grp = i / (cN * cD);
        int idx = i - grp * (cN * cD);
        const float* x = grp ? x1 : x0;
        int n = idx / cD;
        int d = idx - n * cD;
        float x0v = x[n * cND + 0];
        float x1v = x[n * cND + 1];
        float x2v = x[n * cND + 2];
        float x3v = x[n * cND + 3];
        float aq = bq[d] + x0v * Wq[0 * cD + d] + x1v * Wq[1 * cD + d] + x2v * Wq[2 * cD + d] + x3v * Wq[3 * cD + d];
        float ak = bk[d] + x0v * Wk[0 * cD + d] + x1v * Wk[1 * cD + d] + x2v * Wk[2 * cD + d] + x3v * Wk[3 * cD + d];
        float av = bv[d] + x0v * Wv[0 * cD + d] + x1v * Wv[1 * cD + d] + x2v * Wv[2 * cD + d] + x3v * Wv[3 * cD + d];
        float as = bs[d] + x0v * Ws[0 * cD + d] + x1v * Ws[1 * cD + d] + x2v * Ws[2 * cD + d] + x3v * Ws[3 * cD + d];
        size_t o = (size_t)grp * NSZ + idx;
        g_q[o] = aq;
        g_k[o] = ak;
        g_v[o] = av;
        g_hn[o] = as;
    }
}

// ---------------- CSR scan (one block per graph) ----------------
__global__ void __launch_bounds__(1024) k_scan() {
    const int T = 1024;
    const int CH = (cN + T - 1) / T;
    int grp = blockIdx.x;
    int t = threadIdx.x;
    const int* deg = g_deg + grp * cN;
    int* off = g_off + grp * (cN + 1);
    int vals[CH];
    int local = 0;
    int base = t * CH;
#pragma unroll
    for (int j = 0; j < CH; j++) {
        int idx = base + j;
        int v = (idx < cN) ? deg[idx] : 0;
        vals[j] = local;
        local += v;
    }
    __shared__ int sh[T];
    sh[t] = local;
    __syncthreads();
    for (int o = 1; o < T; o <<= 1) {
        int v = (t >= o) ? sh[t - o] : 0;
        __syncthreads();
        sh[t] += v;
        __syncthreads();
    }
    int prefix = sh[t] - local;
#pragma unroll
    for (int j = 0; j < CH; j++) {
        int idx = base + j;
        if (idx < cN) off[idx] = prefix + vals[j];
    }
    if (t == T - 1) off[cN] = sh[T - 1];
}

__global__ void k_scatter() {
    int i = blockIdx.x * blockDim.x + threadIdx.x;
    if (i < 2 * cE) {
        int grp = i / cE;
        int e = i - grp * cE;
        int d = g_dst[i];
        int p = atomicAdd(&g_cur[grp * cN + d], 1);
        g_csr[grp * cE + g_off[grp * (cN + 1) + d] + p] = e;
    }
}

// ---------------- weight split + transpose (+ flag zero) ----------------
__global__ void k_wconv(const float* __restrict__ Wq, const float* __restrict__ Wk,
                        const float* __restrict__ Wv, const float* __restrict__ Ws) {
    if (blockIdx.x == 0 && blockIdx.y == 0 && blockIdx.z == 0 &&
        threadIdx.y == 0 && threadIdx.x < 4) {
        g_flag[threadIdx.x] = 0;
    }
    int z = blockIdx.z;
    int l = z >> 2;
    int m = z & 3;
    const float* Wsel;
    if (m == 0)      Wsel = Wq;
    else if (m == 1) Wsel = Wk;
    else if (m == 2) Wsel = Wv;
    else             Wsel = Ws;
    const float* W = Wsel + (size_t)l * cD * cD;

    __shared__ float tile[32][33];
    int k0 = blockIdx.x * 32;
    int n0 = blockIdx.y * 32;
    for (int i = threadIdx.y; i < 32; i += 8) {
        tile[i][threadIdx.x] = W[(size_t)(k0 + i) * cD + n0 + threadIdx.x];
    }
    __syncthreads();
    __nv_bfloat16* hi = g_wsp + ((size_t)z * 2 + 0) * cD * cD;
    __nv_bfloat16* lo = g_wsp + ((size_t)z * 2 + 1) * cD * cD;
    for (int i = threadIdx.y; i < 32; i += 8) {
        float wv = tile[threadIdx.x][i];
        __nv_bfloat16 h = __float2bfloat16(wv);
        float r = wv - __bfloat162float(h);
        hi[(size_t)(n0 + i) * cD + k0 + threadIdx.x] = h;
        lo[(size_t)(n0 + i) * cD + k0 + threadIdx.x] = __float2bfloat16(r);
    }
}

// ---------------- fused edge aggregation, unroll-2, one graph per launch ----
// mode 1: relu + store bf16 splits (feeds next gemm); mode 2: pool (final layer)
__global__ void __launch_bounds__(256, 2) k_edge(const float* __restrict__ ea,
                                                 const float* __restrict__ We,
                                                 int grp, int mode) {
    int n = (blockIdx.x * blockDim.x + threadIdx.x) >> 5;
    int lane = threadIdx.x & 31;
    if (n >= cN) return;
    size_t gb = (size_t)grp * NSZ;
    const float4* qrow = (const float4*)(g_q + gb + (size_t)n * cD);
    const float* kbase = g_k + gb;
    const float* vbase = g_v + gb;
    const int* csr = g_csr + grp * cE;
    const int* srcarr = g_src + grp * cE;
    const int fi = lane;

    float4 qr[V4];
#pragma unroll
    for (int i = 0; i < V4; i++) qr[i] = qrow[fi + 32 * i];

    float4 qeA, qeB;
    {
        float qe[cED];
#pragma unroll
        for (int c = 0; c < cED; c++) {
            const float4* wr = (const float4*)(We + (size_t)c * cD);
            float p = 0.f;
#pragma unroll
            for (int i = 0; i < V4; i++) {
                float4 wv = wr[fi + 32 * i];
                p += qr[i].x * wv.x + qr[i].y * wv.y + qr[i].z * wv.z + qr[i].w * wv.w;
            }
#pragma unroll
            for (int o = 16; o > 0; o >>= 1) p += __shfl_xor_sync(FULLMASK, p, o);
            qe[c] = p;
        }
        qeA = make_float4(qe[0], qe[1], qe[2], qe[3]);
        qeB = make_float4(qe[4], qe[5], qe[6], qe[7]);
    }

    float m = -1e30f;
    float s = 0.f;
    float4 acc[V4];
    float4 avA = make_float4(0.f, 0.f, 0.f, 0.f);
    float4 avB = make_float4(0.f, 0.f, 0.f, 0.f);
#pragma unroll
    for (int i = 0; i < V4; i++) acc[i] = make_float4(0.f, 0.f, 0.f, 0.f);

    int beg = g_off[grp * (cN + 1) + n];
    int end = g_off[grp * (cN + 1) + n + 1];
    int idx = beg;

    for (; idx + 2 <= end; idx += 2) {
        int e0 = csr[idx];
        int e1 = csr[idx + 1];
        int s0 = srcarr[e0];
        int s1 = srcarr[e1];
        const float4* kr0 = (const float4*)(kbase + (size_t)s0 * cD);
        const float4* kr1 = (const float4*)(kbase + (size_t)s1 * cD);
        float4 e0A = ((const float4*)(ea + (size_t)e0 * cED))[0];
        float4 e0B = ((const float4*)(ea + (size_t)e0 * cED))[1];
        float4 e1A = ((const float4*)(ea + (size_t)e1 * cED))[0];
        float4 e1B = ((const float4*)(ea + (size_t)e1 * cED))[1];

        float dp0 = 0.f;
        float dp1 = 0.f;
#pragma unroll
        for (int i = 0; i < V4; i++) {
            float4 a = kr0[fi + 32 * i];
            float4 b = kr1[fi + 32 * i];
            dp0 += qr[i].x * a.x + qr[i].y * a.y + qr[i].z * a.z + qr[i].w * a.w;
            dp1 += qr[i].x * b.x + qr[i].y * b.y + qr[i].z * b.z + qr[i].w * b.w;
        }
#pragma unroll
        for (int o = 16; o > 0; o >>= 1) {
            dp0 += __shfl_xor_sync(FULLMASK, dp0, o);
            dp1 += __shfl_xor_sync(FULLMASK, dp1, o);
        }
        float sc0 = dp0 + qeA.x * e0A.x + qeA.y * e0A.y + qeA.z * e0A.z + qeA.w * e0A.w
                        + qeB.x * e0B.x + qeB.y * e0B.y + qeB.z * e0B.z + qeB.w * e0B.w;
        float sc1 = dp1 + qeA.x * e1A.x + qeA.y * e1A.y + qeA.z * e1A.z + qeA.w * e1A.w
                        + qeB.x * e1B.x + qeB.y * e1B.y + qeB.z * e1B.z + qeB.w * e1B.w;
        sc0 *= SCALE;
        sc1 *= SCALE;

        float mn = fmaxf(m, fmaxf(sc0, sc1));
        float f  = __expf(m - mn);
        float w0 = __expf(sc0 - mn);
        float w1 = __expf(sc1 - mn);
        s = s * f + w0 + w1;

        const float4* vr0 = (const float4*)(vbase + (size_t)s0 * cD);
        const float4* vr1 = (const float4*)(vbase + (size_t)s1 * cD);
#pragma unroll
        for (int i = 0; i < V4; i++) {
            float4 v0 = vr0[fi + 32 * i];
            float4 v1 = vr1[fi + 32 * i];
            acc[i].x = acc[i].x * f + w0 * v0.x + w1 * v1.x;
            acc[i].y = acc[i].y * f + w0 * v0.y + w1 * v1.y;
            acc[i].z = acc[i].z * f + w0 * v0.z + w1 * v1.z;
            acc[i].w = acc[i].w * f + w0 * v0.w + w1 * v1.w;
        }
        avA.x = avA.x * f + w0 * e0A.x + w1 * e1A.x;
        avA.y = avA.y * f + w0 * e0A.y + w1 * e1A.y;
        avA.z = avA.z * f + w0 * e0A.z + w1 * e1A.z;
        avA.w = avA.w * f + w0 * e0A.w + w1 * e1A.w;
        avB.x = avB.x * f + w0 * e0B.x + w1 * e1B.x;
        avB.y = avB.y * f + w0 * e0B.y + w1 * e1B.y;
        avB.z = avB.z * f + w0 * e0B.z + w1 * e1B.z;
        avB.w = avB.w * f + w0 * e0B.w + w1 * e1B.w;
        m = mn;
    }

    if (idx < end) {
        int e0 = csr[idx];
        int s0 = srcarr[e0];
        const float4* kr0 = (const float4*)(kbase + (size_t)s0 * cD);
        float4 e0A = ((const float4*)(ea + (size_t)e0 * cED))[0];
        float4 e0B = ((const float4*)(ea + (size_t)e0 * cED))[1];
        float dp0 = 0.f;
#pragma unroll
        for (int i = 0; i < V4; i++) {
            float4 a = kr0[fi + 32 * i];
            dp0 += qr[i].x * a.x + qr[i].y * a.y + qr[i].z * a.z + qr[i].w * a.w;
        }
#pragma unroll
        for (int o = 16; o > 0; o >>= 1) dp0 += __shfl_xor_sync(FULLMASK, dp0, o);
        float sc0 = dp0 + qeA.x * e0A.x + qeA.y * e0A.y + qeA.z * e0A.z + qeA.w * e0A.w
                        + qeB.x * e0B.x + qeB.y * e0B.y + qeB.z * e0B.z + qeB.w * e0B.w;
        sc0 *= SCALE;
        float mn = fmaxf(m, sc0);
        float f  = __expf(m - mn);
        float w0 = __expf(sc0 - mn);
        s = s * f + w0;
        const float4* vr0 = (const float4*)(vbase + (size_t)s0 * cD);
#pragma unroll
        for (int i = 0; i < V4; i++) {
            float4 v0 = vr0[fi + 32 * i];
            acc[i].x = acc[i].x * f + w0 * v0.x;
            acc[i].y = acc[i].y * f + w0 * v0.y;
            acc[i].z = acc[i].z * f + w0 * v0.z;
            acc[i].w = acc[i].w * f + w0 * v0.w;
        }
        avA.x = avA.x * f + w0 * e0A.x;
        avA.y = avA.y * f + w0 * e0A.y;
        avA.z = avA.z * f + w0 * e0A.z;
        avA.w = avA.w * f + w0 * e0A.w;
        avB.x = avB.x * f + w0 * e0B.x;
        avB.y = avB.y * f + w0 * e0B.y;
        avB.z = avB.z * f + w0 * e0B.z;
        avB.w = avB.w * f + w0 * e0B.w;
        m = mn;
    }

    float inv = 1.f / (s + 1e-16f);
    float av[cED];
    av[0] = avA.x; av[1] = avA.y; av[2] = avA.z; av[3] = avA.w;
    av[4] = avB.x; av[5] = avB.y; av[6] = avB.z; av[7] = avB.w;

    int bpool = g_bat[grp * cN + n];
    float* pool = g_pool + grp * cB * cD;

#pragma unroll
    for (int i = 0; i < V4; i++) {
        float4 ep = make_float4(0.f, 0.f, 0.f, 0.f);
#pragma unroll
        for (int c = 0; c < cED; c++) {
            float4 wv = ((const float4*)(We + (size_t)c * cD))[fi + 32 * i];
            ep.x += av[c] * wv.x;
            ep.y += av[c] * wv.y;
            ep.z += av[c] * wv.z;
            ep.w += av[c] * wv.w;
        }
        float4 hb = ((const float4*)(g_hn + gb + (size_t)n * cD))[fi + 32 * i];
        float4 o;
        o.x = hb.x + (acc[i].x + ep.x) * inv;
        o.y = hb.y + (acc[i].y + ep.y) * inv;
        o.z = hb.z + (acc[i].z + ep.z) * inv;
        o.w = hb.w + (acc[i].w + ep.w) * inv;

        if (mode == 1) {
            o.x = fmaxf(o.x, 0.f);
            o.y = fmaxf(o.y, 0.f);
            o.z = fmaxf(o.z, 0.f);
            o.w = fmaxf(o.w, 0.f);
            __nv_bfloat16 h0 = __float2bfloat16(o.x);
            __nv_bfloat16 h1 = __float2bfloat16(o.y);
            __nv_bfloat16 h2 = __float2bfloat16(o.z);
            __nv_bfloat16 h3 = __float2bfloat16(o.w);
            __nv_bfloat16 l0 = __float2bfloat16(o.x - __bfloat162float(h0));
            __nv_bfloat16 l1 = __float2bfloat16(o.y - __bfloat162float(h1));
            __nv_bfloat16 l2 = __float2bfloat16(o.z - __bfloat162float(h2));
            __nv_bfloat16 l3 = __float2bfloat16(o.w - __bfloat162float(h3));
            ushort4 hv, lv;
            hv.x = *(unsigned short*)&h0; hv.y = *(unsigned short*)&h1;
            hv.z = *(unsigned short*)&h2; hv.w = *(unsigned short*)&h3;
            lv.x = *(unsigned short*)&l0; lv.y = *(unsigned short*)&l1;
            lv.z = *(unsigned short*)&l2; lv.w = *(unsigned short*)&l3;
            ((ushort4*)(g_ahi + gb + (size_t)n * cD))[fi + 32 * i] = hv;
            ((ushort4*)(g_alo + gb + (size_t)n * cD))[fi + 32 * i] = lv;
        } else {
            // final layer: no relu, pool directly
            int d = (fi + 32 * i) * 4;
            atomicAdd(&pool[bpool * cD + d + 0], o.x);
            atomicAdd(&pool[bpool * cD + d + 1], o.y);
            atomicAdd(&pool[bpool * cD + d + 2], o.z);
            atomicAdd(&pool[bpool * cD + d + 3], o.w);
        }
    }
}

// ---------------- LN + Linear + ReLU head (both graphs) ----------------
__global__ void __launch_bounds__(640) k_head(const float* __restrict__ ln_g,
                                              const float* __restrict__ ln_b,
                                              const float* __restrict__ Wemb,
                                              const float* __restrict__ bemb) {
    int bx = blockIdx.x;
    int grp = bx >> 6;
    int b = bx & 63;
    int t = threadIdx.x;
    __shared__ float red[20];
    __shared__ float zsh[cD];
    __shared__ float s_mu;
    __shared__ float s_rs;
    float x = g_pool[grp * cB * cD + b * cD + t];

    float v = x;
#pragma unroll
    for (int o = 16; o > 0; o >>= 1) v += __shfl_xor_sync(FULLMASK, v, o);
    if ((t & 31) == 0) red[t >> 5] = v;
    __syncthreads();
    if (t == 0) {
        float s = 0.f;
        for (int i = 0; i < 20; i++) s += red[i];
        s_mu = s / cD;
    }
    __syncthreads();
    float dev = x - s_mu;
    v = dev * dev;
#pragma unroll
    for (int o = 16; o > 0; o >>= 1) v += __shfl_xor_sync(FULLMASK, v, o);
    if ((t & 31) == 0) red[t >> 5] = v;
    __syncthreads();
    if (t == 0) {
        float s = 0.f;
        for (int i = 0; i < 20; i++) s += red[i];
        s_rs = rsqrtf(s / cD + 1e-5f);
    }
    __syncthreads();
    zsh[t] = dev * s_rs * ln_g[t] + ln_b[t];
    __syncthreads();

    float o = bemb[t];
#pragma unroll 4
    for (int kk = 0; kk < cD; kk++) o += zsh[kk] * Wemb[(size_t)kk * cD + t];
    g_z[grp][b * cD + t] = fmaxf(o, 0.f);
}

// ---------------- cosine ----------------
__global__ void k_cos(float* __restrict__ out) {
    int b = blockIdx.x;
    int t = threadIdx.x;
    float dp = 0.f;
    float ai = 0.f;
    float aj = 0.f;
    for (int d = t; d < cD; d += 256) {
        float zi = g_z[0][b * cD + d];
        float zj = g_z[1][b * cD + d];
        dp += zi * zj;
        ai += zi * zi;
        aj += zj * zj;
    }
#pragma unroll
    for (int o = 16; o > 0; o >>= 1) {
        dp += __shfl_xor_sync(FULLMASK, dp, o);
        ai += __shfl_xor_sync(FULLMASK, ai, o);
        aj += __shfl_xor_sync(FULLMASK, aj, o);
    }
    __shared__ float r1[8];
    __shared__ float r2[8];
    __shared__ float r3[8];
    int wd = t >> 5;
    if ((t & 31) == 0) { r1[wd] = dp; r2[wd] = ai; r3[wd] = aj; }
    __syncthreads();
    if (t == 0) {
        float sD = 0.f;
        float sA = 0.f;
        float sB = 0.f;
        for (int i = 0; i < 8; i++) { sD += r1[i]; sA += r2[i]; sB += r3[i]; }
        out[b] = sD / (fmaxf(sqrtf(sA), 1e-8f) * fmaxf(sqrtf(sB), 1e-8f));
    }
}

// ---------------- driver ----------------
extern "C" void kernel_launch(void* const* d_in, const int* in_sizes, int n_in,
                              void* d_out, int out_size) {
    const float* x_i   = (const float*)d_in[0];
    const int*   ei_i  = (const int*)d_in[1];
    const float* ea_i  = (const float*)d_in[2];
    const int*   bat_i = (const int*)d_in[3];
    const float* x_j   = (const float*)d_in[4];
    const int*   ei_j  = (const int*)d_in[5];
    const float* ea_j  = (const float*)d_in[6];
    const int*   bat_j = (const int*)d_in[7];
    const float* W0q = (const float*)d_in[8];
    const float* b0q = (const float*)d_in[9];
    const float* W0k = (const float*)d_in[10];
    const float* b0k = (const float*)d_in[11];
    const float* W0v = (const float*)d_in[12];
    const float* b0v = (const float*)d_in[13];
    const float* W0e = (const float*)d_in[14];
    const float* W0s = (const float*)d_in[15];
    const float* b0s = (const float*)d_in[16];
    const float* Wq  = (const float*)d_in[17];
    const float* bq  = (const float*)d_in[18];
    const float* Wk  = (const float*)d_in[19];
    const float* bk  = (const float*)d_in[20];
    const float* Wv  = (const float*)d_in[21];
    const float* bv  = (const float*)d_in[22];
    const float* We  = (const float*)d_in[23];
    const float* Ws  = (const float*)d_in[24];
    const float* bs  = (const float*)d_in[25];
    const float* ln_g = (const float*)d_in[26];
    const float* ln_b = (const float*)d_in[27];
    const float* Wemb = (const float*)d_in[28];
    const float* bemb = (const float*)d_in[29];
    float* out = (float*)d_out;

    const int TB = 256;

    static int init_done = 0;
    static cudaStream_t st1;
    static cudaEvent_t evF, evJ;
    if (!init_done) {
        cudaFuncSetAttribute(k_gemm_m, cudaFuncAttributeMaxDynamicSharedMemorySize, GSMEM);
        cudaStreamCreateWithFlags(&st1, cudaStreamNonBlocking);
        cudaEventCreateWithFlags(&evF, cudaEventDisableTiming);
        cudaEventCreateWithFlags(&evJ, cudaEventDisableTiming);
        init_done = 1;
    }

    // ---- shared prologue on default stream ----
    dim3 wgrid(cD / 32, cD / 32, cL1 * 4);
    dim3 wblock(32, 8, 1);
    k_wconv<<<wgrid, wblock>>>(Wq, Wk, Wv, Ws);
    k_detect<<<(2 * cE + TB - 1) / TB, TB>>>(ei_i, bat_i, ei_j, bat_j);
    k_prep<<<(2 * cN * cD + TB - 1) / TB, TB>>>(ei_i, bat_i, ei_j, bat_j, x_i, x_j,
                                                W0q, b0q, W0k, b0k, W0v, b0v, W0s, b0s);
    k_scan<<<2, 1024>>>();
    k_scatter<<<(2 * cE + TB - 1) / TB, TB>>>();

    // ---- fork ----
    cudaEventRecord(evF, 0);
    cudaStreamWaitEvent(st1, evF, 0);

    int eb = (cN + 7) / 8;
    dim3 gemm_grid((cN + 127) / 128, cD / 128, 4);

    k_edge<<<eb, TB>>>(ea_i, W0e, 0, 1);
    k_edge<<<eb, TB, 0, st1>>>(ea_j, W0e, 1, 1);

    for (int l = 0; l < cL1; l++) {
        int mode = (l < 4) ? 1 : 2;   // last layer: fuse pool, no relu
        const float* wel = We + (size_t)l * cED * cD;
        k_gemm_m<<<gemm_grid, 512, GSMEM>>>(l, 0,
            bq + (size_t)l * cD, bk + (size_t)l * cD,
            bv + (size_t)l * cD, bs + (size_t)l * cD);
        k_edge<<<eb, TB>>>(ea_i, wel, 0, mode);
        k_gemm_m<<<gemm_grid, 512, GSMEM, st1>>>(l, 1,
            bq + (size_t)l * cD, bk + (size_t)l * cD,
            bv + (size_t)l * cD, bs + (size_t)l * cD);
        k_edge<<<eb, TB, 0, st1>>>(ea_j, wel, 1, mode);
    }

    // ---- join ----
    cudaEventRecord(evJ, st1);
    cudaStreamWaitEvent(0, evJ, 0);

    // ---- epilogue ----
    k_head<<<2 * cB, cD>>>(ln_g, ln_b, Wemb, bemb);
    k_cos<<<cB, 256>>>(out);
}